// round 2
// baseline (speedup 1.0000x reference)
#include <cuda_runtime.h>

#define N_NODES 50000
#define N_EDGES 600000
#define HID 128
#define N_LAYERS 6
#define TE 64
#define KC 16

// ---- scratch (no allocations allowed) ----
__device__ float g_h   [(size_t)N_NODES * HID];
__device__ float g_h2  [(size_t)N_NODES * HID];
__device__ float g_aggr[(size_t)N_NODES * HID];
__device__ float g_deg [N_NODES];
__device__ float g_inv [N_NODES];

__global__ void zero_aggr_kernel() {
    size_t i = (size_t)blockIdx.x * blockDim.x + threadIdx.x;
    if (i < (size_t)N_NODES * HID) g_aggr[i] = 0.0f;
}

__global__ void zero_deg_kernel() {
    int i = blockIdx.x * blockDim.x + threadIdx.x;
    if (i < N_NODES) g_deg[i] = 0.0f;
}

__global__ void deg_kernel(const int* __restrict__ dst) {
    int e = blockIdx.x * blockDim.x + threadIdx.x;
    if (e < N_EDGES) atomicAdd(&g_deg[dst[e]], 1.0f);
}

__global__ void inv_kernel() {
    int i = blockIdx.x * blockDim.x + threadIdx.x;
    if (i < N_NODES) {
        float d = g_deg[i];
        g_inv[i] = (d > 0.0f) ? (1.0f / d) : 0.0f;
    }
}

// ---- encoder: h = relu(x@W1+b1)@W2+b2, x:[N,3] -> g_h ----
__global__ __launch_bounds__(128) void encoder_kernel(
    const float* __restrict__ x,
    const float* __restrict__ W1, const float* __restrict__ b1,
    const float* __restrict__ W2, const float* __restrict__ b2)
{
    __shared__ float Hs[32][HID];
    __shared__ float xs[32][3];
    int tid = threadIdx.x;
    int n0 = blockIdx.x * 32;

    for (int idx = tid; idx < 32 * 3; idx += 128) {
        int i = idx / 3, j = idx % 3;
        int n = n0 + i;
        xs[i][j] = (n < N_NODES) ? x[(size_t)n * 3 + j] : 0.0f;
    }
    __syncthreads();

    int c = tid;
    float w0 = W1[c], w1 = W1[HID + c], w2 = W1[2 * HID + c], bc = b1[c];
    #pragma unroll 4
    for (int i = 0; i < 32; i++) {
        float v = bc + xs[i][0] * w0 + xs[i][1] * w1 + xs[i][2] * w2;
        Hs[i][c] = fmaxf(v, 0.0f);
    }
    __syncthreads();

    float acc[32];
    #pragma unroll
    for (int i = 0; i < 32; i++) acc[i] = 0.0f;
    for (int k = 0; k < HID; k++) {
        float w = W2[(size_t)k * HID + c];
        #pragma unroll
        for (int i = 0; i < 32; i++) acc[i] = fmaf(Hs[i][k], w, acc[i]);
    }
    float b2c = b2[c];
    for (int i = 0; i < 32; i++) {
        int n = n0 + i;
        if (n < N_NODES) g_h[(size_t)n * HID + c] = acc[i] + b2c;
    }
}

// ---- fused edge MLP: m = relu([h_dst,h_src,erow]@W1+b1)@W2+b2 ; atomic g_aggr[dst] += m ----
__global__ __launch_bounds__(128, 3) void edge_kernel(
    int parity,
    const int*   __restrict__ src, const int* __restrict__ dst,
    const float* __restrict__ eattr,
    const float* __restrict__ eeW, const float* __restrict__ eeb,
    const float* __restrict__ W1, const float* __restrict__ b1,
    const float* __restrict__ W2, const float* __restrict__ b2)
{
    __shared__ float Hs[TE][HID];     // erow, later hidden (32KB)
    __shared__ float Asub[TE][KC];    // 4KB
    __shared__ float Wsub[KC][HID];   // 8KB
    __shared__ int   s_src[TE];
    __shared__ int   s_dst[TE];
    __shared__ float s_ea[TE][4];

    const float* __restrict__ h = parity ? g_h2 : g_h;

    int tid = threadIdx.x;
    int e0  = blockIdx.x * TE;
    int cg  = tid & 15;        // column group (8 cols)
    int eg  = tid >> 4;        // edge group (8 edges)
    int c0  = cg * 8;
    int er0 = eg * 8;

    if (tid < TE) { s_src[tid] = src[e0 + tid]; s_dst[tid] = dst[e0 + tid]; }
    for (int idx = tid; idx < TE * 4; idx += 128)
        ((float*)s_ea)[idx] = eattr[(size_t)e0 * 4 + idx];
    __syncthreads();

    // edge encoder row, recomputed (cheap): erow = relu(ea @ eeW + eeb)
    {
        int c = tid;
        float w0 = eeW[c], w1 = eeW[HID + c], w2 = eeW[2 * HID + c], w3 = eeW[3 * HID + c];
        float bb = eeb[c];
        #pragma unroll 4
        for (int e = 0; e < TE; e++) {
            float v = bb + s_ea[e][0] * w0 + s_ea[e][1] * w1
                         + s_ea[e][2] * w2 + s_ea[e][3] * w3;
            Hs[e][c] = fmaxf(v, 0.0f);
        }
    }
    __syncthreads();

    float acc[8][8];
    #pragma unroll
    for (int i = 0; i < 8; i++)
        #pragma unroll
        for (int j = 0; j < 8; j++) acc[i][j] = 0.0f;

    int le = tid >> 1;            // edge row this thread stages
    int lp = (tid & 1) * 8;       // k sub-offset
    int wr = tid >> 3;            // W row (0..15)
    int wc = (tid & 7) * 16;      // W col base

    // GEMM1: [64 x 384] @ [384 x 128]
    for (int ch = 0; ch < 24; ch++) {
        int k0 = ch * KC;
        const float* ap;
        if (k0 < HID)          ap = h + (size_t)s_dst[le] * HID + (k0 + lp);
        else if (k0 < 2 * HID) ap = h + (size_t)s_src[le] * HID + (k0 - HID + lp);
        else                   ap = &Hs[le][k0 - 2 * HID + lp];
        float4 a0 = *(const float4*)ap;
        float4 a1 = *(const float4*)(ap + 4);
        const float4* wp = (const float4*)(W1 + (size_t)(k0 + wr) * HID + wc);
        float4 wv0 = wp[0], wv1 = wp[1], wv2 = wp[2], wv3 = wp[3];
        __syncthreads();   // prior chunk's smem reads complete
        *(float4*)&Asub[le][lp]     = a0;
        *(float4*)&Asub[le][lp + 4] = a1;
        float4* wd = (float4*)&Wsub[wr][wc];
        wd[0] = wv0; wd[1] = wv1; wd[2] = wv2; wd[3] = wv3;
        __syncthreads();
        #pragma unroll
        for (int k = 0; k < KC; k++) {
            float a[8];
            #pragma unroll
            for (int i = 0; i < 8; i++) a[i] = Asub[er0 + i][k];
            float4 q0 = *(float4*)&Wsub[k][c0];
            float4 q1 = *(float4*)&Wsub[k][c0 + 4];
            float w[8] = {q0.x, q0.y, q0.z, q0.w, q1.x, q1.y, q1.z, q1.w};
            #pragma unroll
            for (int i = 0; i < 8; i++)
                #pragma unroll
                for (int j = 0; j < 8; j++)
                    acc[i][j] = fmaf(a[i], w[j], acc[i][j]);
        }
    }
    __syncthreads();   // everyone done reading Hs (erow) before overwrite

    // bias + relu -> hidden tile in Hs
    {
        float4 b0 = *(const float4*)(b1 + c0);
        float4 b1v = *(const float4*)(b1 + c0 + 4);
        float bv[8] = {b0.x, b0.y, b0.z, b0.w, b1v.x, b1v.y, b1v.z, b1v.w};
        #pragma unroll
        for (int i = 0; i < 8; i++) {
            float4 h0, h1;
            h0.x = fmaxf(acc[i][0] + bv[0], 0.0f);
            h0.y = fmaxf(acc[i][1] + bv[1], 0.0f);
            h0.z = fmaxf(acc[i][2] + bv[2], 0.0f);
            h0.w = fmaxf(acc[i][3] + bv[3], 0.0f);
            h1.x = fmaxf(acc[i][4] + bv[4], 0.0f);
            h1.y = fmaxf(acc[i][5] + bv[5], 0.0f);
            h1.z = fmaxf(acc[i][6] + bv[6], 0.0f);
            h1.w = fmaxf(acc[i][7] + bv[7], 0.0f);
            *(float4*)&Hs[er0 + i][c0]     = h0;
            *(float4*)&Hs[er0 + i][c0 + 4] = h1;
        }
    }
    __syncthreads();

    // GEMM2: [64 x 128] @ [128 x 128]
    float acc2[8][8];
    #pragma unroll
    for (int i = 0; i < 8; i++)
        #pragma unroll
        for (int j = 0; j < 8; j++) acc2[i][j] = 0.0f;

    for (int ch = 0; ch < 8; ch++) {
        int k0 = ch * KC;
        const float4* wp = (const float4*)(W2 + (size_t)(k0 + wr) * HID + wc);
        float4 wv0 = wp[0], wv1 = wp[1], wv2 = wp[2], wv3 = wp[3];
        __syncthreads();
        float4* wd = (float4*)&Wsub[wr][wc];
        wd[0] = wv0; wd[1] = wv1; wd[2] = wv2; wd[3] = wv3;
        __syncthreads();
        #pragma unroll
        for (int k = 0; k < KC; k++) {
            float a[8];
            #pragma unroll
            for (int i = 0; i < 8; i++) a[i] = Hs[er0 + i][k0 + k];
            float4 q0 = *(float4*)&Wsub[k][c0];
            float4 q1 = *(float4*)&Wsub[k][c0 + 4];
            float w[8] = {q0.x, q0.y, q0.z, q0.w, q1.x, q1.y, q1.z, q1.w};
            #pragma unroll
            for (int i = 0; i < 8; i++)
                #pragma unroll
                for (int j = 0; j < 8; j++)
                    acc2[i][j] = fmaf(a[i], w[j], acc2[i][j]);
        }
    }

    // bias + scatter-add
    {
        float4 b0 = *(const float4*)(b2 + c0);
        float4 b1v = *(const float4*)(b2 + c0 + 4);
        float bw[8] = {b0.x, b0.y, b0.z, b0.w, b1v.x, b1v.y, b1v.z, b1v.w};
        #pragma unroll
        for (int i = 0; i < 8; i++) {
            int d = s_dst[er0 + i];
            float* ag = g_aggr + (size_t)d * HID + c0;
            #pragma unroll
            for (int j = 0; j < 8; j++)
                atomicAdd(ag + j, acc2[i][j] + bw[j]);
        }
    }
}

// ---- node update + layernorm: hout = LN(h + relu([h, aggr*inv]@W + b)) ----
__global__ __launch_bounds__(128) void node_kernel(
    int parity,
    const float* __restrict__ W, const float* __restrict__ b,
    const float* __restrict__ lg, const float* __restrict__ lb)
{
    __shared__ float As[32][2 * HID];   // [h | aggr*inv], later r in upper half
    __shared__ float s_mu[32], s_rs[32];

    const float* __restrict__ h    = parity ? g_h2 : g_h;
    float*       __restrict__ hout = parity ? g_h  : g_h2;

    int tid = threadIdx.x;
    int n0 = blockIdx.x * 32;

    for (int idx = tid; idx < 32 * 2 * HID; idx += 128) {
        int i = idx >> 8;
        int k = idx & 255;
        int n = n0 + i;
        float v = 0.0f;
        if (n < N_NODES)
            v = (k < HID) ? h[(size_t)n * HID + k]
                          : g_aggr[(size_t)n * HID + (k - HID)] * g_inv[n];
        As[i][k] = v;
    }
    __syncthreads();

    int c = tid;
    float acc[32];
    #pragma unroll
    for (int i = 0; i < 32; i++) acc[i] = 0.0f;
    for (int k = 0; k < 2 * HID; k++) {
        float w = W[(size_t)k * HID + c];
        #pragma unroll
        for (int i = 0; i < 32; i++) acc[i] = fmaf(As[i][k], w, acc[i]);
    }
    __syncthreads();   // all reads of As done before overwrite of upper half

    float bc = b[c];
    #pragma unroll
    for (int i = 0; i < 32; i++) {
        float r = As[i][c] + fmaxf(acc[i] + bc, 0.0f);
        As[i][HID + c] = r;
    }
    __syncthreads();

    int warp = tid >> 5, lane = tid & 31;
    for (int i = warp; i < 32; i += 4) {
        float v0 = As[i][HID + lane],      v1 = As[i][HID + 32 + lane];
        float v2 = As[i][HID + 64 + lane], v3 = As[i][HID + 96 + lane];
        float s = v0 + v1 + v2 + v3;
        float q = v0 * v0 + v1 * v1 + v2 * v2 + v3 * v3;
        #pragma unroll
        for (int o = 16; o > 0; o >>= 1) {
            s += __shfl_xor_sync(0xffffffffu, s, o);
            q += __shfl_xor_sync(0xffffffffu, q, o);
        }
        if (lane == 0) {
            float mu = s * (1.0f / HID);
            float var = q * (1.0f / HID) - mu * mu;
            s_mu[i] = mu;
            s_rs[i] = rsqrtf(var + 1e-5f);
        }
    }
    __syncthreads();

    float gc = lg[c], lbc = lb[c];
    for (int i = 0; i < 32; i++) {
        int n = n0 + i;
        if (n < N_NODES)
            hout[(size_t)n * HID + c] = (As[i][HID + c] - s_mu[i]) * s_rs[i] * gc + lbc;
    }
}

// ---- decoder: out = (relu(h@W1+b1)@W2 + b2)[:,0] ----
__global__ __launch_bounds__(128) void decoder_kernel(
    int parity,
    const float* __restrict__ W1, const float* __restrict__ b1,
    const float* __restrict__ W2, const float* __restrict__ b2,
    float* __restrict__ out)
{
    __shared__ float Hs[32][HID];
    __shared__ float s_red[32];

    const float* __restrict__ h = parity ? g_h2 : g_h;

    int tid = threadIdx.x;
    int n0 = blockIdx.x * 32;

    for (int idx = tid; idx < 32 * HID; idx += 128) {
        int i = idx >> 7, k = idx & 127;
        int n = n0 + i;
        Hs[i][k] = (n < N_NODES) ? h[(size_t)n * HID + k] : 0.0f;
    }
    __syncthreads();

    int c = tid;
    float acc[32];
    #pragma unroll
    for (int i = 0; i < 32; i++) acc[i] = 0.0f;
    for (int k = 0; k < HID; k++) {
        float w = W1[(size_t)k * HID + c];
        #pragma unroll
        for (int i = 0; i < 32; i++) acc[i] = fmaf(Hs[i][k], w, acc[i]);
    }
    __syncthreads();   // reads of Hs done

    float b1c = b1[c], w2c = W2[c];
    #pragma unroll
    for (int i = 0; i < 32; i++)
        Hs[i][c] = fmaxf(acc[i] + b1c, 0.0f) * w2c;
    __syncthreads();

    int warp = tid >> 5, lane = tid & 31;
    for (int i = warp; i < 32; i += 4) {
        float s = Hs[i][lane] + Hs[i][32 + lane] + Hs[i][64 + lane] + Hs[i][96 + lane];
        #pragma unroll
        for (int o = 16; o > 0; o >>= 1) s += __shfl_xor_sync(0xffffffffu, s, o);
        if (lane == 0) s_red[i] = s;
    }
    __syncthreads();
    if (tid < 32) {
        int n = n0 + tid;
        if (n < N_NODES) out[n] = s_red[tid] + b2[0];
    }
}

extern "C" void kernel_launch(void* const* d_in, const int* in_sizes, int n_in,
                              void* d_out, int out_size)
{
    const float* x      = (const float*)d_in[0];
    const int*   ei     = (const int*)  d_in[1];
    const float* eattr  = (const float*)d_in[2];
    const float* encW1  = (const float*)d_in[3];
    const float* encb1  = (const float*)d_in[4];
    const float* encW2  = (const float*)d_in[5];
    const float* encb2  = (const float*)d_in[6];
    const float* eeW    = (const float*)d_in[7];
    const float* eeb    = (const float*)d_in[8];
    const float* msgW1  = (const float*)d_in[9];
    const float* msgb1  = (const float*)d_in[10];
    const float* msgW2  = (const float*)d_in[11];
    const float* msgb2  = (const float*)d_in[12];
    const float* updW   = (const float*)d_in[13];
    const float* updb   = (const float*)d_in[14];
    const float* lng    = (const float*)d_in[15];
    const float* lnb    = (const float*)d_in[16];
    const float* decW1  = (const float*)d_in[17];
    const float* decb1  = (const float*)d_in[18];
    const float* decW2  = (const float*)d_in[19];
    const float* decb2  = (const float*)d_in[20];
    float* out = (float*)d_out;

    const int* src = ei;
    const int* dst = ei + N_EDGES;

    zero_deg_kernel<<<(N_NODES + 255) / 256, 256>>>();
    deg_kernel<<<(N_EDGES + 255) / 256, 256>>>(dst);
    inv_kernel<<<(N_NODES + 255) / 256, 256>>>();
    encoder_kernel<<<(N_NODES + 31) / 32, 128>>>(x, encW1, encb1, encW2, encb2);

    for (int l = 0; l < N_LAYERS; l++) {
        int parity = l & 1;   // layer input lives in g_h when parity==0, g_h2 when 1
        zero_aggr_kernel<<<((N_NODES * HID) + 511) / 512, 512>>>();
        edge_kernel<<<N_EDGES / TE, 128>>>(
            parity, src, dst, eattr, eeW, eeb,
            msgW1 + (size_t)l * 3 * HID * HID, msgb1 + (size_t)l * HID,
            msgW2 + (size_t)l * HID * HID,     msgb2 + (size_t)l * HID);
        node_kernel<<<(N_NODES + 31) / 32, 128>>>(
            parity,
            updW + (size_t)l * 2 * HID * HID, updb + (size_t)l * HID,
            lng + (size_t)l * HID, lnb + (size_t)l * HID);
    }
    // after 6 layers (even count), result is back in g_h -> parity 0
    decoder_kernel<<<(N_NODES + 31) / 32, 128>>>(0, decW1, decb1, decW2, decb2, out);
}

// round 3
// speedup vs baseline: 1.0714x; 1.0714x over previous
#include <cuda_runtime.h>

#define N_NODES 50000
#define N_EDGES 600000
#define HID 128
#define N_LAYERS 6
#define TE 64
#define KC 16

// ---- scratch (no allocations allowed) ----
__device__ float g_h   [(size_t)N_NODES * HID];
__device__ float g_h2  [(size_t)N_NODES * HID];
__device__ float g_aggr[(size_t)N_NODES * HID];
__device__ float g_deg [N_NODES];
__device__ float g_inv [N_NODES];

// packed f32x2 helpers
__device__ __forceinline__ unsigned long long pack2(float lo, float hi) {
    unsigned long long r;
    asm("mov.b64 %0, {%1, %2};" : "=l"(r) : "f"(lo), "f"(hi));
    return r;
}
__device__ __forceinline__ unsigned long long bcast2(float v) {
    unsigned long long r;
    asm("mov.b64 %0, {%1, %1};" : "=l"(r) : "f"(v));
    return r;
}
__device__ __forceinline__ void unpack2(unsigned long long p, float& lo, float& hi) {
    asm("mov.b64 {%0, %1}, %2;" : "=f"(lo), "=f"(hi) : "l"(p));
}
__device__ __forceinline__ void fma2(unsigned long long& acc,
                                     unsigned long long a, unsigned long long b) {
    asm("fma.rn.f32x2 %0, %1, %2, %0;" : "+l"(acc) : "l"(a), "l"(b));
}

__global__ void zero_aggr_kernel() {
    size_t i = (size_t)blockIdx.x * blockDim.x + threadIdx.x;
    if (i < (size_t)N_NODES * HID) g_aggr[i] = 0.0f;
}

__global__ void zero_deg_kernel() {
    int i = blockIdx.x * blockDim.x + threadIdx.x;
    if (i < N_NODES) g_deg[i] = 0.0f;
}

__global__ void deg_kernel(const int* __restrict__ dst) {
    int e = blockIdx.x * blockDim.x + threadIdx.x;
    if (e < N_EDGES) atomicAdd(&g_deg[dst[e]], 1.0f);
}

__global__ void inv_kernel() {
    int i = blockIdx.x * blockDim.x + threadIdx.x;
    if (i < N_NODES) {
        float d = g_deg[i];
        g_inv[i] = (d > 0.0f) ? (1.0f / d) : 0.0f;
    }
}

// ---- encoder: h = relu(x@W1+b1)@W2+b2, x:[N,3] -> g_h ----
__global__ __launch_bounds__(128) void encoder_kernel(
    const float* __restrict__ x,
    const float* __restrict__ W1, const float* __restrict__ b1,
    const float* __restrict__ W2, const float* __restrict__ b2)
{
    __shared__ float Hs[32][HID];
    __shared__ float xs[32][3];
    int tid = threadIdx.x;
    int n0 = blockIdx.x * 32;

    for (int idx = tid; idx < 32 * 3; idx += 128) {
        int i = idx / 3, j = idx % 3;
        int n = n0 + i;
        xs[i][j] = (n < N_NODES) ? x[(size_t)n * 3 + j] : 0.0f;
    }
    __syncthreads();

    int c = tid;
    float w0 = W1[c], w1 = W1[HID + c], w2 = W1[2 * HID + c], bc = b1[c];
    #pragma unroll 4
    for (int i = 0; i < 32; i++) {
        float v = bc + xs[i][0] * w0 + xs[i][1] * w1 + xs[i][2] * w2;
        Hs[i][c] = fmaxf(v, 0.0f);
    }
    __syncthreads();

    float acc[32];
    #pragma unroll
    for (int i = 0; i < 32; i++) acc[i] = 0.0f;
    for (int k = 0; k < HID; k++) {
        float w = W2[(size_t)k * HID + c];
        #pragma unroll
        for (int i = 0; i < 32; i++) acc[i] = fmaf(Hs[i][k], w, acc[i]);
    }
    float b2c = b2[c];
    for (int i = 0; i < 32; i++) {
        int n = n0 + i;
        if (n < N_NODES) g_h[(size_t)n * HID + c] = acc[i] + b2c;
    }
}

// ---- fused edge MLP: m = relu([h_dst,h_src,erow]@W1+b1)@W2+b2 ; atomic g_aggr[dst] += m ----
__global__ __launch_bounds__(128, 3) void edge_kernel(
    int parity,
    const int*   __restrict__ src, const int* __restrict__ dst,
    const float* __restrict__ eattr,
    const float* __restrict__ eeW, const float* __restrict__ eeb,
    const float* __restrict__ W1, const float* __restrict__ b1,
    const float* __restrict__ W2, const float* __restrict__ b2)
{
    __shared__ float Hs[TE][HID];     // erow, later hidden (32KB)
    __shared__ float Asub[TE][KC];    // 4KB
    __shared__ float Wsub[KC][HID];   // 8KB
    __shared__ int   s_src[TE];
    __shared__ int   s_dst[TE];
    __shared__ float s_ea[TE][4];

    const float* __restrict__ h = parity ? g_h2 : g_h;

    int tid = threadIdx.x;
    int e0  = blockIdx.x * TE;
    int cg  = tid & 15;        // column group (8 cols)
    int eg  = tid >> 4;        // edge group (8 edges)
    int c0  = cg * 8;
    int er0 = eg * 8;

    if (tid < TE) { s_src[tid] = src[e0 + tid]; s_dst[tid] = dst[e0 + tid]; }
    for (int idx = tid; idx < TE * 4; idx += 128)
        ((float*)s_ea)[idx] = eattr[(size_t)e0 * 4 + idx];
    __syncthreads();

    // edge encoder row, recomputed (cheap): erow = relu(ea @ eeW + eeb)
    {
        int c = tid;
        float w0 = eeW[c], w1 = eeW[HID + c], w2 = eeW[2 * HID + c], w3 = eeW[3 * HID + c];
        float bb = eeb[c];
        #pragma unroll 4
        for (int e = 0; e < TE; e++) {
            float v = bb + s_ea[e][0] * w0 + s_ea[e][1] * w1
                         + s_ea[e][2] * w2 + s_ea[e][3] * w3;
            Hs[e][c] = fmaxf(v, 0.0f);
        }
    }
    __syncthreads();

    // packed accumulators: acc[i][jp] = (c0+2jp, c0+2jp+1)
    unsigned long long acc[8][4];
    #pragma unroll
    for (int i = 0; i < 8; i++)
        #pragma unroll
        for (int j = 0; j < 4; j++) acc[i][j] = 0ull;

    int le = tid >> 1;            // edge row this thread stages
    int lp = (tid & 1) * 8;       // k sub-offset
    int wr = tid >> 3;            // W row (0..15)
    int wc = (tid & 7) * 16;      // W col base

    // GEMM1: [64 x 384] @ [384 x 128]
    for (int ch = 0; ch < 24; ch++) {
        int k0 = ch * KC;
        const float* ap;
        if (k0 < HID)          ap = h + (size_t)s_dst[le] * HID + (k0 + lp);
        else if (k0 < 2 * HID) ap = h + (size_t)s_src[le] * HID + (k0 - HID + lp);
        else                   ap = &Hs[le][k0 - 2 * HID + lp];
        float4 a0 = *(const float4*)ap;
        float4 a1 = *(const float4*)(ap + 4);
        const float4* wp = (const float4*)(W1 + (size_t)(k0 + wr) * HID + wc);
        float4 wv0 = wp[0], wv1 = wp[1], wv2 = wp[2], wv3 = wp[3];
        __syncthreads();   // prior chunk's smem reads complete
        *(float4*)&Asub[le][lp]     = a0;
        *(float4*)&Asub[le][lp + 4] = a1;
        float4* wd = (float4*)&Wsub[wr][wc];
        wd[0] = wv0; wd[1] = wv1; wd[2] = wv2; wd[3] = wv3;
        __syncthreads();
        #pragma unroll
        for (int k = 0; k < KC; k++) {
            unsigned long long aP[8];
            #pragma unroll
            for (int i = 0; i < 8; i++) aP[i] = bcast2(Asub[er0 + i][k]);
            ulonglong2 w01 = *reinterpret_cast<const ulonglong2*>(&Wsub[k][c0]);
            ulonglong2 w23 = *reinterpret_cast<const ulonglong2*>(&Wsub[k][c0 + 4]);
            unsigned long long wP[4] = {w01.x, w01.y, w23.x, w23.y};
            #pragma unroll
            for (int i = 0; i < 8; i++)
                #pragma unroll
                for (int j = 0; j < 4; j++)
                    fma2(acc[i][j], aP[i], wP[j]);
        }
    }
    __syncthreads();   // everyone done reading Hs (erow) before overwrite

    // bias + relu -> hidden tile in Hs
    {
        float4 b0 = *(const float4*)(b1 + c0);
        float4 b1v = *(const float4*)(b1 + c0 + 4);
        float bv[8] = {b0.x, b0.y, b0.z, b0.w, b1v.x, b1v.y, b1v.z, b1v.w};
        #pragma unroll
        for (int i = 0; i < 8; i++) {
            float v[8];
            #pragma unroll
            for (int j = 0; j < 4; j++) unpack2(acc[i][j], v[2 * j], v[2 * j + 1]);
            float4 h0, h1;
            h0.x = fmaxf(v[0] + bv[0], 0.0f);
            h0.y = fmaxf(v[1] + bv[1], 0.0f);
            h0.z = fmaxf(v[2] + bv[2], 0.0f);
            h0.w = fmaxf(v[3] + bv[3], 0.0f);
            h1.x = fmaxf(v[4] + bv[4], 0.0f);
            h1.y = fmaxf(v[5] + bv[5], 0.0f);
            h1.z = fmaxf(v[6] + bv[6], 0.0f);
            h1.w = fmaxf(v[7] + bv[7], 0.0f);
            *(float4*)&Hs[er0 + i][c0]     = h0;
            *(float4*)&Hs[er0 + i][c0 + 4] = h1;
        }
    }
    __syncthreads();

    // GEMM2: [64 x 128] @ [128 x 128]
    unsigned long long acc2[8][4];
    #pragma unroll
    for (int i = 0; i < 8; i++)
        #pragma unroll
        for (int j = 0; j < 4; j++) acc2[i][j] = 0ull;

    for (int ch = 0; ch < 8; ch++) {
        int k0 = ch * KC;
        const float4* wp = (const float4*)(W2 + (size_t)(k0 + wr) * HID + wc);
        float4 wv0 = wp[0], wv1 = wp[1], wv2 = wp[2], wv3 = wp[3];
        __syncthreads();
        float4* wd = (float4*)&Wsub[wr][wc];
        wd[0] = wv0; wd[1] = wv1; wd[2] = wv2; wd[3] = wv3;
        __syncthreads();
        #pragma unroll
        for (int k = 0; k < KC; k++) {
            unsigned long long aP[8];
            #pragma unroll
            for (int i = 0; i < 8; i++) aP[i] = bcast2(Hs[er0 + i][k0 + k]);
            ulonglong2 w01 = *reinterpret_cast<const ulonglong2*>(&Wsub[k][c0]);
            ulonglong2 w23 = *reinterpret_cast<const ulonglong2*>(&Wsub[k][c0 + 4]);
            unsigned long long wP[4] = {w01.x, w01.y, w23.x, w23.y};
            #pragma unroll
            for (int i = 0; i < 8; i++)
                #pragma unroll
                for (int j = 0; j < 4; j++)
                    fma2(acc2[i][j], aP[i], wP[j]);
        }
    }

    // bias + scatter-add
    {
        float4 b0 = *(const float4*)(b2 + c0);
        float4 b1v = *(const float4*)(b2 + c0 + 4);
        float bw[8] = {b0.x, b0.y, b0.z, b0.w, b1v.x, b1v.y, b1v.z, b1v.w};
        #pragma unroll
        for (int i = 0; i < 8; i++) {
            float v[8];
            #pragma unroll
            for (int j = 0; j < 4; j++) unpack2(acc2[i][j], v[2 * j], v[2 * j + 1]);
            int d = s_dst[er0 + i];
            float* ag = g_aggr + (size_t)d * HID + c0;
            #pragma unroll
            for (int j = 0; j < 8; j++)
                atomicAdd(ag + j, v[j] + bw[j]);
        }
    }
}

// ---- node update + layernorm: hout = LN(h + relu([h, aggr*inv]@W + b)) ----
__global__ __launch_bounds__(128) void node_kernel(
    int parity,
    const float* __restrict__ W, const float* __restrict__ b,
    const float* __restrict__ lg, const float* __restrict__ lb)
{
    __shared__ float As[32][2 * HID];   // [h | aggr*inv], later r in upper half
    __shared__ float s_mu[32], s_rs[32];

    const float* __restrict__ h    = parity ? g_h2 : g_h;
    float*       __restrict__ hout = parity ? g_h  : g_h2;

    int tid = threadIdx.x;
    int n0 = blockIdx.x * 32;

    for (int idx = tid; idx < 32 * 2 * HID; idx += 128) {
        int i = idx >> 8;
        int k = idx & 255;
        int n = n0 + i;
        float v = 0.0f;
        if (n < N_NODES)
            v = (k < HID) ? h[(size_t)n * HID + k]
                          : g_aggr[(size_t)n * HID + (k - HID)] * g_inv[n];
        As[i][k] = v;
    }
    __syncthreads();

    int c = tid;
    // packed along k: accP[i] = (acc_even, acc_odd), a-pairs contiguous in smem
    unsigned long long accP[32];
    #pragma unroll
    for (int i = 0; i < 32; i++) accP[i] = 0ull;
    for (int kp = 0; kp < HID; kp++) {           // 128 k-pairs over 2*HID
        float w0 = W[(size_t)(2 * kp) * HID + c];
        float w1 = W[(size_t)(2 * kp + 1) * HID + c];
        unsigned long long wP = pack2(w0, w1);
        #pragma unroll
        for (int i = 0; i < 32; i++) {
            unsigned long long aP =
                *reinterpret_cast<const unsigned long long*>(&As[i][2 * kp]);
            fma2(accP[i], aP, wP);
        }
    }
    float acc[32];
    #pragma unroll
    for (int i = 0; i < 32; i++) {
        float lo, hi;
        unpack2(accP[i], lo, hi);
        acc[i] = lo + hi;
    }
    __syncthreads();   // all reads of As done before overwrite of upper half

    float bc = b[c];
    #pragma unroll
    for (int i = 0; i < 32; i++) {
        float r = As[i][c] + fmaxf(acc[i] + bc, 0.0f);
        As[i][HID + c] = r;
    }
    __syncthreads();

    int warp = tid >> 5, lane = tid & 31;
    for (int i = warp; i < 32; i += 4) {
        float v0 = As[i][HID + lane],      v1 = As[i][HID + 32 + lane];
        float v2 = As[i][HID + 64 + lane], v3 = As[i][HID + 96 + lane];
        float s = v0 + v1 + v2 + v3;
        float q = v0 * v0 + v1 * v1 + v2 * v2 + v3 * v3;
        #pragma unroll
        for (int o = 16; o > 0; o >>= 1) {
            s += __shfl_xor_sync(0xffffffffu, s, o);
            q += __shfl_xor_sync(0xffffffffu, q, o);
        }
        if (lane == 0) {
            float mu = s * (1.0f / HID);
            float var = q * (1.0f / HID) - mu * mu;
            s_mu[i] = mu;
            s_rs[i] = rsqrtf(var + 1e-5f);
        }
    }
    __syncthreads();

    float gc = lg[c], lbc = lb[c];
    for (int i = 0; i < 32; i++) {
        int n = n0 + i;
        if (n < N_NODES)
            hout[(size_t)n * HID + c] = (As[i][HID + c] - s_mu[i]) * s_rs[i] * gc + lbc;
    }
}

// ---- decoder: out = (relu(h@W1+b1)@W2 + b2)[:,0] ----
__global__ __launch_bounds__(128) void decoder_kernel(
    int parity,
    const float* __restrict__ W1, const float* __restrict__ b1,
    const float* __restrict__ W2, const float* __restrict__ b2,
    float* __restrict__ out)
{
    __shared__ float Hs[32][HID];
    __shared__ float s_red[32];

    const float* __restrict__ h = parity ? g_h2 : g_h;

    int tid = threadIdx.x;
    int n0 = blockIdx.x * 32;

    for (int idx = tid; idx < 32 * HID; idx += 128) {
        int i = idx >> 7, k = idx & 127;
        int n = n0 + i;
        Hs[i][k] = (n < N_NODES) ? h[(size_t)n * HID + k] : 0.0f;
    }
    __syncthreads();

    int c = tid;
    float acc[32];
    #pragma unroll
    for (int i = 0; i < 32; i++) acc[i] = 0.0f;
    for (int k = 0; k < HID; k++) {
        float w = W1[(size_t)k * HID + c];
        #pragma unroll
        for (int i = 0; i < 32; i++) acc[i] = fmaf(Hs[i][k], w, acc[i]);
    }
    __syncthreads();   // reads of Hs done

    float b1c = b1[c], w2c = W2[c];
    #pragma unroll
    for (int i = 0; i < 32; i++)
        Hs[i][c] = fmaxf(acc[i] + b1c, 0.0f) * w2c;
    __syncthreads();

    int warp = tid >> 5, lane = tid & 31;
    for (int i = warp; i < 32; i += 4) {
        float s = Hs[i][lane] + Hs[i][32 + lane] + Hs[i][64 + lane] + Hs[i][96 + lane];
        #pragma unroll
        for (int o = 16; o > 0; o >>= 1) s += __shfl_xor_sync(0xffffffffu, s, o);
        if (lane == 0) s_red[i] = s;
    }
    __syncthreads();
    if (tid < 32) {
        int n = n0 + tid;
        if (n < N_NODES) out[n] = s_red[tid] + b2[0];
    }
}

extern "C" void kernel_launch(void* const* d_in, const int* in_sizes, int n_in,
                              void* d_out, int out_size)
{
    const float* x      = (const float*)d_in[0];
    const int*   ei     = (const int*)  d_in[1];
    const float* eattr  = (const float*)d_in[2];
    const float* encW1  = (const float*)d_in[3];
    const float* encb1  = (const float*)d_in[4];
    const float* encW2  = (const float*)d_in[5];
    const float* encb2  = (const float*)d_in[6];
    const float* eeW    = (const float*)d_in[7];
    const float* eeb    = (const float*)d_in[8];
    const float* msgW1  = (const float*)d_in[9];
    const float* msgb1  = (const float*)d_in[10];
    const float* msgW2  = (const float*)d_in[11];
    const float* msgb2  = (const float*)d_in[12];
    const float* updW   = (const float*)d_in[13];
    const float* updb   = (const float*)d_in[14];
    const float* lng    = (const float*)d_in[15];
    const float* lnb    = (const float*)d_in[16];
    const float* decW1  = (const float*)d_in[17];
    const float* decb1  = (const float*)d_in[18];
    const float* decW2  = (const float*)d_in[19];
    const float* decb2  = (const float*)d_in[20];
    float* out = (float*)d_out;

    const int* src = ei;
    const int* dst = ei + N_EDGES;

    zero_deg_kernel<<<(N_NODES + 255) / 256, 256>>>();
    deg_kernel<<<(N_EDGES + 255) / 256, 256>>>(dst);
    inv_kernel<<<(N_NODES + 255) / 256, 256>>>();
    encoder_kernel<<<(N_NODES + 31) / 32, 128>>>(x, encW1, encb1, encW2, encb2);

    for (int l = 0; l < N_LAYERS; l++) {
        int parity = l & 1;   // layer input lives in g_h when parity==0, g_h2 when 1
        zero_aggr_kernel<<<((N_NODES * HID) + 511) / 512, 512>>>();
        edge_kernel<<<N_EDGES / TE, 128>>>(
            parity, src, dst, eattr, eeW, eeb,
            msgW1 + (size_t)l * 3 * HID * HID, msgb1 + (size_t)l * HID,
            msgW2 + (size_t)l * HID * HID,     msgb2 + (size_t)l * HID);
        node_kernel<<<(N_NODES + 31) / 32, 128>>>(
            parity,
            updW + (size_t)l * 2 * HID * HID, updb + (size_t)l * HID,
            lng + (size_t)l * HID, lnb + (size_t)l * HID);
    }
    // after 6 layers (even count), result is back in g_h -> parity 0
    decoder_kernel<<<(N_NODES + 31) / 32, 128>>>(0, decW1, decb1, decW2, decb2, out);
}

// round 5
// speedup vs baseline: 2.1439x; 2.0009x over previous
#include <cuda_runtime.h>
#include <cuda_bf16.h>
#include <cstdint>

#define N_NODES 50000
#define N_EDGES 600000
#define HID 128
#define N_LAYERS 6
#define N_TILES 4688          // ceil(600000/128)

// ---- edge-kernel dynamic smem layout (bytes) ----
#define BUFA6_HI 0
#define BUFA6_LO 16384
#define BUFA7_HI 32768
#define BUFA7_LO 49152
#define BUFB_HI  65536
#define BUFB_LO  81920
#define OFF_DST  98304
#define OFF_SRC  98816
#define OFF_B1   99328
#define OFF_B2   99840
#define EDGE_SMEM 100352

#define SWZ(x) ((x) ^ (((x) >> 3) & 0x70))

// ---- scratch (no allocations allowed) ----
__device__ float g_h   [(size_t)N_NODES * HID];
__device__ float g_h2  [(size_t)N_NODES * HID];
__device__ float g_aggr[(size_t)N_NODES * HID];
__device__ float g_deg [N_NODES];
__device__ float g_inv [N_NODES];
// weight images: [layer][chunk 0..7][hi/lo][16KB]; [n][k] bf16x2 at SWZ(n*128+k*2)
__device__ unsigned char g_wimg[(size_t)N_LAYERS * 8 * 2 * 16384];
// edge-embedding images: [tile][half][hi/lo][16KB]; [r][k] bf16x2 at SWZ(r*128+k*2)
__device__ unsigned char g_eimg[(size_t)N_TILES * 2 * 2 * 16384];

// ================= helpers =================
__device__ __forceinline__ uint32_t smem_u32(const void* p) {
    uint32_t a;
    asm("{ .reg .u64 t; cvta.to.shared.u64 t, %1; cvt.u32.u64 %0, t; }" : "=r"(a) : "l"(p));
    return a;
}
// bf16x2 pack: (lo, hi) -> low/high halves
__device__ __forceinline__ uint32_t bf16x2_of(float lo, float hi) {
    uint32_t r;
    asm("cvt.rn.bf16x2.f32 %0, %1, %2;" : "=r"(r) : "f"(hi), "f"(lo));
    return r;
}
__device__ __forceinline__ float lo_f(uint32_t p) { return __uint_as_float(p << 16); }
__device__ __forceinline__ float hi_f(uint32_t p) { return __uint_as_float(p & 0xffff0000u); }

__device__ __forceinline__ void ldsm_x4(uint32_t* r, uint32_t addr) {
    asm volatile("ldmatrix.sync.aligned.m8n8.x4.shared.b16 {%0,%1,%2,%3}, [%4];"
        : "=r"(r[0]), "=r"(r[1]), "=r"(r[2]), "=r"(r[3]) : "r"(addr));
}
__device__ __forceinline__ void mma_bf16(float* d, const uint32_t* a, const uint32_t* b) {
    asm volatile(
        "mma.sync.aligned.m16n8k16.row.col.f32.bf16.bf16.f32 "
        "{%0,%1,%2,%3}, {%4,%5,%6,%7}, {%8,%9}, {%0,%1,%2,%3};"
        : "+f"(d[0]), "+f"(d[1]), "+f"(d[2]), "+f"(d[3])
        : "r"(a[0]), "r"(a[1]), "r"(a[2]), "r"(a[3]), "r"(b[0]), "r"(b[1]));
}

// packed f32x2 helpers (node kernel)
__device__ __forceinline__ unsigned long long pack2(float lo, float hi) {
    unsigned long long r;
    asm("mov.b64 %0, {%1, %2};" : "=l"(r) : "f"(lo), "f"(hi));
    return r;
}
__device__ __forceinline__ void unpack2(unsigned long long p, float& lo, float& hi) {
    asm("mov.b64 {%0, %1}, %2;" : "=f"(lo), "=f"(hi) : "l"(p));
}
__device__ __forceinline__ void fma2(unsigned long long& acc,
                                     unsigned long long a, unsigned long long b) {
    asm("fma.rn.f32x2 %0, %1, %2, %0;" : "+l"(acc) : "l"(a), "l"(b));
}

// ================= small kernels =================
__global__ void zero_aggr_kernel() {
    size_t i = (size_t)blockIdx.x * blockDim.x + threadIdx.x;
    if (i < (size_t)N_NODES * HID) g_aggr[i] = 0.0f;
}
__global__ void zero_deg_kernel() {
    int i = blockIdx.x * blockDim.x + threadIdx.x;
    if (i < N_NODES) g_deg[i] = 0.0f;
}
__global__ void deg_kernel(const int* __restrict__ dst) {
    int e = blockIdx.x * blockDim.x + threadIdx.x;
    if (e < N_EDGES) atomicAdd(&g_deg[dst[e]], 1.0f);
}
__global__ void inv_kernel() {
    int i = blockIdx.x * blockDim.x + threadIdx.x;
    if (i < N_NODES) {
        float d = g_deg[i];
        g_inv[i] = (d > 0.0f) ? (1.0f / d) : 0.0f;
    }
}

// ---- precompute: weight chunk images ([n][k] bf16 hi/lo, swizzled) ----
__global__ __launch_bounds__(128) void conv_w_kernel(
    const float* __restrict__ msgW1, const float* __restrict__ msgW2)
{
    int l = blockIdx.x >> 3, ch = blockIdx.x & 7, tid = threadIdx.x;
    const float* W = (ch < 6) ? (msgW1 + (size_t)l * 384 * 128 + (size_t)(64 * ch) * 128)
                              : (msgW2 + (size_t)l * 128 * 128 + (size_t)(64 * (ch - 6)) * 128);
    unsigned char* hiImg = g_wimg + ((size_t)(l * 8 + ch) * 2) * 16384;
    unsigned char* loImg = hiImg + 16384;
    for (int i = tid; i < 4096; i += 128) {
        int n = i & 127, kp = i >> 7;
        int k = kp * 2;
        float v0 = W[(size_t)k * 128 + n];
        float v1 = W[(size_t)(k + 1) * 128 + n];
        uint32_t hi = bf16x2_of(v0, v1);
        uint32_t lo = bf16x2_of(v0 - lo_f(hi), v1 - hi_f(hi));
        uint32_t byte = SWZ((uint32_t)(n * 128 + k * 2));
        *(uint32_t*)(hiImg + byte) = hi;
        *(uint32_t*)(loImg + byte) = lo;
    }
}

// ---- precompute: edge embedding images erow = relu(ea@eeW+eeb) ----
__global__ __launch_bounds__(128) void conv_e_kernel(
    const float* __restrict__ eattr, const float* __restrict__ eeW, const float* __restrict__ eeb)
{
    __shared__ float s_w[4 * HID];
    __shared__ float s_b[HID];
    int tid = threadIdx.x, t = blockIdx.x;
    for (int i = tid; i < 4 * HID; i += 128) s_w[i] = eeW[i];
    s_b[tid] = eeb[tid];
    __syncthreads();
    int e = t * 128 + tid;
    float a0 = 0, a1 = 0, a2 = 0, a3 = 0;
    if (e < N_EDGES) {
        const float4 ea = *(const float4*)(eattr + (size_t)e * 4);
        a0 = ea.x; a1 = ea.y; a2 = ea.z; a3 = ea.w;
    }
    unsigned char* base = g_eimg + (size_t)t * 4 * 16384;
    for (int kp = 0; kp < 64; kp++) {
        int k = kp * 2;
        float v0 = fmaxf(s_b[k]     + a0 * s_w[k]       + a1 * s_w[128 + k]
                                    + a2 * s_w[256 + k] + a3 * s_w[384 + k], 0.0f);
        float v1 = fmaxf(s_b[k + 1] + a0 * s_w[k + 1]       + a1 * s_w[128 + k + 1]
                                    + a2 * s_w[256 + k + 1] + a3 * s_w[384 + k + 1], 0.0f);
        uint32_t hi = bf16x2_of(v0, v1);
        uint32_t lo = bf16x2_of(v0 - lo_f(hi), v1 - hi_f(hi));
        int hh = k >> 6;
        uint32_t byte = SWZ((uint32_t)(tid * 128 + (k & 63) * 2));
        *(uint32_t*)(base + (size_t)(hh * 2) * 16384 + byte)     = hi;
        *(uint32_t*)(base + (size_t)(hh * 2 + 1) * 16384 + byte) = lo;
    }
}

// ---- encoder ----
__global__ __launch_bounds__(128) void encoder_kernel(
    const float* __restrict__ x,
    const float* __restrict__ W1, const float* __restrict__ b1,
    const float* __restrict__ W2, const float* __restrict__ b2)
{
    __shared__ float Hs[32][HID];
    __shared__ float xs[32][3];
    int tid = threadIdx.x;
    int n0 = blockIdx.x * 32;

    for (int idx = tid; idx < 32 * 3; idx += 128) {
        int i = idx / 3, j = idx % 3;
        int n = n0 + i;
        xs[i][j] = (n < N_NODES) ? x[(size_t)n * 3 + j] : 0.0f;
    }
    __syncthreads();

    int c = tid;
    float w0 = W1[c], w1 = W1[HID + c], w2 = W1[2 * HID + c], bc = b1[c];
    #pragma unroll 4
    for (int i = 0; i < 32; i++) {
        float v = bc + xs[i][0] * w0 + xs[i][1] * w1 + xs[i][2] * w2;
        Hs[i][c] = fmaxf(v, 0.0f);
    }
    __syncthreads();

    float acc[32];
    #pragma unroll
    for (int i = 0; i < 32; i++) acc[i] = 0.0f;
    for (int k = 0; k < HID; k++) {
        float w = W2[(size_t)k * HID + c];
        #pragma unroll
        for (int i = 0; i < 32; i++) acc[i] = fmaf(Hs[i][k], w, acc[i]);
    }
    float b2c = b2[c];
    for (int i = 0; i < 32; i++) {
        int n = n0 + i;
        if (n < N_NODES) g_h[(size_t)n * HID + c] = acc[i] + b2c;
    }
}

// ================ HMMA edge kernel ================
__device__ __forceinline__ void run_chunk_mma(
    uint32_t aHi, uint32_t aLo, uint32_t bHi, uint32_t bLo,
    const int rbyte[4], const int xa[4], const int nbyte[2], const int xb[2],
    float acc[4][4][4])
{
    #pragma unroll
    for (int ks = 0; ks < 4; ks++) {
        int kb = ks * 32;
        uint32_t aH[4][4], aL[4][4], bH[2][4], bL[2][4];
        #pragma unroll
        for (int rt = 0; rt < 4; rt++) {
            uint32_t off = (uint32_t)((rbyte[rt] + kb) ^ xa[rt]);
            ldsm_x4(aH[rt], aHi + off);
            ldsm_x4(aL[rt], aLo + off);
        }
        #pragma unroll
        for (int cp = 0; cp < 2; cp++) {
            uint32_t off = (uint32_t)((nbyte[cp] + kb) ^ xb[cp]);
            ldsm_x4(bH[cp], bHi + off);
            ldsm_x4(bL[cp], bLo + off);
        }
        #pragma unroll
        for (int rt = 0; rt < 4; rt++)
            #pragma unroll
            for (int ct = 0; ct < 4; ct++) {
                const uint32_t* bh = &bH[ct >> 1][(ct & 1) * 2];
                const uint32_t* bl = &bL[ct >> 1][(ct & 1) * 2];
                mma_bf16(acc[rt][ct], aH[rt], bh);
                mma_bf16(acc[rt][ct], aH[rt], bl);
                mma_bf16(acc[rt][ct], aL[rt], bh);
            }
    }
}

__global__ void __launch_bounds__(256) edge_kernel(
    int parity, int layer,
    const int* __restrict__ src, const int* __restrict__ dst,
    const float* __restrict__ b1, const float* __restrict__ b2)
{
    extern __shared__ char dsm[];
    uint32_t sb = smem_u32(dsm);
    int tid = threadIdx.x, wid = tid >> 5, lane = tid & 31;
    int wr = wid >> 2, wc = wid & 3;          // 2x4 warp grid
    int wrow = 64 * wr, wcol = 32 * wc;
    int t = blockIdx.x, e0 = t * 128;
    const float* __restrict__ h = parity ? g_h2 : g_h;

    if (tid < 128) {
        int e = e0 + tid;
        ((int*)(dsm + OFF_DST))[tid] = (e < N_EDGES) ? dst[e] : 0;
        ((int*)(dsm + OFF_SRC))[tid] = (e < N_EDGES) ? src[e] : 0;
        ((float*)(dsm + OFF_B1))[tid] = b1[tid];
        ((float*)(dsm + OFF_B2))[tid] = b2[tid];
    }
    __syncthreads();
    const int* sd = (const int*)(dsm + OFF_DST);
    const int* ssrc = (const int*)(dsm + OFF_SRC);
    const float* sb1 = (const float*)(dsm + OFF_B1);
    const float* sb2 = (const float*)(dsm + OFF_B2);
    const unsigned char* wimg = g_wimg + (size_t)layer * 8 * 2 * 16384;

    // ldmatrix per-lane address precompute
    int q = lane >> 3, i8 = lane & 7;
    int rbyte[4], xa[4];
    #pragma unroll
    for (int rt = 0; rt < 4; rt++) {
        int r = wrow + 16 * rt + i8 + 8 * (q & 1);
        rbyte[rt] = r * 128 + 16 * (q >> 1);
        xa[rt] = (r & 7) << 4;
    }
    int nbyte[2], xb[2];
    #pragma unroll
    for (int cp = 0; cp < 2; cp++) {
        int n = wcol + 16 * cp + i8 + 8 * (q >> 1);
        nbyte[cp] = n * 128 + 16 * (q & 1);
        xb[cp] = (n & 7) << 4;
    }

    float acc[4][4][4];
    #pragma unroll
    for (int a = 0; a < 4; a++)
        #pragma unroll
        for (int b = 0; b < 4; b++)
            #pragma unroll
            for (int c = 0; c < 4; c++) acc[a][b][c] = 0.0f;

    // =================== GEMM1: K=384, six 64-chunks ===================
    for (int c = 0; c < 6; c++) {
        // ---- stage A into BUFA6 (working buffer) ----
        if (c < 4) {
            const int* ids = (c < 2) ? sd : ssrc;
            int koff = (c & 1) * 64;
            int r = tid >> 1, part = tid & 1;
            const float4* p = (const float4*)(h + (size_t)ids[r] * HID + koff + part * 32);
            float4 f[8];
            #pragma unroll
            for (int j = 0; j < 8; j++) f[j] = p[j];
            const float* ff = (const float*)f;
            int bb = r * 128 + part * 64;
            #pragma unroll
            for (int j = 0; j < 16; j++) {
                float v0 = ff[2 * j], v1 = ff[2 * j + 1];
                uint32_t hi = bf16x2_of(v0, v1);
                uint32_t lo = bf16x2_of(v0 - lo_f(hi), v1 - hi_f(hi));
                uint32_t byte = SWZ((uint32_t)(bb + 4 * j));
                *(uint32_t*)(dsm + BUFA6_HI + byte) = hi;
                *(uint32_t*)(dsm + BUFA6_LO + byte) = lo;
            }
        } else {
            const float4* ehi = (const float4*)(g_eimg + ((size_t)(t * 2 + (c - 4)) * 2) * 16384);
            const float4* elo = ehi + 1024;
            float4* dhi = (float4*)(dsm + BUFA6_HI);
            float4* dlo = (float4*)(dsm + BUFA6_LO);
            #pragma unroll
            for (int i = 0; i < 4; i++) {
                dhi[tid + 256 * i] = ehi[tid + 256 * i];
                dlo[tid + 256 * i] = elo[tid + 256 * i];
            }
        }
        // ---- stage B (weight image chunk c) ----
        {
            const float4* whi = (const float4*)(wimg + (size_t)(c * 2) * 16384);
            const float4* wlo = whi + 1024;
            float4* dhi = (float4*)(dsm + BUFB_HI);
            float4* dlo = (float4*)(dsm + BUFB_LO);
            #pragma unroll
            for (int i = 0; i < 4; i++) {
                dhi[tid + 256 * i] = whi[tid + 256 * i];
                dlo[tid + 256 * i] = wlo[tid + 256 * i];
            }
        }
        __syncthreads();
        run_chunk_mma(sb + BUFA6_HI, sb + BUFA6_LO, sb + BUFB_HI, sb + BUFB_LO,
                      rbyte, xa, nbyte, xb, acc);
        __syncthreads();
    }

    // =================== hidden export: relu(D1+b1) -> A6/A7 ===================
    #pragma unroll
    for (int rt = 0; rt < 4; rt++) {
        int m1 = wrow + 16 * rt + (lane >> 2);
        int m2 = m1 + 8;
        #pragma unroll
        for (int ct = 0; ct < 4; ct++) {
            int col = wcol + 8 * ct + 2 * (lane & 3);
            int chb = (col >> 6) ? BUFA7_HI : BUFA6_HI;
            int ci2 = (col & 63) * 2;
            float bv0 = sb1[col], bv1 = sb1[col + 1];
            {
                float v0 = fmaxf(acc[rt][ct][0] + bv0, 0.0f);
                float v1 = fmaxf(acc[rt][ct][1] + bv1, 0.0f);
                uint32_t hi = bf16x2_of(v0, v1);
                uint32_t lo = bf16x2_of(v0 - lo_f(hi), v1 - hi_f(hi));
                uint32_t byte = SWZ((uint32_t)(m1 * 128 + ci2));
                *(uint32_t*)(dsm + chb + byte) = hi;
                *(uint32_t*)(dsm + chb + 16384 + byte) = lo;
            }
            {
                float v0 = fmaxf(acc[rt][ct][2] + bv0, 0.0f);
                float v1 = fmaxf(acc[rt][ct][3] + bv1, 0.0f);
                uint32_t hi = bf16x2_of(v0, v1);
                uint32_t lo = bf16x2_of(v0 - lo_f(hi), v1 - hi_f(hi));
                uint32_t byte = SWZ((uint32_t)(m2 * 128 + ci2));
                *(uint32_t*)(dsm + chb + byte) = hi;
                *(uint32_t*)(dsm + chb + 16384 + byte) = lo;
            }
        }
    }
    // zero accs for GEMM2
    #pragma unroll
    for (int a = 0; a < 4; a++)
        #pragma unroll
        for (int b = 0; b < 4; b++)
            #pragma unroll
            for (int c = 0; c < 4; c++) acc[a][b][c] = 0.0f;

    // =================== GEMM2: K=128, chunks from A6/A7 ===================
    for (int g = 0; g < 2; g++) {
        {
            const float4* whi = (const float4*)(wimg + (size_t)((6 + g) * 2) * 16384);
            const float4* wlo = whi + 1024;
            float4* dhi = (float4*)(dsm + BUFB_HI);
            float4* dlo = (float4*)(dsm + BUFB_LO);
            #pragma unroll
            for (int i = 0; i < 4; i++) {
                dhi[tid + 256 * i] = whi[tid + 256 * i];
                dlo[tid + 256 * i] = wlo[tid + 256 * i];
            }
        }
        __syncthreads();
        uint32_t aHi = sb + (g ? BUFA7_HI : BUFA6_HI);
        run_chunk_mma(aHi, aHi + 16384, sb + BUFB_HI, sb + BUFB_LO,
                      rbyte, xa, nbyte, xb, acc);
        __syncthreads();
    }

    // =================== epilogue: D2 + b2 -> atomic scatter ===================
    #pragma unroll
    for (int rt = 0; rt < 4; rt++) {
        int m1 = wrow + 16 * rt + (lane >> 2);
        int m2 = m1 + 8;
        bool v1ok = (e0 + m1) < N_EDGES;
        bool v2ok = (e0 + m2) < N_EDGES;
        float* a1 = g_aggr + (size_t)sd[m1] * HID;
        float* a2 = g_aggr + (size_t)sd[m2] * HID;
        #pragma unroll
        for (int ct = 0; ct < 4; ct++) {
            int col = wcol + 8 * ct + 2 * (lane & 3);
            float bv0 = sb2[col], bv1 = sb2[col + 1];
            if (v1ok) {
                atomicAdd(a1 + col,     acc[rt][ct][0] + bv0);
                atomicAdd(a1 + col + 1, acc[rt][ct][1] + bv1);
            }
            if (v2ok) {
                atomicAdd(a2 + col,     acc[rt][ct][2] + bv0);
                atomicAdd(a2 + col + 1, acc[rt][ct][3] + bv1);
            }
        }
    }
}

// ---- node update + layernorm ----
__global__ __launch_bounds__(128) void node_kernel(
    int parity,
    const float* __restrict__ W, const float* __restrict__ b,
    const float* __restrict__ lg, const float* __restrict__ lb)
{
    __shared__ float As[32][2 * HID];
    __shared__ float s_mu[32], s_rs[32];

    const float* __restrict__ h    = parity ? g_h2 : g_h;
    float*       __restrict__ hout = parity ? g_h  : g_h2;

    int tid = threadIdx.x;
    int n0 = blockIdx.x * 32;

    for (int idx = tid; idx < 32 * 2 * HID; idx += 128) {
        int i = idx >> 8;
        int k = idx & 255;
        int n = n0 + i;
        float v = 0.0f;
        if (n < N_NODES)
            v = (k < HID) ? h[(size_t)n * HID + k]
                          : g_aggr[(size_t)n * HID + (k - HID)] * g_inv[n];
        As[i][k] = v;
    }
    __syncthreads();

    int c = tid;
    unsigned long long accP[32];
    #pragma unroll
    for (int i = 0; i < 32; i++) accP[i] = 0ull;
    for (int kp = 0; kp < HID; kp++) {
        float w0 = W[(size_t)(2 * kp) * HID + c];
        float w1 = W[(size_t)(2 * kp + 1) * HID + c];
        unsigned long long wP = pack2(w0, w1);
        #pragma unroll
        for (int i = 0; i < 32; i++) {
            unsigned long long aP =
                *reinterpret_cast<const unsigned long long*>(&As[i][2 * kp]);
            fma2(accP[i], aP, wP);
        }
    }
    float acc[32];
    #pragma unroll
    for (int i = 0; i < 32; i++) {
        float lo, hi;
        unpack2(accP[i], lo, hi);
        acc[i] = lo + hi;
    }
    __syncthreads();

    float bc = b[c];
    #pragma unroll
    for (int i = 0; i < 32; i++) {
        float r = As[i][c] + fmaxf(acc[i] + bc, 0.0f);
        As[i][HID + c] = r;
    }
    __syncthreads();

    int warp = tid >> 5, lane = tid & 31;
    for (int i = warp; i < 32; i += 4) {
        float v0 = As[i][HID + lane],      v1 = As[i][HID + 32 + lane];
        float v2 = As[i][HID + 64 + lane], v3 = As[i][HID + 96 + lane];
        float s = v0 + v1 + v2 + v3;
        float qq = v0 * v0 + v1 * v1 + v2 * v2 + v3 * v3;
        #pragma unroll
        for (int o = 16; o > 0; o >>= 1) {
            s += __shfl_xor_sync(0xffffffffu, s, o);
            qq += __shfl_xor_sync(0xffffffffu, qq, o);
        }
        if (lane == 0) {
            float mu = s * (1.0f / HID);
            float var = qq * (1.0f / HID) - mu * mu;
            s_mu[i] = mu;
            s_rs[i] = rsqrtf(var + 1e-5f);
        }
    }
    __syncthreads();

    float gc = lg[c], lbc = lb[c];
    for (int i = 0; i < 32; i++) {
        int n = n0 + i;
        if (n < N_NODES)
            hout[(size_t)n * HID + c] = (As[i][HID + c] - s_mu[i]) * s_rs[i] * gc + lbc;
    }
}

// ---- decoder ----
__global__ __launch_bounds__(128) void decoder_kernel(
    int parity,
    const float* __restrict__ W1, const float* __restrict__ b1,
    const float* __restrict__ W2, const float* __restrict__ b2,
    float* __restrict__ out)
{
    __shared__ float Hs[32][HID];
    __shared__ float s_red[32];

    const float* __restrict__ h = parity ? g_h2 : g_h;

    int tid = threadIdx.x;
    int n0 = blockIdx.x * 32;

    for (int idx = tid; idx < 32 * HID; idx += 128) {
        int i = idx >> 7, k = idx & 127;
        int n = n0 + i;
        Hs[i][k] = (n < N_NODES) ? h[(size_t)n * HID + k] : 0.0f;
    }
    __syncthreads();

    int c = tid;
    float acc[32];
    #pragma unroll
    for (int i = 0; i < 32; i++) acc[i] = 0.0f;
    for (int k = 0; k < HID; k++) {
        float w = W1[(size_t)k * HID + c];
        #pragma unroll
        for (int i = 0; i < 32; i++) acc[i] = fmaf(Hs[i][k], w, acc[i]);
    }
    __syncthreads();

    float b1c = b1[c], w2c = W2[c];
    #pragma unroll
    for (int i = 0; i < 32; i++)
        Hs[i][c] = fmaxf(acc[i] + b1c, 0.0f) * w2c;
    __syncthreads();

    int warp = tid >> 5, lane = tid & 31;
    for (int i = warp; i < 32; i += 4) {
        float s = Hs[i][lane] + Hs[i][32 + lane] + Hs[i][64 + lane] + Hs[i][96 + lane];
        #pragma unroll
        for (int o = 16; o > 0; o >>= 1) s += __shfl_xor_sync(0xffffffffu, s, o);
        if (lane == 0) s_red[i] = s;
    }
    __syncthreads();
    if (tid < 32) {
        int n = n0 + tid;
        if (n < N_NODES) out[n] = s_red[tid] + b2[0];
    }
}

extern "C" void kernel_launch(void* const* d_in, const int* in_sizes, int n_in,
                              void* d_out, int out_size)
{
    const float* x      = (const float*)d_in[0];
    const int*   ei     = (const int*)  d_in[1];
    const float* eattr  = (const float*)d_in[2];
    const float* encW1  = (const float*)d_in[3];
    const float* encb1  = (const float*)d_in[4];
    const float* encW2  = (const float*)d_in[5];
    const float* encb2  = (const float*)d_in[6];
    const float* eeW    = (const float*)d_in[7];
    const float* eeb    = (const float*)d_in[8];
    const float* msgW1  = (const float*)d_in[9];
    const float* msgb1  = (const float*)d_in[10];
    const float* msgW2  = (const float*)d_in[11];
    const float* msgb2  = (const float*)d_in[12];
    const float* updW   = (const float*)d_in[13];
    const float* updb   = (const float*)d_in[14];
    const float* lng    = (const float*)d_in[15];
    const float* lnb    = (const float*)d_in[16];
    const float* decW1  = (const float*)d_in[17];
    const float* decb1  = (const float*)d_in[18];
    const float* decW2  = (const float*)d_in[19];
    const float* decb2  = (const float*)d_in[20];
    float* out = (float*)d_out;

    const int* src = ei;
    const int* dst = ei + N_EDGES;

    cudaFuncSetAttribute(edge_kernel, cudaFuncAttributeMaxDynamicSharedMemorySize, EDGE_SMEM);

    conv_w_kernel<<<N_LAYERS * 8, 128>>>(msgW1, msgW2);
    conv_e_kernel<<<N_TILES, 128>>>(eattr, eeW, eeb);

    zero_deg_kernel<<<(N_NODES + 255) / 256, 256>>>();
    deg_kernel<<<(N_EDGES + 255) / 256, 256>>>(dst);
    inv_kernel<<<(N_NODES + 255) / 256, 256>>>();
    encoder_kernel<<<(N_NODES + 31) / 32, 128>>>(x, encW1, encb1, encW2, encb2);

    for (int l = 0; l < N_LAYERS; l++) {
        int parity = l & 1;
        zero_aggr_kernel<<<((N_NODES * HID) + 511) / 512, 512>>>();
        edge_kernel<<<N_TILES, 256, EDGE_SMEM>>>(
            parity, l, src, dst,
            msgb1 + (size_t)l * HID, msgb2 + (size_t)l * HID);
        node_kernel<<<(N_NODES + 31) / 32, 128>>>(
            parity,
            updW + (size_t)l * 2 * HID * HID, updb + (size_t)l * HID,
            lng + (size_t)l * HID, lnb + (size_t)l * HID);
    }
    decoder_kernel<<<(N_NODES + 31) / 32, 128>>>(0, decW1, decb1, decW2, decb2, out);
}

// round 10
// speedup vs baseline: 2.3700x; 1.1055x over previous
#include <cuda_runtime.h>
#include <cuda_bf16.h>
#include <cstdint>

#define N_NODES 50000
#define N_EDGES 600000
#define HID 128
#define N_LAYERS 6
#define N_TILES 4688          // ceil(600000/128)

// ---- edge-kernel dynamic smem layout (bytes) ----
#define BUFA6_HI 0
#define BUFA6_LO 16384
#define BUFA7_HI 32768
#define BUFA7_LO 49152
#define BUFB_HI  65536
#define BUFB_LO  81920
#define OFF_DST  98304
#define OFF_SRC  98816
#define OFF_B1   99328
#define OFF_B2   99840
#define EDGE_SMEM 100352

#define SWZ(x) ((x) ^ (((x) >> 3) & 0x70))

// ---- scratch (no allocations allowed) ----
__device__ float g_h   [(size_t)N_NODES * HID];
__device__ float g_h2  [(size_t)N_NODES * HID];
__device__ float g_aggr[(size_t)N_NODES * HID];
__device__ float g_deg [N_NODES];
__device__ float g_inv [N_NODES];
// bf16 hi/lo images of current h: [n][128 cols] bf16 = 256B per node
__device__ unsigned char g_hbf_hi[(size_t)N_NODES * 256];
__device__ unsigned char g_hbf_lo[(size_t)N_NODES * 256];
// weight images: [layer][chunk 0..7][hi/lo][16KB]; [n][k] bf16x2 at SWZ(n*128+k*2)
__device__ unsigned char g_wimg[(size_t)N_LAYERS * 8 * 2 * 16384];
// edge-embedding images: [tile][half][hi/lo][16KB]; [r][k] bf16x2 at SWZ(r*128+k*2)
__device__ unsigned char g_eimg[(size_t)N_TILES * 2 * 2 * 16384];

// ================= helpers =================
__device__ __forceinline__ uint32_t smem_u32(const void* p) {
    uint32_t a;
    asm("{ .reg .u64 t; cvta.to.shared.u64 t, %1; cvt.u32.u64 %0, t; }" : "=r"(a) : "l"(p));
    return a;
}
// bf16x2 pack: (lo, hi) -> low/high halves
__device__ __forceinline__ uint32_t bf16x2_of(float lo, float hi) {
    uint32_t r;
    asm("cvt.rn.bf16x2.f32 %0, %1, %2;" : "=r"(r) : "f"(hi), "f"(lo));
    return r;
}
__device__ __forceinline__ float lo_f(uint32_t p) { return __uint_as_float(p << 16); }
__device__ __forceinline__ float hi_f(uint32_t p) { return __uint_as_float(p & 0xffff0000u); }

__device__ __forceinline__ void ldsm_x4(uint32_t* r, uint32_t addr) {
    asm volatile("ldmatrix.sync.aligned.m8n8.x4.shared.b16 {%0,%1,%2,%3}, [%4];"
        : "=r"(r[0]), "=r"(r[1]), "=r"(r[2]), "=r"(r[3]) : "r"(addr));
}
__device__ __forceinline__ void mma_bf16(float* d, const uint32_t* a, const uint32_t* b) {
    asm volatile(
        "mma.sync.aligned.m16n8k16.row.col.f32.bf16.bf16.f32 "
        "{%0,%1,%2,%3}, {%4,%5,%6,%7}, {%8,%9}, {%0,%1,%2,%3};"
        : "+f"(d[0]), "+f"(d[1]), "+f"(d[2]), "+f"(d[3])
        : "r"(a[0]), "r"(a[1]), "r"(a[2]), "r"(a[3]), "r"(b[0]), "r"(b[1]));
}
__device__ __forceinline__ void red_v2(float* p, float v0, float v1) {
    asm volatile("red.global.add.v2.f32 [%0], {%1, %2};"
                 :: "l"(p), "f"(v0), "f"(v1) : "memory");
}

// packed f32x2 helpers (node kernel)
__device__ __forceinline__ unsigned long long pack2(float lo, float hi) {
    unsigned long long r;
    asm("mov.b64 %0, {%1, %2};" : "=l"(r) : "f"(lo), "f"(hi));
    return r;
}
__device__ __forceinline__ void unpack2(unsigned long long p, float& lo, float& hi) {
    asm("mov.b64 {%0, %1}, %2;" : "=f"(lo), "=f"(hi) : "l"(p));
}
__device__ __forceinline__ void fma2(unsigned long long& acc,
                                     unsigned long long a, unsigned long long b) {
    asm("fma.rn.f32x2 %0, %1, %2, %0;" : "+l"(acc) : "l"(a), "l"(b));
}

// ================= small kernels =================
__global__ void zero_aggr_kernel() {
    size_t i = (size_t)blockIdx.x * blockDim.x + threadIdx.x;
    if (i < (size_t)N_NODES * HID) g_aggr[i] = 0.0f;
}
__global__ void zero_deg_kernel() {
    int i = blockIdx.x * blockDim.x + threadIdx.x;
    if (i < N_NODES) g_deg[i] = 0.0f;
}
__global__ void deg_kernel(const int* __restrict__ dst) {
    int e = blockIdx.x * blockDim.x + threadIdx.x;
    if (e < N_EDGES) atomicAdd(&g_deg[dst[e]], 1.0f);
}
__global__ void inv_kernel() {
    int i = blockIdx.x * blockDim.x + threadIdx.x;
    if (i < N_NODES) {
        float d = g_deg[i];
        g_inv[i] = (d > 0.0f) ? (1.0f / d) : 0.0f;
    }
}

// ---- convert h (fp32, buf 0/1) -> bf16 hi/lo node images ----
__global__ __launch_bounds__(256) void conv_h_kernel(int buf) {
    size_t i = (size_t)blockIdx.x * blockDim.x + threadIdx.x;   // pair index
    if (i >= (size_t)N_NODES * 64) return;
    const float2 v = *((const float2*)(buf ? g_h2 : g_h) + i);
    uint32_t hi = bf16x2_of(v.x, v.y);
    uint32_t lo = bf16x2_of(v.x - lo_f(hi), v.y - hi_f(hi));
    ((uint32_t*)g_hbf_hi)[i] = hi;
    ((uint32_t*)g_hbf_lo)[i] = lo;
}

// ---- precompute: weight chunk images ([n][k] bf16 hi/lo, swizzled) ----
__global__ __launch_bounds__(128) void conv_w_kernel(
    const float* __restrict__ msgW1, const float* __restrict__ msgW2)
{
    int l = blockIdx.x >> 3, ch = blockIdx.x & 7, tid = threadIdx.x;
    const float* W = (ch < 6) ? (msgW1 + (size_t)l * 384 * 128 + (size_t)(64 * ch) * 128)
                              : (msgW2 + (size_t)l * 128 * 128 + (size_t)(64 * (ch - 6)) * 128);
    unsigned char* hiImg = g_wimg + ((size_t)(l * 8 + ch) * 2) * 16384;
    unsigned char* loImg = hiImg + 16384;
    for (int i = tid; i < 4096; i += 128) {
        int n = i & 127, kp = i >> 7;
        int k = kp * 2;
        float v0 = W[(size_t)k * 128 + n];
        float v1 = W[(size_t)(k + 1) * 128 + n];
        uint32_t hi = bf16x2_of(v0, v1);
        uint32_t lo = bf16x2_of(v0 - lo_f(hi), v1 - hi_f(hi));
        uint32_t byte = SWZ((uint32_t)(n * 128 + k * 2));
        *(uint32_t*)(hiImg + byte) = hi;
        *(uint32_t*)(loImg + byte) = lo;
    }
}

// ---- precompute: edge embedding images erow = relu(ea@eeW+eeb) ----
__global__ __launch_bounds__(128) void conv_e_kernel(
    const float* __restrict__ eattr, const float* __restrict__ eeW, const float* __restrict__ eeb)
{
    __shared__ float s_w[4 * HID];
    __shared__ float s_b[HID];
    int tid = threadIdx.x, t = blockIdx.x;
    for (int i = tid; i < 4 * HID; i += 128) s_w[i] = eeW[i];
    s_b[tid] = eeb[tid];
    __syncthreads();
    int e = t * 128 + tid;
    float a0 = 0, a1 = 0, a2 = 0, a3 = 0;
    if (e < N_EDGES) {
        const float4 ea = *(const float4*)(eattr + (size_t)e * 4);
        a0 = ea.x; a1 = ea.y; a2 = ea.z; a3 = ea.w;
    }
    unsigned char* base = g_eimg + (size_t)t * 4 * 16384;
    for (int kp = 0; kp < 64; kp++) {
        int k = kp * 2;
        float v0 = fmaxf(s_b[k]     + a0 * s_w[k]       + a1 * s_w[128 + k]
                                    + a2 * s_w[256 + k] + a3 * s_w[384 + k], 0.0f);
        float v1 = fmaxf(s_b[k + 1] + a0 * s_w[k + 1]       + a1 * s_w[128 + k + 1]
                                    + a2 * s_w[256 + k + 1] + a3 * s_w[384 + k + 1], 0.0f);
        uint32_t hi = bf16x2_of(v0, v1);
        uint32_t lo = bf16x2_of(v0 - lo_f(hi), v1 - hi_f(hi));
        int hh = k >> 6;
        uint32_t byte = SWZ((uint32_t)(tid * 128 + (k & 63) * 2));
        *(uint32_t*)(base + (size_t)(hh * 2) * 16384 + byte)     = hi;
        *(uint32_t*)(base + (size_t)(hh * 2 + 1) * 16384 + byte) = lo;
    }
}

// ---- encoder ----
__global__ __launch_bounds__(128) void encoder_kernel(
    const float* __restrict__ x,
    const float* __restrict__ W1, const float* __restrict__ b1,
    const float* __restrict__ W2, const float* __restrict__ b2)
{
    __shared__ float Hs[32][HID];
    __shared__ float xs[32][3];
    int tid = threadIdx.x;
    int n0 = blockIdx.x * 32;

    for (int idx = tid; idx < 32 * 3; idx += 128) {
        int i = idx / 3, j = idx % 3;
        int n = n0 + i;
        xs[i][j] = (n < N_NODES) ? x[(size_t)n * 3 + j] : 0.0f;
    }
    __syncthreads();

    int c = tid;
    float w0 = W1[c], w1 = W1[HID + c], w2 = W1[2 * HID + c], bc = b1[c];
    #pragma unroll 4
    for (int i = 0; i < 32; i++) {
        float v = bc + xs[i][0] * w0 + xs[i][1] * w1 + xs[i][2] * w2;
        Hs[i][c] = fmaxf(v, 0.0f);
    }
    __syncthreads();

    float acc[32];
    #pragma unroll
    for (int i = 0; i < 32; i++) acc[i] = 0.0f;
    for (int k = 0; k < HID; k++) {
        float w = W2[(size_t)k * HID + c];
        #pragma unroll
        for (int i = 0; i < 32; i++) acc[i] = fmaf(Hs[i][k], w, acc[i]);
    }
    float b2c = b2[c];
    for (int i = 0; i < 32; i++) {
        int n = n0 + i;
        if (n < N_NODES) g_h[(size_t)n * HID + c] = acc[i] + b2c;
    }
}

// ================ HMMA edge kernel ================
__device__ __forceinline__ void run_chunk_mma(
    uint32_t aHi, uint32_t aLo, uint32_t bHi, uint32_t bLo,
    const int rbyte[4], const int xa[4], const int nbyte[2], const int xb[2],
    float acc[4][4][4])
{
    #pragma unroll
    for (int ks = 0; ks < 4; ks++) {
        int kb = ks * 32;
        uint32_t aH[4][4], aL[4][4], bH[2][4], bL[2][4];
        #pragma unroll
        for (int rt = 0; rt < 4; rt++) {
            uint32_t off = (uint32_t)((rbyte[rt] + kb) ^ xa[rt]);
            ldsm_x4(aH[rt], aHi + off);
            ldsm_x4(aL[rt], aLo + off);
        }
        #pragma unroll
        for (int cp = 0; cp < 2; cp++) {
            uint32_t off = (uint32_t)((nbyte[cp] + kb) ^ xb[cp]);
            ldsm_x4(bH[cp], bHi + off);
            ldsm_x4(bL[cp], bLo + off);
        }
        #pragma unroll
        for (int rt = 0; rt < 4; rt++)
            #pragma unroll
            for (int ct = 0; ct < 4; ct++) {
                const uint32_t* bh = &bH[ct >> 1][(ct & 1) * 2];
                const uint32_t* bl = &bL[ct >> 1][(ct & 1) * 2];
                mma_bf16(acc[rt][ct], aH[rt], bh);
                mma_bf16(acc[rt][ct], aH[rt], bl);
                mma_bf16(acc[rt][ct], aL[rt], bh);
            }
    }
}

__global__ void __launch_bounds__(256) edge_kernel(
    int layer,
    const int* __restrict__ src, const int* __restrict__ dst,
    const float* __restrict__ b1, const float* __restrict__ b2)
{
    extern __shared__ char dsm[];
    uint32_t sb = smem_u32(dsm);
    int tid = threadIdx.x, wid = tid >> 5, lane = tid & 31;
    int wr = wid >> 2, wc = wid & 3;          // 2x4 warp grid
    int wrow = 64 * wr, wcol = 32 * wc;
    int t = blockIdx.x, e0 = t * 128;

    if (tid < 128) {
        int e = e0 + tid;
        ((int*)(dsm + OFF_DST))[tid] = (e < N_EDGES) ? dst[e] : 0;
        ((int*)(dsm + OFF_SRC))[tid] = (e < N_EDGES) ? src[e] : 0;
        ((float*)(dsm + OFF_B1))[tid] = b1[tid];
        ((float*)(dsm + OFF_B2))[tid] = b2[tid];
    }
    __syncthreads();
    const int* sd = (const int*)(dsm + OFF_DST);
    const int* ssrc = (const int*)(dsm + OFF_SRC);
    const float* sb1 = (const float*)(dsm + OFF_B1);
    const float* sb2 = (const float*)(dsm + OFF_B2);
    const unsigned char* wimg = g_wimg + (size_t)layer * 8 * 2 * 16384;

    // ldmatrix per-lane address precompute
    int q = lane >> 3, i8 = lane & 7;
    int rbyte[4], xa[4];
    #pragma unroll
    for (int rt = 0; rt < 4; rt++) {
        int r = wrow + 16 * rt + i8 + 8 * (q & 1);
        rbyte[rt] = r * 128 + 16 * (q >> 1);
        xa[rt] = (r & 7) << 4;
    }
    int nbyte[2], xb[2];
    #pragma unroll
    for (int cp = 0; cp < 2; cp++) {
        int n = wcol + 16 * cp + i8 + 8 * (q >> 1);
        nbyte[cp] = n * 128 + 16 * (q & 1);
        xb[cp] = (n & 7) << 4;
    }

    float acc[4][4][4];
    #pragma unroll
    for (int a = 0; a < 4; a++)
        #pragma unroll
        for (int b = 0; b < 4; b++)
            #pragma unroll
            for (int c = 0; c < 4; c++) acc[a][b][c] = 0.0f;

    // =================== GEMM1: K=384, six 64-chunks ===================
    for (int c = 0; c < 6; c++) {
        // ---- stage A into BUFA6 ----
        if (c < 4) {
            // pure gather-copy of precomputed bf16 hi/lo node rows, swizzle in STS addr
            const int* ids = (c < 2) ? sd : ssrc;
            int r = tid >> 1, half = tid & 1;
            int node = ids[r];
            int sgbase = 8 * (c & 1) + half * 4;       // source granule (16B units)
            const uint4* pHi = (const uint4*)(g_hbf_hi + (size_t)node * 256) + sgbase;
            const uint4* pLo = (const uint4*)(g_hbf_lo + (size_t)node * 256) + sgbase;
            uint4 vh[4], vl[4];
            #pragma unroll
            for (int j = 0; j < 4; j++) { vh[j] = pHi[j]; vl[j] = pLo[j]; }
            int rx = r & 7;
            #pragma unroll
            for (int j = 0; j < 4; j++) {
                int dg = (half * 4 + j) ^ rx;          // dest granule within row
                *(uint4*)(dsm + BUFA6_HI + r * 128 + dg * 16) = vh[j];
                *(uint4*)(dsm + BUFA6_LO + r * 128 + dg * 16) = vl[j];
            }
        } else {
            const float4* ehi = (const float4*)(g_eimg + ((size_t)(t * 2 + (c - 4)) * 2) * 16384);
            const float4* elo = ehi + 1024;
            float4* dhi = (float4*)(dsm + BUFA6_HI);
            float4* dlo = (float4*)(dsm + BUFA6_LO);
            #pragma unroll
            for (int i = 0; i < 4; i++) {
                dhi[tid + 256 * i] = ehi[tid + 256 * i];
                dlo[tid + 256 * i] = elo[tid + 256 * i];
            }
        }
        // ---- stage B (weight image chunk c) ----
        {
            const float4* whi = (const float4*)(wimg + (size_t)(c * 2) * 16384);
            const float4* wlo = whi + 1024;
            float4* dhi = (float4*)(dsm + BUFB_HI);
            float4* dlo = (float4*)(dsm + BUFB_LO);
            #pragma unroll
            for (int i = 0; i < 4; i++) {
                dhi[tid + 256 * i] = whi[tid + 256 * i];
                dlo[tid + 256 * i] = wlo[tid + 256 * i];
            }
        }
        __syncthreads();
        run_chunk_mma(sb + BUFA6_HI, sb + BUFA6_LO, sb + BUFB_HI, sb + BUFB_LO,
                      rbyte, xa, nbyte, xb, acc);
        __syncthreads();
    }

    // =================== hidden export: relu(D1+b1) -> A6/A7 ===================
    #pragma unroll
    for (int rt = 0; rt < 4; rt++) {
        int m1 = wrow + 16 * rt + (lane >> 2);
        int m2 = m1 + 8;
        #pragma unroll
        for (int ct = 0; ct < 4; ct++) {
            int col = wcol + 8 * ct + 2 * (lane & 3);
            int chb = (col >> 6) ? BUFA7_HI : BUFA6_HI;
            int ci2 = (col & 63) * 2;
            float bv0 = sb1[col], bv1 = sb1[col + 1];
            {
                float v0 = fmaxf(acc[rt][ct][0] + bv0, 0.0f);
                float v1 = fmaxf(acc[rt][ct][1] + bv1, 0.0f);
                uint32_t hi = bf16x2_of(v0, v1);
                uint32_t lo = bf16x2_of(v0 - lo_f(hi), v1 - hi_f(hi));
                uint32_t byte = SWZ((uint32_t)(m1 * 128 + ci2));
                *(uint32_t*)(dsm + chb + byte) = hi;
                *(uint32_t*)(dsm + chb + 16384 + byte) = lo;
            }
            {
                float v0 = fmaxf(acc[rt][ct][2] + bv0, 0.0f);
                float v1 = fmaxf(acc[rt][ct][3] + bv1, 0.0f);
                uint32_t hi = bf16x2_of(v0, v1);
                uint32_t lo = bf16x2_of(v0 - lo_f(hi), v1 - hi_f(hi));
                uint32_t byte = SWZ((uint32_t)(m2 * 128 + ci2));
                *(uint32_t*)(dsm + chb + byte) = hi;
                *(uint32_t*)(dsm + chb + 16384 + byte) = lo;
            }
        }
    }
    // zero accs for GEMM2
    #pragma unroll
    for (int a = 0; a < 4; a++)
        #pragma unroll
        for (int b = 0; b < 4; b++)
            #pragma unroll
            for (int c = 0; c < 4; c++) acc[a][b][c] = 0.0f;

    // =================== GEMM2: K=128, chunks from A6/A7 ===================
    for (int g = 0; g < 2; g++) {
        {
            const float4* whi = (const float4*)(wimg + (size_t)((6 + g) * 2) * 16384);
            const float4* wlo = whi + 1024;
            float4* dhi = (float4*)(dsm + BUFB_HI);
            float4* dlo = (float4*)(dsm + BUFB_LO);
            #pragma unroll
            for (int i = 0; i < 4; i++) {
                dhi[tid + 256 * i] = whi[tid + 256 * i];
                dlo[tid + 256 * i] = wlo[tid + 256 * i];
            }
        }
        __syncthreads();
        uint32_t aHi = sb + (g ? BUFA7_HI : BUFA6_HI);
        run_chunk_mma(aHi, aHi + 16384, sb + BUFB_HI, sb + BUFB_LO,
                      rbyte, xa, nbyte, xb, acc);
        __syncthreads();
    }

    // =================== epilogue: D2 + b2 -> vector red scatter ===================
    #pragma unroll
    for (int rt = 0; rt < 4; rt++) {
        int m1 = wrow + 16 * rt + (lane >> 2);
        int m2 = m1 + 8;
        bool v1ok = (e0 + m1) < N_EDGES;
        bool v2ok = (e0 + m2) < N_EDGES;
        float* a1 = g_aggr + (size_t)sd[m1] * HID;
        float* a2 = g_aggr + (size_t)sd[m2] * HID;
        #pragma unroll
        for (int ct = 0; ct < 4; ct++) {
            int col = wcol + 8 * ct + 2 * (lane & 3);
            float bv0 = sb2[col], bv1 = sb2[col + 1];
            if (v1ok) red_v2(a1 + col, acc[rt][ct][0] + bv0, acc[rt][ct][1] + bv1);
            if (v2ok) red_v2(a2 + col, acc[rt][ct][2] + bv0, acc[rt][ct][3] + bv1);
        }
    }
}

// ---- node update + layernorm ----
__global__ __launch_bounds__(128) void node_kernel(
    int parity,
    const float* __restrict__ W, const float* __restrict__ b,
    const float* __restrict__ lg, const float* __restrict__ lb)
{
    __shared__ float As[32][2 * HID];
    __shared__ float s_mu[32], s_rs[32];

    const float* __restrict__ h    = parity ? g_h2 : g_h;
    float*       __restrict__ hout = parity ? g_h  : g_h2;

    int tid = threadIdx.x;
    int n0 = blockIdx.x * 32;

    for (int idx = tid; idx < 32 * 2 * HID; idx += 128) {
        int i = idx >> 8;
        int k = idx & 255;
        int n = n0 + i;
        float v = 0.0f;
        if (n < N_NODES)
            v = (k < HID) ? h[(size_t)n * HID + k]
                          : g_aggr[(size_t)n * HID + (k - HID)] * g_inv[n];
        As[i][k] = v;
    }
    __syncthreads();

    int c = tid;
    unsigned long long accP[32];
    #pragma unroll
    for (int i = 0; i < 32; i++) accP[i] = 0ull;
    for (int kp = 0; kp < HID; kp++) {
        float w0 = W[(size_t)(2 * kp) * HID + c];
        float w1 = W[(size_t)(2 * kp + 1) * HID + c];
        unsigned long long wP = pack2(w0, w1);
        #pragma unroll
        for (int i = 0; i < 32; i++) {
            unsigned long long aP =
                *reinterpret_cast<const unsigned long long*>(&As[i][2 * kp]);
            fma2(accP[i], aP, wP);
        }
    }
    float acc[32];
    #pragma unroll
    for (int i = 0; i < 32; i++) {
        float lo, hi;
        unpack2(accP[i], lo, hi);
        acc[i] = lo + hi;
    }
    __syncthreads();

    float bc = b[c];
    #pragma unroll
    for (int i = 0; i < 32; i++) {
        float r = As[i][c] + fmaxf(acc[i] + bc, 0.0f);
        As[i][HID + c] = r;
    }
    __syncthreads();

    int warp = tid >> 5, lane = tid & 31;
    for (int i = warp; i < 32; i += 4) {
        float v0 = As[i][HID + lane],      v1 = As[i][HID + 32 + lane];
        float v2 = As[i][HID + 64 + lane], v3 = As[i][HID + 96 + lane];
        float s = v0 + v1 + v2 + v3;
        float qq = v0 * v0 + v1 * v1 + v2 * v2 + v3 * v3;
        #pragma unroll
        for (int o = 16; o > 0; o >>= 1) {
            s += __shfl_xor_sync(0xffffffffu, s, o);
            qq += __shfl_xor_sync(0xffffffffu, qq, o);
        }
        if (lane == 0) {
            float mu = s * (1.0f / HID);
            float var = qq * (1.0f / HID) - mu * mu;
            s_mu[i] = mu;
            s_rs[i] = rsqrtf(var + 1e-5f);
        }
    }
    __syncthreads();

    float gc = lg[c], lbc = lb[c];
    for (int i = 0; i < 32; i++) {
        int n = n0 + i;
        if (n < N_NODES)
            hout[(size_t)n * HID + c] = (As[i][HID + c] - s_mu[i]) * s_rs[i] * gc + lbc;
    }
}

// ---- decoder ----
__global__ __launch_bounds__(128) void decoder_kernel(
    int parity,
    const float* __restrict__ W1, const float* __restrict__ b1,
    const float* __restrict__ W2, const float* __restrict__ b2,
    float* __restrict__ out)
{
    __shared__ float Hs[32][HID];
    __shared__ float s_red[32];

    const float* __restrict__ h = parity ? g_h2 : g_h;

    int tid = threadIdx.x;
    int n0 = blockIdx.x * 32;

    for (int idx = tid; idx < 32 * HID; idx += 128) {
        int i = idx >> 7, k = idx & 127;
        int n = n0 + i;
        Hs[i][k] = (n < N_NODES) ? h[(size_t)n * HID + k] : 0.0f;
    }
    __syncthreads();

    int c = tid;
    float acc[32];
    #pragma unroll
    for (int i = 0; i < 32; i++) acc[i] = 0.0f;
    for (int k = 0; k < HID; k++) {
        float w = W1[(size_t)k * HID + c];
        #pragma unroll
        for (int i = 0; i < 32; i++) acc[i] = fmaf(Hs[i][k], w, acc[i]);
    }
    __syncthreads();

    float b1c = b1[c], w2c = W2[c];
    #pragma unroll
    for (int i = 0; i < 32; i++)
        Hs[i][c] = fmaxf(acc[i] + b1c, 0.0f) * w2c;
    __syncthreads();

    int warp = tid >> 5, lane = tid & 31;
    for (int i = warp; i < 32; i += 4) {
        float s = Hs[i][lane] + Hs[i][32 + lane] + Hs[i][64 + lane] + Hs[i][96 + lane];
        #pragma unroll
        for (int o = 16; o > 0; o >>= 1) s += __shfl_xor_sync(0xffffffffu, s, o);
        if (lane == 0) s_red[i] = s;
    }
    __syncthreads();
    if (tid < 32) {
        int n = n0 + tid;
        if (n < N_NODES) out[n] = s_red[tid] + b2[0];
    }
}

extern "C" void kernel_launch(void* const* d_in, const int* in_sizes, int n_in,
                              void* d_out, int out_size)
{
    const float* x      = (const float*)d_in[0];
    const int*   ei     = (const int*)  d_in[1];
    const float* eattr  = (const float*)d_in[2];
    const float* encW1  = (const float*)d_in[3];
    const float* encb1  = (const float*)d_in[4];
    const float* encW2  = (const float*)d_in[5];
    const float* encb2  = (const float*)d_in[6];
    const float* eeW    = (const float*)d_in[7];
    const float* eeb    = (const float*)d_in[8];
    const float* msgW1  = (const float*)d_in[9];
    const float* msgb1  = (const float*)d_in[10];
    const float* msgW2  = (const float*)d_in[11];
    const float* msgb2  = (const float*)d_in[12];
    const float* updW   = (const float*)d_in[13];
    const float* updb   = (const float*)d_in[14];
    const float* lng    = (const float*)d_in[15];
    const float* lnb    = (const float*)d_in[16];
    const float* decW1  = (const float*)d_in[17];
    const float* decb1  = (const float*)d_in[18];
    const float* decW2  = (const float*)d_in[19];
    const float* decb2  = (const float*)d_in[20];
    float* out = (float*)d_out;

    const int* src = ei;
    const int* dst = ei + N_EDGES;

    cudaFuncSetAttribute(edge_kernel, cudaFuncAttributeMaxDynamicSharedMemorySize, EDGE_SMEM);

    conv_w_kernel<<<N_LAYERS * 8, 128>>>(msgW1, msgW2);
    conv_e_kernel<<<N_TILES, 128>>>(eattr, eeW, eeb);

    zero_deg_kernel<<<(N_NODES + 255) / 256, 256>>>();
    deg_kernel<<<(N_EDGES + 255) / 256, 256>>>(dst);
    inv_kernel<<<(N_NODES + 255) / 256, 256>>>();
    encoder_kernel<<<(N_NODES + 31) / 32, 128>>>(x, encW1, encb1, encW2, encb2);
    conv_h_kernel<<<(N_NODES * 64 + 255) / 256, 256>>>(0);   // h in g_h

    for (int l = 0; l < N_LAYERS; l++) {
        int parity = l & 1;
        zero_aggr_kernel<<<((N_NODES * HID) + 511) / 512, 512>>>();
        edge_kernel<<<N_TILES, 256, EDGE_SMEM>>>(
            l, src, dst,
            msgb1 + (size_t)l * HID, msgb2 + (size_t)l * HID);
        node_kernel<<<(N_NODES + 31) / 32, 128>>>(
            parity,
            updW + (size_t)l * 2 * HID * HID, updb + (size_t)l * HID,
            lng + (size_t)l * HID, lnb + (size_t)l * HID);
        if (l < N_LAYERS - 1) {
            // node output buffer: parity==0 -> g_h2 (buf 1), parity==1 -> g_h (buf 0)
            conv_h_kernel<<<(N_NODES * 64 + 255) / 256, 256>>>(parity ? 0 : 1);
        }
    }
    decoder_kernel<<<(N_NODES + 31) / 32, 128>>>(0, decW1, decb1, decW2, decb2, out);
}

// round 11
// speedup vs baseline: 2.8670x; 1.2097x over previous
#include <cuda_runtime.h>
#include <cuda_bf16.h>
#include <cstdint>

#define N_NODES 50000
#define N_EDGES 600000
#define HID 128
#define N_LAYERS 6
#define N_TILES 4688          // ceil(600000/128)
#define N_NTILES 391          // ceil(50000/128)
#define N_PAD (N_NTILES * 128)

#define SWZ(x) ((x) ^ (((x) >> 3) & 0x70))

// ---- node_pre smem layout ----
#define NPA0_HI 0
#define NPA0_LO 16384
#define NPA1_HI 32768
#define NPA1_LO 49152
#define NPB_HI  65536
#define NPB_LO  81920
#define NP_SMEM 98304

// ---- edge smem layout ----
#define EA_HI 0
#define EA_LO 16384
#define EB_HI 32768
#define EB_LO 49152
#define EOFF_DST 65536
#define EOFF_SRC 66048
#define EOFF_B1  66560
#define E_SMEM   67072

// ---- scratch (no allocations allowed) ----
__device__ float g_h   [(size_t)N_NODES * HID];
__device__ float g_h2  [(size_t)N_NODES * HID];
__device__ float g_aggr[(size_t)N_NODES * HID];   // S = sum of relu(z)
__device__ float g_Pa  [(size_t)N_PAD * HID];
__device__ float g_Pb  [(size_t)N_PAD * HID];
__device__ float g_deg [N_NODES];
__device__ float g_inv [N_NODES];
// bf16 hi/lo images of current h: [n][128 cols] bf16 = 256B per node
__device__ unsigned char g_hbf_hi[(size_t)N_NODES * 256];
__device__ unsigned char g_hbf_lo[(size_t)N_NODES * 256];
// weight images: [layer][chunk 0..7][hi/lo][16KB]; [n][k] bf16x2 at SWZ(n*128+k*2)
// chunks 0,1=W1a  2,3=W1b  4,5=W1c  6,7=W2 (unused by MMA now)
__device__ unsigned char g_wimg[(size_t)N_LAYERS * 8 * 2 * 16384];
// edge-embedding images: [tile][half][hi/lo][16KB]; [r][k] bf16x2 at SWZ(r*128+k*2)
__device__ unsigned char g_eimg[(size_t)N_TILES * 2 * 2 * 16384];

// ================= helpers =================
__device__ __forceinline__ uint32_t smem_u32(const void* p) {
    uint32_t a;
    asm("{ .reg .u64 t; cvta.to.shared.u64 t, %1; cvt.u32.u64 %0, t; }" : "=r"(a) : "l"(p));
    return a;
}
__device__ __forceinline__ uint32_t bf16x2_of(float lo, float hi) {
    uint32_t r;
    asm("cvt.rn.bf16x2.f32 %0, %1, %2;" : "=r"(r) : "f"(hi), "f"(lo));
    return r;
}
__device__ __forceinline__ float lo_f(uint32_t p) { return __uint_as_float(p << 16); }
__device__ __forceinline__ float hi_f(uint32_t p) { return __uint_as_float(p & 0xffff0000u); }

__device__ __forceinline__ void ldsm_x4(uint32_t* r, uint32_t addr) {
    asm volatile("ldmatrix.sync.aligned.m8n8.x4.shared.b16 {%0,%1,%2,%3}, [%4];"
        : "=r"(r[0]), "=r"(r[1]), "=r"(r[2]), "=r"(r[3]) : "r"(addr));
}
__device__ __forceinline__ void mma_bf16(float* d, const uint32_t* a, const uint32_t* b) {
    asm volatile(
        "mma.sync.aligned.m16n8k16.row.col.f32.bf16.bf16.f32 "
        "{%0,%1,%2,%3}, {%4,%5,%6,%7}, {%8,%9}, {%0,%1,%2,%3};"
        : "+f"(d[0]), "+f"(d[1]), "+f"(d[2]), "+f"(d[3])
        : "r"(a[0]), "r"(a[1]), "r"(a[2]), "r"(a[3]), "r"(b[0]), "r"(b[1]));
}
__device__ __forceinline__ void red_v2(float* p, float v0, float v1) {
    asm volatile("red.global.add.v2.f32 [%0], {%1, %2};"
                 :: "l"(p), "f"(v0), "f"(v1) : "memory");
}

// packed f32x2 helpers (node kernel)
__device__ __forceinline__ unsigned long long pack2(float lo, float hi) {
    unsigned long long r;
    asm("mov.b64 %0, {%1, %2};" : "=l"(r) : "f"(lo), "f"(hi));
    return r;
}
__device__ __forceinline__ void unpack2(unsigned long long p, float& lo, float& hi) {
    asm("mov.b64 {%0, %1}, %2;" : "=f"(lo), "=f"(hi) : "l"(p));
}
__device__ __forceinline__ void fma2(unsigned long long& acc,
                                     unsigned long long a, unsigned long long b) {
    asm("fma.rn.f32x2 %0, %1, %2, %0;" : "+l"(acc) : "l"(a), "l"(b));
}

// ================= small kernels =================
__global__ void zero_aggr_kernel() {
    size_t i = (size_t)blockIdx.x * blockDim.x + threadIdx.x;
    if (i < (size_t)N_NODES * HID) g_aggr[i] = 0.0f;
}
__global__ void zero_deg_kernel() {
    int i = blockIdx.x * blockDim.x + threadIdx.x;
    if (i < N_NODES) g_deg[i] = 0.0f;
}
__global__ void deg_kernel(const int* __restrict__ dst) {
    int e = blockIdx.x * blockDim.x + threadIdx.x;
    if (e < N_EDGES) atomicAdd(&g_deg[dst[e]], 1.0f);
}
__global__ void inv_kernel() {
    int i = blockIdx.x * blockDim.x + threadIdx.x;
    if (i < N_NODES) {
        float d = g_deg[i];
        g_inv[i] = (d > 0.0f) ? (1.0f / d) : 0.0f;
    }
}

// ---- convert h (fp32, buf 0/1) -> bf16 hi/lo node images ----
__global__ __launch_bounds__(256) void conv_h_kernel(int buf) {
    size_t i = (size_t)blockIdx.x * blockDim.x + threadIdx.x;   // pair index
    if (i >= (size_t)N_NODES * 64) return;
    const float2 v = *((const float2*)(buf ? g_h2 : g_h) + i);
    uint32_t hi = bf16x2_of(v.x, v.y);
    uint32_t lo = bf16x2_of(v.x - lo_f(hi), v.y - hi_f(hi));
    ((uint32_t*)g_hbf_hi)[i] = hi;
    ((uint32_t*)g_hbf_lo)[i] = lo;
}

// ---- precompute: weight chunk images ([n][k] bf16 hi/lo, swizzled) ----
__global__ __launch_bounds__(128) void conv_w_kernel(
    const float* __restrict__ msgW1, const float* __restrict__ msgW2)
{
    int l = blockIdx.x >> 3, ch = blockIdx.x & 7, tid = threadIdx.x;
    const float* W = (ch < 6) ? (msgW1 + (size_t)l * 384 * 128 + (size_t)(64 * ch) * 128)
                              : (msgW2 + (size_t)l * 128 * 128 + (size_t)(64 * (ch - 6)) * 128);
    unsigned char* hiImg = g_wimg + ((size_t)(l * 8 + ch) * 2) * 16384;
    unsigned char* loImg = hiImg + 16384;
    for (int i = tid; i < 4096; i += 128) {
        int n = i & 127, kp = i >> 7;
        int k = kp * 2;
        float v0 = W[(size_t)k * 128 + n];
        float v1 = W[(size_t)(k + 1) * 128 + n];
        uint32_t hi = bf16x2_of(v0, v1);
        uint32_t lo = bf16x2_of(v0 - lo_f(hi), v1 - hi_f(hi));
        uint32_t byte = SWZ((uint32_t)(n * 128 + k * 2));
        *(uint32_t*)(hiImg + byte) = hi;
        *(uint32_t*)(loImg + byte) = lo;
    }
}

// ---- precompute: edge embedding images erow = relu(ea@eeW+eeb) ----
__global__ __launch_bounds__(128) void conv_e_kernel(
    const float* __restrict__ eattr, const float* __restrict__ eeW, const float* __restrict__ eeb)
{
    __shared__ float s_w[4 * HID];
    __shared__ float s_b[HID];
    int tid = threadIdx.x, t = blockIdx.x;
    for (int i = tid; i < 4 * HID; i += 128) s_w[i] = eeW[i];
    s_b[tid] = eeb[tid];
    __syncthreads();
    int e = t * 128 + tid;
    float a0 = 0, a1 = 0, a2 = 0, a3 = 0;
    if (e < N_EDGES) {
        const float4 ea = *(const float4*)(eattr + (size_t)e * 4);
        a0 = ea.x; a1 = ea.y; a2 = ea.z; a3 = ea.w;
    }
    unsigned char* base = g_eimg + (size_t)t * 4 * 16384;
    for (int kp = 0; kp < 64; kp++) {
        int k = kp * 2;
        float v0 = fmaxf(s_b[k]     + a0 * s_w[k]       + a1 * s_w[128 + k]
                                    + a2 * s_w[256 + k] + a3 * s_w[384 + k], 0.0f);
        float v1 = fmaxf(s_b[k + 1] + a0 * s_w[k + 1]       + a1 * s_w[128 + k + 1]
                                    + a2 * s_w[256 + k + 1] + a3 * s_w[384 + k + 1], 0.0f);
        uint32_t hi = bf16x2_of(v0, v1);
        uint32_t lo = bf16x2_of(v0 - lo_f(hi), v1 - hi_f(hi));
        int hh = k >> 6;
        uint32_t byte = SWZ((uint32_t)(tid * 128 + (k & 63) * 2));
        *(uint32_t*)(base + (size_t)(hh * 2) * 16384 + byte)     = hi;
        *(uint32_t*)(base + (size_t)(hh * 2 + 1) * 16384 + byte) = lo;
    }
}

// ---- encoder ----
__global__ __launch_bounds__(128) void encoder_kernel(
    const float* __restrict__ x,
    const float* __restrict__ W1, const float* __restrict__ b1,
    const float* __restrict__ W2, const float* __restrict__ b2)
{
    __shared__ float Hs[32][HID];
    __shared__ float xs[32][3];
    int tid = threadIdx.x;
    int n0 = blockIdx.x * 32;

    for (int idx = tid; idx < 32 * 3; idx += 128) {
        int i = idx / 3, j = idx % 3;
        int n = n0 + i;
        xs[i][j] = (n < N_NODES) ? x[(size_t)n * 3 + j] : 0.0f;
    }
    __syncthreads();

    int c = tid;
    float w0 = W1[c], w1 = W1[HID + c], w2 = W1[2 * HID + c], bc = b1[c];
    #pragma unroll 4
    for (int i = 0; i < 32; i++) {
        float v = bc + xs[i][0] * w0 + xs[i][1] * w1 + xs[i][2] * w2;
        Hs[i][c] = fmaxf(v, 0.0f);
    }
    __syncthreads();

    float acc[32];
    #pragma unroll
    for (int i = 0; i < 32; i++) acc[i] = 0.0f;
    for (int k = 0; k < HID; k++) {
        float w = W2[(size_t)k * HID + c];
        #pragma unroll
        for (int i = 0; i < 32; i++) acc[i] = fmaf(Hs[i][k], w, acc[i]);
    }
    float b2c = b2[c];
    for (int i = 0; i < 32; i++) {
        int n = n0 + i;
        if (n < N_NODES) g_h[(size_t)n * HID + c] = acc[i] + b2c;
    }
}

// ================ shared MMA chunk routine ================
__device__ __forceinline__ void run_chunk_mma(
    uint32_t aHi, uint32_t aLo, uint32_t bHi, uint32_t bLo,
    const int rbyte[4], const int xa[4], const int nbyte[2], const int xb[2],
    float acc[4][4][4])
{
    #pragma unroll
    for (int ks = 0; ks < 4; ks++) {
        int kb = ks * 32;
        uint32_t aH[4][4], aL[4][4], bH[2][4], bL[2][4];
        #pragma unroll
        for (int rt = 0; rt < 4; rt++) {
            uint32_t off = (uint32_t)((rbyte[rt] + kb) ^ xa[rt]);
            ldsm_x4(aH[rt], aHi + off);
            ldsm_x4(aL[rt], aLo + off);
        }
        #pragma unroll
        for (int cp = 0; cp < 2; cp++) {
            uint32_t off = (uint32_t)((nbyte[cp] + kb) ^ xb[cp]);
            ldsm_x4(bH[cp], bHi + off);
            ldsm_x4(bL[cp], bLo + off);
        }
        #pragma unroll
        for (int rt = 0; rt < 4; rt++)
            #pragma unroll
            for (int ct = 0; ct < 4; ct++) {
                const uint32_t* bh = &bH[ct >> 1][(ct & 1) * 2];
                const uint32_t* bl = &bL[ct >> 1][(ct & 1) * 2];
                mma_bf16(acc[rt][ct], aH[rt], bh);
                mma_bf16(acc[rt][ct], aH[rt], bl);
                mma_bf16(acc[rt][ct], aL[rt], bh);
            }
    }
}

__device__ __forceinline__ void ldsm_addrs(int lane, int wrow, int wcol,
                                           int rbyte[4], int xa[4], int nbyte[2], int xb[2])
{
    int q = lane >> 3, i8 = lane & 7;
    #pragma unroll
    for (int rt = 0; rt < 4; rt++) {
        int r = wrow + 16 * rt + i8 + 8 * (q & 1);
        rbyte[rt] = r * 128 + 16 * (q >> 1);
        xa[rt] = (r & 7) << 4;
    }
    #pragma unroll
    for (int cp = 0; cp < 2; cp++) {
        int n = wcol + 16 * cp + i8 + 8 * (q >> 1);
        nbyte[cp] = n * 128 + 16 * (q & 1);
        xb[cp] = (n & 7) << 4;
    }
}

// ================ node_pre: P_a = h@W1a, P_b = h@W1b ================
__global__ void __launch_bounds__(256) node_pre_kernel(int layer)
{
    extern __shared__ char dsm[];
    uint32_t sb = smem_u32(dsm);
    int tid = threadIdx.x, wid = tid >> 5, lane = tid & 31;
    int wrow = 64 * (wid >> 2), wcol = 32 * (wid & 3);
    int n0 = blockIdx.x * 128;
    const unsigned char* wimg = g_wimg + (size_t)layer * 8 * 2 * 16384;

    // stage A: both 64-col halves of h rows n0..n0+127 (bf16 hi/lo images)
    {
        int r = tid >> 1, half = tid & 1;
        int node = n0 + r; if (node >= N_NODES) node = N_NODES - 1;
        int rx = r & 7;
        #pragma unroll
        for (int hh = 0; hh < 2; hh++) {
            int sgbase = 8 * hh + half * 4;
            const uint4* pHi = (const uint4*)(g_hbf_hi + (size_t)node * 256) + sgbase;
            const uint4* pLo = (const uint4*)(g_hbf_lo + (size_t)node * 256) + sgbase;
            int abase = hh ? NPA1_HI : NPA0_HI;
            #pragma unroll
            for (int j = 0; j < 4; j++) {
                int dg = (half * 4 + j) ^ rx;
                *(uint4*)(dsm + abase + r * 128 + dg * 16) = pHi[j];
                *(uint4*)(dsm + abase + 16384 + r * 128 + dg * 16) = pLo[j];
            }
        }
    }

    int rbyte[4], xa[4], nbyte[2], xb[2];
    ldsm_addrs(lane, wrow, wcol, rbyte, xa, nbyte, xb);

    float acc[4][4][4];
    #pragma unroll
    for (int a = 0; a < 4; a++)
        #pragma unroll
        for (int b = 0; b < 4; b++)
            #pragma unroll
            for (int c = 0; c < 4; c++) acc[a][b][c] = 0.0f;

    for (int chunk = 0; chunk < 4; chunk++) {
        __syncthreads();                 // A visible (iter 0) / prior B reads done
        {
            const float4* whi = (const float4*)(wimg + (size_t)(chunk * 2) * 16384);
            const float4* wlo = whi + 1024;
            float4* dhi = (float4*)(dsm + NPB_HI);
            float4* dlo = (float4*)(dsm + NPB_LO);
            #pragma unroll
            for (int i = 0; i < 4; i++) {
                dhi[tid + 256 * i] = whi[tid + 256 * i];
                dlo[tid + 256 * i] = wlo[tid + 256 * i];
            }
        }
        __syncthreads();
        uint32_t aBase = sb + ((chunk & 1) ? NPA1_HI : NPA0_HI);
        run_chunk_mma(aBase, aBase + 16384, sb + NPB_HI, sb + NPB_LO,
                      rbyte, xa, nbyte, xb, acc);
        if (chunk & 1) {
            float* P = (chunk < 2) ? g_Pa : g_Pb;
            #pragma unroll
            for (int rt = 0; rt < 4; rt++) {
                int m1 = wrow + 16 * rt + (lane >> 2);
                int m2 = m1 + 8;
                #pragma unroll
                for (int ct = 0; ct < 4; ct++) {
                    int col = wcol + 8 * ct + 2 * (lane & 3);
                    if (n0 + m1 < N_NODES) {
                        float2 v = {acc[rt][ct][0], acc[rt][ct][1]};
                        *(float2*)(P + (size_t)(n0 + m1) * HID + col) = v;
                    }
                    if (n0 + m2 < N_NODES) {
                        float2 v = {acc[rt][ct][2], acc[rt][ct][3]};
                        *(float2*)(P + (size_t)(n0 + m2) * HID + col) = v;
                    }
                }
            }
            #pragma unroll
            for (int a = 0; a < 4; a++)
                #pragma unroll
                for (int b = 0; b < 4; b++)
                    #pragma unroll
                    for (int c = 0; c < 4; c++) acc[a][b][c] = 0.0f;
        }
    }
}

// ================ edge kernel: Pe MMA + gather-add + relu + scatter S ================
__global__ void __launch_bounds__(256) edge_kernel(
    int layer,
    const int* __restrict__ src, const int* __restrict__ dst,
    const float* __restrict__ b1)
{
    extern __shared__ char dsm[];
    uint32_t sb = smem_u32(dsm);
    int tid = threadIdx.x, wid = tid >> 5, lane = tid & 31;
    int wrow = 64 * (wid >> 2), wcol = 32 * (wid & 3);
    int t = blockIdx.x, e0 = t * 128;

    if (tid < 128) {
        int e = e0 + tid;
        ((int*)(dsm + EOFF_DST))[tid] = (e < N_EDGES) ? dst[e] : 0;
        ((int*)(dsm + EOFF_SRC))[tid] = (e < N_EDGES) ? src[e] : 0;
        ((float*)(dsm + EOFF_B1))[tid] = b1[tid];
    }
    const int* sd = (const int*)(dsm + EOFF_DST);
    const int* ssrc = (const int*)(dsm + EOFF_SRC);
    const float* sb1 = (const float*)(dsm + EOFF_B1);
    const unsigned char* wimg = g_wimg + (size_t)layer * 8 * 2 * 16384;

    int rbyte[4], xa[4], nbyte[2], xb[2];
    ldsm_addrs(lane, wrow, wcol, rbyte, xa, nbyte, xb);

    float acc[4][4][4];
    #pragma unroll
    for (int a = 0; a < 4; a++)
        #pragma unroll
        for (int b = 0; b < 4; b++)
            #pragma unroll
            for (int c = 0; c < 4; c++) acc[a][b][c] = 0.0f;

    // Pe = e-image @ W1c  (chunks 4,5)
    for (int c = 0; c < 2; c++) {
        if (c) __syncthreads();          // prior chunk reads done
        {
            const float4* ehi = (const float4*)(g_eimg + ((size_t)(t * 2 + c) * 2) * 16384);
            const float4* elo = ehi + 1024;
            const float4* whi = (const float4*)(wimg + (size_t)((4 + c) * 2) * 16384);
            const float4* wlo = whi + 1024;
            float4* dahi = (float4*)(dsm + EA_HI);
            float4* dalo = (float4*)(dsm + EA_LO);
            float4* dbhi = (float4*)(dsm + EB_HI);
            float4* dblo = (float4*)(dsm + EB_LO);
            #pragma unroll
            for (int i = 0; i < 4; i++) {
                dahi[tid + 256 * i] = ehi[tid + 256 * i];
                dalo[tid + 256 * i] = elo[tid + 256 * i];
                dbhi[tid + 256 * i] = whi[tid + 256 * i];
                dblo[tid + 256 * i] = wlo[tid + 256 * i];
            }
        }
        __syncthreads();
        run_chunk_mma(sb + EA_HI, sb + EA_LO, sb + EB_HI, sb + EB_LO,
                      rbyte, xa, nbyte, xb, acc);
    }

    // epilogue: z = Pe + b1 + Pa[dst] + Pb[src]; relu; scatter-add into S
    #pragma unroll
    for (int rt = 0; rt < 4; rt++) {
        int m1 = wrow + 16 * rt + (lane >> 2);
        int m2 = m1 + 8;
        bool v1ok = (e0 + m1) < N_EDGES;
        bool v2ok = (e0 + m2) < N_EDGES;
        int d1 = sd[m1], s1 = ssrc[m1];
        int d2 = sd[m2], s2 = ssrc[m2];
        const float* pa1 = g_Pa + (size_t)d1 * HID;
        const float* pb1 = g_Pb + (size_t)s1 * HID;
        const float* pa2 = g_Pa + (size_t)d2 * HID;
        const float* pb2 = g_Pb + (size_t)s2 * HID;
        float* ag1 = g_aggr + (size_t)d1 * HID;
        float* ag2 = g_aggr + (size_t)d2 * HID;
        #pragma unroll
        for (int ct = 0; ct < 4; ct++) {
            int col = wcol + 8 * ct + 2 * (lane & 3);
            float bv0 = sb1[col], bv1 = sb1[col + 1];
            if (v1ok) {
                float2 a = *(const float2*)(pa1 + col);
                float2 b = *(const float2*)(pb1 + col);
                float z0 = fmaxf(acc[rt][ct][0] + bv0 + a.x + b.x, 0.0f);
                float z1 = fmaxf(acc[rt][ct][1] + bv1 + a.y + b.y, 0.0f);
                red_v2(ag1 + col, z0, z1);
            }
            if (v2ok) {
                float2 a = *(const float2*)(pa2 + col);
                float2 b = *(const float2*)(pb2 + col);
                float z0 = fmaxf(acc[rt][ct][2] + bv0 + a.x + b.x, 0.0f);
                float z1 = fmaxf(acc[rt][ct][3] + bv1 + a.y + b.y, 0.0f);
                red_v2(ag2 + col, z0, z1);
            }
        }
    }
}

// ---- node_post: u = (S*inv)@W2 + b2[deg>0]; upd = relu([h,u]@W+b); LN(h+upd) ----
__global__ __launch_bounds__(128) void node_post_kernel(
    int parity,
    const float* __restrict__ W2, const float* __restrict__ b2,
    const float* __restrict__ W, const float* __restrict__ b,
    const float* __restrict__ lg, const float* __restrict__ lb)
{
    __shared__ float As[32][2 * HID];
    __shared__ float s_mu[32], s_rs[32];

    const float* __restrict__ h    = parity ? g_h2 : g_h;
    float*       __restrict__ hout = parity ? g_h  : g_h2;

    int tid = threadIdx.x;
    int n0 = blockIdx.x * 32;

    // load [h | S*inv]
    for (int idx = tid; idx < 32 * 2 * HID; idx += 128) {
        int i = idx >> 8;
        int k = idx & 255;
        int n = n0 + i;
        float v = 0.0f;
        if (n < N_NODES)
            v = (k < HID) ? h[(size_t)n * HID + k]
                          : g_aggr[(size_t)n * HID + (k - HID)] * g_inv[n];
        As[i][k] = v;
    }
    __syncthreads();

    int c = tid;
    // ---- stage 1: u = (S*inv)@W2 (+ b2 where deg>0) ----
    {
        unsigned long long accP[32];
        #pragma unroll
        for (int i = 0; i < 32; i++) accP[i] = 0ull;
        for (int kp = 0; kp < 64; kp++) {
            float w0 = W2[(size_t)(2 * kp) * HID + c];
            float w1 = W2[(size_t)(2 * kp + 1) * HID + c];
            unsigned long long wP = pack2(w0, w1);
            #pragma unroll
            for (int i = 0; i < 32; i++) {
                unsigned long long aP =
                    *reinterpret_cast<const unsigned long long*>(&As[i][HID + 2 * kp]);
                fma2(accP[i], aP, wP);
            }
        }
        float u[32];
        float b2c = b2[c];
        #pragma unroll
        for (int i = 0; i < 32; i++) {
            float lo, hi;
            unpack2(accP[i], lo, hi);
            int n = n0 + i;
            float hasdeg = (n < N_NODES && g_deg[n] > 0.0f) ? 1.0f : 0.0f;
            u[i] = lo + hi + hasdeg * b2c;
        }
        __syncthreads();   // all reads of As upper done
        #pragma unroll
        for (int i = 0; i < 32; i++) As[i][HID + c] = u[i];
    }
    __syncthreads();

    // ---- stage 2: upd GEMM over [h | u], K=256 ----
    unsigned long long accP[32];
    #pragma unroll
    for (int i = 0; i < 32; i++) accP[i] = 0ull;
    for (int kp = 0; kp < HID; kp++) {
        float w0 = W[(size_t)(2 * kp) * HID + c];
        float w1 = W[(size_t)(2 * kp + 1) * HID + c];
        unsigned long long wP = pack2(w0, w1);
        #pragma unroll
        for (int i = 0; i < 32; i++) {
            unsigned long long aP =
                *reinterpret_cast<const unsigned long long*>(&As[i][2 * kp]);
            fma2(accP[i], aP, wP);
        }
    }
    float acc[32];
    #pragma unroll
    for (int i = 0; i < 32; i++) {
        float lo, hi;
        unpack2(accP[i], lo, hi);
        acc[i] = lo + hi;
    }
    __syncthreads();

    float bc = b[c];
    #pragma unroll
    for (int i = 0; i < 32; i++) {
        float r = As[i][c] + fmaxf(acc[i] + bc, 0.0f);
        As[i][HID + c] = r;
    }
    __syncthreads();

    int warp = tid >> 5, lane = tid & 31;
    for (int i = warp; i < 32; i += 4) {
        float v0 = As[i][HID + lane],      v1 = As[i][HID + 32 + lane];
        float v2 = As[i][HID + 64 + lane], v3 = As[i][HID + 96 + lane];
        float s = v0 + v1 + v2 + v3;
        float qq = v0 * v0 + v1 * v1 + v2 * v2 + v3 * v3;
        #pragma unroll
        for (int o = 16; o > 0; o >>= 1) {
            s += __shfl_xor_sync(0xffffffffu, s, o);
            qq += __shfl_xor_sync(0xffffffffu, qq, o);
        }
        if (lane == 0) {
            float mu = s * (1.0f / HID);
            float var = qq * (1.0f / HID) - mu * mu;
            s_mu[i] = mu;
            s_rs[i] = rsqrtf(var + 1e-5f);
        }
    }
    __syncthreads();

    float gc = lg[c], lbc = lb[c];
    for (int i = 0; i < 32; i++) {
        int n = n0 + i;
        if (n < N_NODES)
            hout[(size_t)n * HID + c] = (As[i][HID + c] - s_mu[i]) * s_rs[i] * gc + lbc;
    }
}

// ---- decoder ----
__global__ __launch_bounds__(128) void decoder_kernel(
    int parity,
    const float* __restrict__ W1, const float* __restrict__ b1,
    const float* __restrict__ W2, const float* __restrict__ b2,
    float* __restrict__ out)
{
    __shared__ float Hs[32][HID];
    __shared__ float s_red[32];

    const float* __restrict__ h = parity ? g_h2 : g_h;

    int tid = threadIdx.x;
    int n0 = blockIdx.x * 32;

    for (int idx = tid; idx < 32 * HID; idx += 128) {
        int i = idx >> 7, k = idx & 127;
        int n = n0 + i;
        Hs[i][k] = (n < N_NODES) ? h[(size_t)n * HID + k] : 0.0f;
    }
    __syncthreads();

    int c = tid;
    float acc[32];
    #pragma unroll
    for (int i = 0; i < 32; i++) acc[i] = 0.0f;
    for (int k = 0; k < HID; k++) {
        float w = W1[(size_t)k * HID + c];
        #pragma unroll
        for (int i = 0; i < 32; i++) acc[i] = fmaf(Hs[i][k], w, acc[i]);
    }
    __syncthreads();

    float b1c = b1[c], w2c = W2[c];
    #pragma unroll
    for (int i = 0; i < 32; i++)
        Hs[i][c] = fmaxf(acc[i] + b1c, 0.0f) * w2c;
    __syncthreads();

    int warp = tid >> 5, lane = tid & 31;
    for (int i = warp; i < 32; i += 4) {
        float s = Hs[i][lane] + Hs[i][32 + lane] + Hs[i][64 + lane] + Hs[i][96 + lane];
        #pragma unroll
        for (int o = 16; o > 0; o >>= 1) s += __shfl_xor_sync(0xffffffffu, s, o);
        if (lane == 0) s_red[i] = s;
    }
    __syncthreads();
    if (tid < 32) {
        int n = n0 + tid;
        if (n < N_NODES) out[n] = s_red[tid] + b2[0];
    }
}

extern "C" void kernel_launch(void* const* d_in, const int* in_sizes, int n_in,
                              void* d_out, int out_size)
{
    const float* x      = (const float*)d_in[0];
    const int*   ei     = (const int*)  d_in[1];
    const float* eattr  = (const float*)d_in[2];
    const float* encW1  = (const float*)d_in[3];
    const float* encb1  = (const float*)d_in[4];
    const float* encW2  = (const float*)d_in[5];
    const float* encb2  = (const float*)d_in[6];
    const float* eeW    = (const float*)d_in[7];
    const float* eeb    = (const float*)d_in[8];
    const float* msgW1  = (const float*)d_in[9];
    const float* msgb1  = (const float*)d_in[10];
    const float* msgW2  = (const float*)d_in[11];
    const float* msgb2  = (const float*)d_in[12];
    const float* updW   = (const float*)d_in[13];
    const float* updb   = (const float*)d_in[14];
    const float* lng    = (const float*)d_in[15];
    const float* lnb    = (const float*)d_in[16];
    const float* decW1  = (const float*)d_in[17];
    const float* decb1  = (const float*)d_in[18];
    const float* decW2  = (const float*)d_in[19];
    const float* decb2  = (const float*)d_in[20];
    float* out = (float*)d_out;

    const int* src = ei;
    const int* dst = ei + N_EDGES;

    cudaFuncSetAttribute(edge_kernel, cudaFuncAttributeMaxDynamicSharedMemorySize, E_SMEM);
    cudaFuncSetAttribute(node_pre_kernel, cudaFuncAttributeMaxDynamicSharedMemorySize, NP_SMEM);

    conv_w_kernel<<<N_LAYERS * 8, 128>>>(msgW1, msgW2);
    conv_e_kernel<<<N_TILES, 128>>>(eattr, eeW, eeb);

    zero_deg_kernel<<<(N_NODES + 255) / 256, 256>>>();
    deg_kernel<<<(N_EDGES + 255) / 256, 256>>>(dst);
    inv_kernel<<<(N_NODES + 255) / 256, 256>>>();
    encoder_kernel<<<(N_NODES + 31) / 32, 128>>>(x, encW1, encb1, encW2, encb2);
    conv_h_kernel<<<(N_NODES * 64 + 255) / 256, 256>>>(0);   // h in g_h

    for (int l = 0; l < N_LAYERS; l++) {
        int parity = l & 1;
        node_pre_kernel<<<N_NTILES, 256, NP_SMEM>>>(l);
        zero_aggr_kernel<<<((N_NODES * HID) + 511) / 512, 512>>>();
        edge_kernel<<<N_TILES, 256, E_SMEM>>>(l, src, dst, msgb1 + (size_t)l * HID);
        node_post_kernel<<<(N_NODES + 31) / 32, 128>>>(
            parity,
            msgW2 + (size_t)l * HID * HID, msgb2 + (size_t)l * HID,
            updW + (size_t)l * 2 * HID * HID, updb + (size_t)l * HID,
            lng + (size_t)l * HID, lnb + (size_t)l * HID);
        if (l < N_LAYERS - 1) {
            conv_h_kernel<<<(N_NODES * 64 + 255) / 256, 256>>>(parity ? 0 : 1);
        }
    }
    decoder_kernel<<<(N_NODES + 31) / 32, 128>>>(0, decW1, decb1, decW2, decb2, out);
}

// round 12
// speedup vs baseline: 2.8681x; 1.0004x over previous
#include <cuda_runtime.h>
#include <cuda_bf16.h>
#include <cstdint>

#define N_NODES 50000
#define N_EDGES 600000
#define HID 128
#define N_LAYERS 6
#define N_TILES 4688          // ceil(600000/128)
#define N_NTILES 391          // ceil(50000/128)
#define N_PAD (N_NTILES * 128)

#define SWZ(x) ((x) ^ (((x) >> 3) & 0x70))

// ---- node_pre smem layout ----
#define NPA0_HI 0
#define NPA0_LO 16384
#define NPA1_HI 32768
#define NPA1_LO 49152
#define NPB_HI  65536
#define NPB_LO  81920
#define NP_SMEM 98304

// ---- edge smem layout ----
#define EA_HI 0
#define EA_LO 16384
#define EB_HI 32768
#define EB_LO 49152
#define EOFF_DST 65536
#define EOFF_SRC 66048
#define EOFF_B1  66560
#define E_SMEM   67072

// ---- scratch (no allocations allowed) ----
__device__ float g_h   [(size_t)N_NODES * HID];
__device__ float g_h2  [(size_t)N_NODES * HID];
__device__ float g_aggr[(size_t)N_NODES * HID];   // S = sum of relu(z)
__device__ float g_Pa  [(size_t)N_PAD * HID];
__device__ float g_Pb  [(size_t)N_PAD * HID];
__device__ float g_deg [N_NODES];
__device__ float g_inv [N_NODES];
// bf16 hi/lo images of current h: [n][128 cols] bf16 = 256B per node
__device__ unsigned char g_hbf_hi[(size_t)N_NODES * 256];
__device__ unsigned char g_hbf_lo[(size_t)N_NODES * 256];
// weight images: [layer][chunk 0..7][hi/lo][16KB]; [n][k] bf16x2 at SWZ(n*128+k*2)
// chunks 0,1=W1a  2,3=W1b  4,5=W1c  6,7=W2 (unused by MMA now)
__device__ unsigned char g_wimg[(size_t)N_LAYERS * 8 * 2 * 16384];
// edge-embedding images: [tile][half][hi/lo][16KB]; [r][k] bf16x2 at SWZ(r*128+k*2)
__device__ unsigned char g_eimg[(size_t)N_TILES * 2 * 2 * 16384];

// ================= helpers =================
__device__ __forceinline__ uint32_t smem_u32(const void* p) {
    uint32_t a;
    asm("{ .reg .u64 t; cvta.to.shared.u64 t, %1; cvt.u32.u64 %0, t; }" : "=r"(a) : "l"(p));
    return a;
}
__device__ __forceinline__ uint32_t bf16x2_of(float lo, float hi) {
    uint32_t r;
    asm("cvt.rn.bf16x2.f32 %0, %1, %2;" : "=r"(r) : "f"(hi), "f"(lo));
    return r;
}
__device__ __forceinline__ float lo_f(uint32_t p) { return __uint_as_float(p << 16); }
__device__ __forceinline__ float hi_f(uint32_t p) { return __uint_as_float(p & 0xffff0000u); }

__device__ __forceinline__ void ldsm_x4(uint32_t* r, uint32_t addr) {
    asm volatile("ldmatrix.sync.aligned.m8n8.x4.shared.b16 {%0,%1,%2,%3}, [%4];"
        : "=r"(r[0]), "=r"(r[1]), "=r"(r[2]), "=r"(r[3]) : "r"(addr));
}
__device__ __forceinline__ void mma_bf16(float* d, const uint32_t* a, const uint32_t* b) {
    asm volatile(
        "mma.sync.aligned.m16n8k16.row.col.f32.bf16.bf16.f32 "
        "{%0,%1,%2,%3}, {%4,%5,%6,%7}, {%8,%9}, {%0,%1,%2,%3};"
        : "+f"(d[0]), "+f"(d[1]), "+f"(d[2]), "+f"(d[3])
        : "r"(a[0]), "r"(a[1]), "r"(a[2]), "r"(a[3]), "r"(b[0]), "r"(b[1]));
}
__device__ __forceinline__ void red_v2(float* p, float v0, float v1) {
    asm volatile("red.global.add.v2.f32 [%0], {%1, %2};"
                 :: "l"(p), "f"(v0), "f"(v1) : "memory");
}

// packed f32x2 helpers (node kernel)
__device__ __forceinline__ unsigned long long pack2(float lo, float hi) {
    unsigned long long r;
    asm("mov.b64 %0, {%1, %2};" : "=l"(r) : "f"(lo), "f"(hi));
    return r;
}
__device__ __forceinline__ void unpack2(unsigned long long p, float& lo, float& hi) {
    asm("mov.b64 {%0, %1}, %2;" : "=f"(lo), "=f"(hi) : "l"(p));
}
__device__ __forceinline__ void fma2(unsigned long long& acc,
                                     unsigned long long a, unsigned long long b) {
    asm("fma.rn.f32x2 %0, %1, %2, %0;" : "+l"(acc) : "l"(a), "l"(b));
}

// ================= small kernels =================
__global__ void zero_aggr_kernel() {
    size_t i = (size_t)blockIdx.x * blockDim.x + threadIdx.x;
    if (i < (size_t)N_NODES * HID) g_aggr[i] = 0.0f;
}
__global__ void zero_deg_kernel() {
    int i = blockIdx.x * blockDim.x + threadIdx.x;
    if (i < N_NODES) g_deg[i] = 0.0f;
}
__global__ void deg_kernel(const int* __restrict__ dst) {
    int e = blockIdx.x * blockDim.x + threadIdx.x;
    if (e < N_EDGES) atomicAdd(&g_deg[dst[e]], 1.0f);
}
__global__ void inv_kernel() {
    int i = blockIdx.x * blockDim.x + threadIdx.x;
    if (i < N_NODES) {
        float d = g_deg[i];
        g_inv[i] = (d > 0.0f) ? (1.0f / d) : 0.0f;
    }
}

// ---- convert h (fp32, buf 0/1) -> bf16 hi/lo node images ----
__global__ __launch_bounds__(256) void conv_h_kernel(int buf) {
    size_t i = (size_t)blockIdx.x * blockDim.x + threadIdx.x;   // pair index
    if (i >= (size_t)N_NODES * 64) return;
    const float2 v = *((const float2*)(buf ? g_h2 : g_h) + i);
    uint32_t hi = bf16x2_of(v.x, v.y);
    uint32_t lo = bf16x2_of(v.x - lo_f(hi), v.y - hi_f(hi));
    ((uint32_t*)g_hbf_hi)[i] = hi;
    ((uint32_t*)g_hbf_lo)[i] = lo;
}

// ---- precompute: weight chunk images ([n][k] bf16 hi/lo, swizzled) ----
__global__ __launch_bounds__(128) void conv_w_kernel(
    const float* __restrict__ msgW1, const float* __restrict__ msgW2)
{
    int l = blockIdx.x >> 3, ch = blockIdx.x & 7, tid = threadIdx.x;
    const float* W = (ch < 6) ? (msgW1 + (size_t)l * 384 * 128 + (size_t)(64 * ch) * 128)
                              : (msgW2 + (size_t)l * 128 * 128 + (size_t)(64 * (ch - 6)) * 128);
    unsigned char* hiImg = g_wimg + ((size_t)(l * 8 + ch) * 2) * 16384;
    unsigned char* loImg = hiImg + 16384;
    for (int i = tid; i < 4096; i += 128) {
        int n = i & 127, kp = i >> 7;
        int k = kp * 2;
        float v0 = W[(size_t)k * 128 + n];
        float v1 = W[(size_t)(k + 1) * 128 + n];
        uint32_t hi = bf16x2_of(v0, v1);
        uint32_t lo = bf16x2_of(v0 - lo_f(hi), v1 - hi_f(hi));
        uint32_t byte = SWZ((uint32_t)(n * 128 + k * 2));
        *(uint32_t*)(hiImg + byte) = hi;
        *(uint32_t*)(loImg + byte) = lo;
    }
}

// ---- precompute: edge embedding images erow = relu(ea@eeW+eeb) ----
__global__ __launch_bounds__(128) void conv_e_kernel(
    const float* __restrict__ eattr, const float* __restrict__ eeW, const float* __restrict__ eeb)
{
    __shared__ float s_w[4 * HID];
    __shared__ float s_b[HID];
    int tid = threadIdx.x, t = blockIdx.x;
    for (int i = tid; i < 4 * HID; i += 128) s_w[i] = eeW[i];
    s_b[tid] = eeb[tid];
    __syncthreads();
    int e = t * 128 + tid;
    float a0 = 0, a1 = 0, a2 = 0, a3 = 0;
    if (e < N_EDGES) {
        const float4 ea = *(const float4*)(eattr + (size_t)e * 4);
        a0 = ea.x; a1 = ea.y; a2 = ea.z; a3 = ea.w;
    }
    unsigned char* base = g_eimg + (size_t)t * 4 * 16384;
    for (int kp = 0; kp < 64; kp++) {
        int k = kp * 2;
        float v0 = fmaxf(s_b[k]     + a0 * s_w[k]       + a1 * s_w[128 + k]
                                    + a2 * s_w[256 + k] + a3 * s_w[384 + k], 0.0f);
        float v1 = fmaxf(s_b[k + 1] + a0 * s_w[k + 1]       + a1 * s_w[128 + k + 1]
                                    + a2 * s_w[256 + k + 1] + a3 * s_w[384 + k + 1], 0.0f);
        uint32_t hi = bf16x2_of(v0, v1);
        uint32_t lo = bf16x2_of(v0 - lo_f(hi), v1 - hi_f(hi));
        int hh = k >> 6;
        uint32_t byte = SWZ((uint32_t)(tid * 128 + (k & 63) * 2));
        *(uint32_t*)(base + (size_t)(hh * 2) * 16384 + byte)     = hi;
        *(uint32_t*)(base + (size_t)(hh * 2 + 1) * 16384 + byte) = lo;
    }
}

// ---- encoder ----
__global__ __launch_bounds__(128) void encoder_kernel(
    const float* __restrict__ x,
    const float* __restrict__ W1, const float* __restrict__ b1,
    const float* __restrict__ W2, const float* __restrict__ b2)
{
    __shared__ float Hs[32][HID];
    __shared__ float xs[32][3];
    int tid = threadIdx.x;
    int n0 = blockIdx.x * 32;

    for (int idx = tid; idx < 32 * 3; idx += 128) {
        int i = idx / 3, j = idx % 3;
        int n = n0 + i;
        xs[i][j] = (n < N_NODES) ? x[(size_t)n * 3 + j] : 0.0f;
    }
    __syncthreads();

    int c = tid;
    float w0 = W1[c], w1 = W1[HID + c], w2 = W1[2 * HID + c], bc = b1[c];
    #pragma unroll 4
    for (int i = 0; i < 32; i++) {
        float v = bc + xs[i][0] * w0 + xs[i][1] * w1 + xs[i][2] * w2;
        Hs[i][c] = fmaxf(v, 0.0f);
    }
    __syncthreads();

    float acc[32];
    #pragma unroll
    for (int i = 0; i < 32; i++) acc[i] = 0.0f;
    for (int k = 0; k < HID; k++) {
        float w = W2[(size_t)k * HID + c];
        #pragma unroll
        for (int i = 0; i < 32; i++) acc[i] = fmaf(Hs[i][k], w, acc[i]);
    }
    float b2c = b2[c];
    for (int i = 0; i < 32; i++) {
        int n = n0 + i;
        if (n < N_NODES) g_h[(size_t)n * HID + c] = acc[i] + b2c;
    }
}

// ================ shared MMA chunk routine ================
__device__ __forceinline__ void run_chunk_mma(
    uint32_t aHi, uint32_t aLo, uint32_t bHi, uint32_t bLo,
    const int rbyte[4], const int xa[4], const int nbyte[2], const int xb[2],
    float acc[4][4][4])
{
    #pragma unroll
    for (int ks = 0; ks < 4; ks++) {
        int kb = ks * 32;
        uint32_t aH[4][4], aL[4][4], bH[2][4], bL[2][4];
        #pragma unroll
        for (int rt = 0; rt < 4; rt++) {
            uint32_t off = (uint32_t)((rbyte[rt] + kb) ^ xa[rt]);
            ldsm_x4(aH[rt], aHi + off);
            ldsm_x4(aL[rt], aLo + off);
        }
        #pragma unroll
        for (int cp = 0; cp < 2; cp++) {
            uint32_t off = (uint32_t)((nbyte[cp] + kb) ^ xb[cp]);
            ldsm_x4(bH[cp], bHi + off);
            ldsm_x4(bL[cp], bLo + off);
        }
        #pragma unroll
        for (int rt = 0; rt < 4; rt++)
            #pragma unroll
            for (int ct = 0; ct < 4; ct++) {
                const uint32_t* bh = &bH[ct >> 1][(ct & 1) * 2];
                const uint32_t* bl = &bL[ct >> 1][(ct & 1) * 2];
                mma_bf16(acc[rt][ct], aH[rt], bh);
                mma_bf16(acc[rt][ct], aH[rt], bl);
                mma_bf16(acc[rt][ct], aL[rt], bh);
            }
    }
}

__device__ __forceinline__ void ldsm_addrs(int lane, int wrow, int wcol,
                                           int rbyte[4], int xa[4], int nbyte[2], int xb[2])
{
    int q = lane >> 3, i8 = lane & 7;
    #pragma unroll
    for (int rt = 0; rt < 4; rt++) {
        int r = wrow + 16 * rt + i8 + 8 * (q & 1);
        rbyte[rt] = r * 128 + 16 * (q >> 1);
        xa[rt] = (r & 7) << 4;
    }
    #pragma unroll
    for (int cp = 0; cp < 2; cp++) {
        int n = wcol + 16 * cp + i8 + 8 * (q >> 1);
        nbyte[cp] = n * 128 + 16 * (q & 1);
        xb[cp] = (n & 7) << 4;
    }
}

// ================ node_pre: P_a = h@W1a, P_b = h@W1b ================
__global__ void __launch_bounds__(256) node_pre_kernel(int layer)
{
    extern __shared__ char dsm[];
    uint32_t sb = smem_u32(dsm);
    int tid = threadIdx.x, wid = tid >> 5, lane = tid & 31;
    int wrow = 64 * (wid >> 2), wcol = 32 * (wid & 3);
    int n0 = blockIdx.x * 128;
    const unsigned char* wimg = g_wimg + (size_t)layer * 8 * 2 * 16384;

    // stage A: both 64-col halves of h rows n0..n0+127 (bf16 hi/lo images)
    {
        int r = tid >> 1, half = tid & 1;
        int node = n0 + r; if (node >= N_NODES) node = N_NODES - 1;
        int rx = r & 7;
        #pragma unroll
        for (int hh = 0; hh < 2; hh++) {
            int sgbase = 8 * hh + half * 4;
            const uint4* pHi = (const uint4*)(g_hbf_hi + (size_t)node * 256) + sgbase;
            const uint4* pLo = (const uint4*)(g_hbf_lo + (size_t)node * 256) + sgbase;
            int abase = hh ? NPA1_HI : NPA0_HI;
            #pragma unroll
            for (int j = 0; j < 4; j++) {
                int dg = (half * 4 + j) ^ rx;
                *(uint4*)(dsm + abase + r * 128 + dg * 16) = pHi[j];
                *(uint4*)(dsm + abase + 16384 + r * 128 + dg * 16) = pLo[j];
            }
        }
    }

    int rbyte[4], xa[4], nbyte[2], xb[2];
    ldsm_addrs(lane, wrow, wcol, rbyte, xa, nbyte, xb);

    float acc[4][4][4];
    #pragma unroll
    for (int a = 0; a < 4; a++)
        #pragma unroll
        for (int b = 0; b < 4; b++)
            #pragma unroll
            for (int c = 0; c < 4; c++) acc[a][b][c] = 0.0f;

    for (int chunk = 0; chunk < 4; chunk++) {
        __syncthreads();                 // A visible (iter 0) / prior B reads done
        {
            const float4* whi = (const float4*)(wimg + (size_t)(chunk * 2) * 16384);
            const float4* wlo = whi + 1024;
            float4* dhi = (float4*)(dsm + NPB_HI);
            float4* dlo = (float4*)(dsm + NPB_LO);
            #pragma unroll
            for (int i = 0; i < 4; i++) {
                dhi[tid + 256 * i] = whi[tid + 256 * i];
                dlo[tid + 256 * i] = wlo[tid + 256 * i];
            }
        }
        __syncthreads();
        uint32_t aBase = sb + ((chunk & 1) ? NPA1_HI : NPA0_HI);
        run_chunk_mma(aBase, aBase + 16384, sb + NPB_HI, sb + NPB_LO,
                      rbyte, xa, nbyte, xb, acc);
        if (chunk & 1) {
            float* P = (chunk < 2) ? g_Pa : g_Pb;
            #pragma unroll
            for (int rt = 0; rt < 4; rt++) {
                int m1 = wrow + 16 * rt + (lane >> 2);
                int m2 = m1 + 8;
                #pragma unroll
                for (int ct = 0; ct < 4; ct++) {
                    int col = wcol + 8 * ct + 2 * (lane & 3);
                    if (n0 + m1 < N_NODES) {
                        float2 v = {acc[rt][ct][0], acc[rt][ct][1]};
                        *(float2*)(P + (size_t)(n0 + m1) * HID + col) = v;
                    }
                    if (n0 + m2 < N_NODES) {
                        float2 v = {acc[rt][ct][2], acc[rt][ct][3]};
                        *(float2*)(P + (size_t)(n0 + m2) * HID + col) = v;
                    }
                }
            }
            #pragma unroll
            for (int a = 0; a < 4; a++)
                #pragma unroll
                for (int b = 0; b < 4; b++)
                    #pragma unroll
                    for (int c = 0; c < 4; c++) acc[a][b][c] = 0.0f;
        }
    }
}

// ================ edge kernel: Pe MMA + gather-add + relu + scatter S ================
__global__ void __launch_bounds__(256) edge_kernel(
    int layer,
    const int* __restrict__ src, const int* __restrict__ dst,
    const float* __restrict__ b1)
{
    extern __shared__ char dsm[];
    uint32_t sb = smem_u32(dsm);
    int tid = threadIdx.x, wid = tid >> 5, lane = tid & 31;
    int wrow = 64 * (wid >> 2), wcol = 32 * (wid & 3);
    int t = blockIdx.x, e0 = t * 128;

    if (tid < 128) {
        int e = e0 + tid;
        ((int*)(dsm + EOFF_DST))[tid] = (e < N_EDGES) ? dst[e] : 0;
        ((int*)(dsm + EOFF_SRC))[tid] = (e < N_EDGES) ? src[e] : 0;
        ((float*)(dsm + EOFF_B1))[tid] = b1[tid];
    }
    const int* sd = (const int*)(dsm + EOFF_DST);
    const int* ssrc = (const int*)(dsm + EOFF_SRC);
    const float* sb1 = (const float*)(dsm + EOFF_B1);
    const unsigned char* wimg = g_wimg + (size_t)layer * 8 * 2 * 16384;

    int rbyte[4], xa[4], nbyte[2], xb[2];
    ldsm_addrs(lane, wrow, wcol, rbyte, xa, nbyte, xb);

    float acc[4][4][4];
    #pragma unroll
    for (int a = 0; a < 4; a++)
        #pragma unroll
        for (int b = 0; b < 4; b++)
            #pragma unroll
            for (int c = 0; c < 4; c++) acc[a][b][c] = 0.0f;

    // Pe = e-image @ W1c  (chunks 4,5)
    for (int c = 0; c < 2; c++) {
        if (c) __syncthreads();          // prior chunk reads done
        {
            const float4* ehi = (const float4*)(g_eimg + ((size_t)(t * 2 + c) * 2) * 16384);
            const float4* elo = ehi + 1024;
            const float4* whi = (const float4*)(wimg + (size_t)((4 + c) * 2) * 16384);
            const float4* wlo = whi + 1024;
            float4* dahi = (float4*)(dsm + EA_HI);
            float4* dalo = (float4*)(dsm + EA_LO);
            float4* dbhi = (float4*)(dsm + EB_HI);
            float4* dblo = (float4*)(dsm + EB_LO);
            #pragma unroll
            for (int i = 0; i < 4; i++) {
                dahi[tid + 256 * i] = ehi[tid + 256 * i];
                dalo[tid + 256 * i] = elo[tid + 256 * i];
                dbhi[tid + 256 * i] = whi[tid + 256 * i];
                dblo[tid + 256 * i] = wlo[tid + 256 * i];
            }
        }
        __syncthreads();
        run_chunk_mma(sb + EA_HI, sb + EA_LO, sb + EB_HI, sb + EB_LO,
                      rbyte, xa, nbyte, xb, acc);
    }

    // epilogue: z = Pe + b1 + Pa[dst] + Pb[src]; relu; scatter-add into S
    #pragma unroll
    for (int rt = 0; rt < 4; rt++) {
        int m1 = wrow + 16 * rt + (lane >> 2);
        int m2 = m1 + 8;
        bool v1ok = (e0 + m1) < N_EDGES;
        bool v2ok = (e0 + m2) < N_EDGES;
        int d1 = sd[m1], s1 = ssrc[m1];
        int d2 = sd[m2], s2 = ssrc[m2];
        const float* pa1 = g_Pa + (size_t)d1 * HID;
        const float* pb1 = g_Pb + (size_t)s1 * HID;
        const float* pa2 = g_Pa + (size_t)d2 * HID;
        const float* pb2 = g_Pb + (size_t)s2 * HID;
        float* ag1 = g_aggr + (size_t)d1 * HID;
        float* ag2 = g_aggr + (size_t)d2 * HID;
        #pragma unroll
        for (int ct = 0; ct < 4; ct++) {
            int col = wcol + 8 * ct + 2 * (lane & 3);
            float bv0 = sb1[col], bv1 = sb1[col + 1];
            if (v1ok) {
                float2 a = *(const float2*)(pa1 + col);
                float2 b = *(const float2*)(pb1 + col);
                float z0 = fmaxf(acc[rt][ct][0] + bv0 + a.x + b.x, 0.0f);
                float z1 = fmaxf(acc[rt][ct][1] + bv1 + a.y + b.y, 0.0f);
                red_v2(ag1 + col, z0, z1);
            }
            if (v2ok) {
                float2 a = *(const float2*)(pa2 + col);
                float2 b = *(const float2*)(pb2 + col);
                float z0 = fmaxf(acc[rt][ct][2] + bv0 + a.x + b.x, 0.0f);
                float z1 = fmaxf(acc[rt][ct][3] + bv1 + a.y + b.y, 0.0f);
                red_v2(ag2 + col, z0, z1);
            }
        }
    }
}

// ---- node_post: u = (S*inv)@W2 + b2[deg>0]; upd = relu([h,u]@W+b); LN(h+upd) ----
__global__ __launch_bounds__(128) void node_post_kernel(
    int parity,
    const float* __restrict__ W2, const float* __restrict__ b2,
    const float* __restrict__ W, const float* __restrict__ b,
    const float* __restrict__ lg, const float* __restrict__ lb)
{
    __shared__ float As[32][2 * HID];
    __shared__ float s_mu[32], s_rs[32];

    const float* __restrict__ h    = parity ? g_h2 : g_h;
    float*       __restrict__ hout = parity ? g_h  : g_h2;

    int tid = threadIdx.x;
    int n0 = blockIdx.x * 32;

    // load [h | S*inv]
    for (int idx = tid; idx < 32 * 2 * HID; idx += 128) {
        int i = idx >> 8;
        int k = idx & 255;
        int n = n0 + i;
        float v = 0.0f;
        if (n < N_NODES)
            v = (k < HID) ? h[(size_t)n * HID + k]
                          : g_aggr[(size_t)n * HID + (k - HID)] * g_inv[n];
        As[i][k] = v;
    }
    __syncthreads();

    int c = tid;
    // ---- stage 1: u = (S*inv)@W2 (+ b2 where deg>0) ----
    {
        unsigned long long accP[32];
        #pragma unroll
        for (int i = 0; i < 32; i++) accP[i] = 0ull;
        for (int kp = 0; kp < 64; kp++) {
            float w0 = W2[(size_t)(2 * kp) * HID + c];
            float w1 = W2[(size_t)(2 * kp + 1) * HID + c];
            unsigned long long wP = pack2(w0, w1);
            #pragma unroll
            for (int i = 0; i < 32; i++) {
                unsigned long long aP =
                    *reinterpret_cast<const unsigned long long*>(&As[i][HID + 2 * kp]);
                fma2(accP[i], aP, wP);
            }
        }
        float u[32];
        float b2c = b2[c];
        #pragma unroll
        for (int i = 0; i < 32; i++) {
            float lo, hi;
            unpack2(accP[i], lo, hi);
            int n = n0 + i;
            float hasdeg = (n < N_NODES && g_deg[n] > 0.0f) ? 1.0f : 0.0f;
            u[i] = lo + hi + hasdeg * b2c;
        }
        __syncthreads();   // all reads of As upper done
        #pragma unroll
        for (int i = 0; i < 32; i++) As[i][HID + c] = u[i];
    }
    __syncthreads();

    // ---- stage 2: upd GEMM over [h | u], K=256 ----
    unsigned long long accP[32];
    #pragma unroll
    for (int i = 0; i < 32; i++) accP[i] = 0ull;
    for (int kp = 0; kp < HID; kp++) {
        float w0 = W[(size_t)(2 * kp) * HID + c];
        float w1 = W[(size_t)(2 * kp + 1) * HID + c];
        unsigned long long wP = pack2(w0, w1);
        #pragma unroll
        for (int i = 0; i < 32; i++) {
            unsigned long long aP =
                *reinterpret_cast<const unsigned long long*>(&As[i][2 * kp]);
            fma2(accP[i], aP, wP);
        }
    }
    float acc[32];
    #pragma unroll
    for (int i = 0; i < 32; i++) {
        float lo, hi;
        unpack2(accP[i], lo, hi);
        acc[i] = lo + hi;
    }
    __syncthreads();

    float bc = b[c];
    #pragma unroll
    for (int i = 0; i < 32; i++) {
        float r = As[i][c] + fmaxf(acc[i] + bc, 0.0f);
        As[i][HID + c] = r;
    }
    __syncthreads();

    int warp = tid >> 5, lane = tid & 31;
    for (int i = warp; i < 32; i += 4) {
        float v0 = As[i][HID + lane],      v1 = As[i][HID + 32 + lane];
        float v2 = As[i][HID + 64 + lane], v3 = As[i][HID + 96 + lane];
        float s = v0 + v1 + v2 + v3;
        float qq = v0 * v0 + v1 * v1 + v2 * v2 + v3 * v3;
        #pragma unroll
        for (int o = 16; o > 0; o >>= 1) {
            s += __shfl_xor_sync(0xffffffffu, s, o);
            qq += __shfl_xor_sync(0xffffffffu, qq, o);
        }
        if (lane == 0) {
            float mu = s * (1.0f / HID);
            float var = qq * (1.0f / HID) - mu * mu;
            s_mu[i] = mu;
            s_rs[i] = rsqrtf(var + 1e-5f);
        }
    }
    __syncthreads();

    float gc = lg[c], lbc = lb[c];
    for (int i = 0; i < 32; i++) {
        int n = n0 + i;
        if (n < N_NODES)
            hout[(size_t)n * HID + c] = (As[i][HID + c] - s_mu[i]) * s_rs[i] * gc + lbc;
    }
}

// ---- decoder ----
__global__ __launch_bounds__(128) void decoder_kernel(
    int parity,
    const float* __restrict__ W1, const float* __restrict__ b1,
    const float* __restrict__ W2, const float* __restrict__ b2,
    float* __restrict__ out)
{
    __shared__ float Hs[32][HID];
    __shared__ float s_red[32];

    const float* __restrict__ h = parity ? g_h2 : g_h;

    int tid = threadIdx.x;
    int n0 = blockIdx.x * 32;

    for (int idx = tid; idx < 32 * HID; idx += 128) {
        int i = idx >> 7, k = idx & 127;
        int n = n0 + i;
        Hs[i][k] = (n < N_NODES) ? h[(size_t)n * HID + k] : 0.0f;
    }
    __syncthreads();

    int c = tid;
    float acc[32];
    #pragma unroll
    for (int i = 0; i < 32; i++) acc[i] = 0.0f;
    for (int k = 0; k < HID; k++) {
        float w = W1[(size_t)k * HID + c];
        #pragma unroll
        for (int i = 0; i < 32; i++) acc[i] = fmaf(Hs[i][k], w, acc[i]);
    }
    __syncthreads();

    float b1c = b1[c], w2c = W2[c];
    #pragma unroll
    for (int i = 0; i < 32; i++)
        Hs[i][c] = fmaxf(acc[i] + b1c, 0.0f) * w2c;
    __syncthreads();

    int warp = tid >> 5, lane = tid & 31;
    for (int i = warp; i < 32; i += 4) {
        float s = Hs[i][lane] + Hs[i][32 + lane] + Hs[i][64 + lane] + Hs[i][96 + lane];
        #pragma unroll
        for (int o = 16; o > 0; o >>= 1) s += __shfl_xor_sync(0xffffffffu, s, o);
        if (lane == 0) s_red[i] = s;
    }
    __syncthreads();
    if (tid < 32) {
        int n = n0 + tid;
        if (n < N_NODES) out[n] = s_red[tid] + b2[0];
    }
}

extern "C" void kernel_launch(void* const* d_in, const int* in_sizes, int n_in,
                              void* d_out, int out_size)
{
    const float* x      = (const float*)d_in[0];
    const int*   ei     = (const int*)  d_in[1];
    const float* eattr  = (const float*)d_in[2];
    const float* encW1  = (const float*)d_in[3];
    const float* encb1  = (const float*)d_in[4];
    const float* encW2  = (const float*)d_in[5];
    const float* encb2  = (const float*)d_in[6];
    const float* eeW    = (const float*)d_in[7];
    const float* eeb    = (const float*)d_in[8];
    const float* msgW1  = (const float*)d_in[9];
    const float* msgb1  = (const float*)d_in[10];
    const float* msgW2  = (const float*)d_in[11];
    const float* msgb2  = (const float*)d_in[12];
    const float* updW   = (const float*)d_in[13];
    const float* updb   = (const float*)d_in[14];
    const float* lng    = (const float*)d_in[15];
    const float* lnb    = (const float*)d_in[16];
    const float* decW1  = (const float*)d_in[17];
    const float* decb1  = (const float*)d_in[18];
    const float* decW2  = (const float*)d_in[19];
    const float* decb2  = (const float*)d_in[20];
    float* out = (float*)d_out;

    const int* src = ei;
    const int* dst = ei + N_EDGES;

    cudaFuncSetAttribute(edge_kernel, cudaFuncAttributeMaxDynamicSharedMemorySize, E_SMEM);
    cudaFuncSetAttribute(node_pre_kernel, cudaFuncAttributeMaxDynamicSharedMemorySize, NP_SMEM);

    conv_w_kernel<<<N_LAYERS * 8, 128>>>(msgW1, msgW2);
    conv_e_kernel<<<N_TILES, 128>>>(eattr, eeW, eeb);

    zero_deg_kernel<<<(N_NODES + 255) / 256, 256>>>();
    deg_kernel<<<(N_EDGES + 255) / 256, 256>>>(dst);
    inv_kernel<<<(N_NODES + 255) / 256, 256>>>();
    encoder_kernel<<<(N_NODES + 31) / 32, 128>>>(x, encW1, encb1, encW2, encb2);
    conv_h_kernel<<<(N_NODES * 64 + 255) / 256, 256>>>(0);   // h in g_h

    for (int l = 0; l < N_LAYERS; l++) {
        int parity = l & 1;
        node_pre_kernel<<<N_NTILES, 256, NP_SMEM>>>(l);
        zero_aggr_kernel<<<((N_NODES * HID) + 511) / 512, 512>>>();
        edge_kernel<<<N_TILES, 256, E_SMEM>>>(l, src, dst, msgb1 + (size_t)l * HID);
        node_post_kernel<<<(N_NODES + 31) / 32, 128>>>(
            parity,
            msgW2 + (size_t)l * HID * HID, msgb2 + (size_t)l * HID,
            updW + (size_t)l * 2 * HID * HID, updb + (size_t)l * HID,
            lng + (size_t)l * HID, lnb + (size_t)l * HID);
        if (l < N_LAYERS - 1) {
            conv_h_kernel<<<(N_NODES * 64 + 255) / 256, 256>>>(parity ? 0 : 1);
        }
    }
    decoder_kernel<<<(N_NODES + 31) / 32, 128>>>(0, decW1, decb1, decW2, decb2, out);
}

// round 13
// speedup vs baseline: 3.2908x; 1.1474x over previous
#include <cuda_runtime.h>
#include <cuda_bf16.h>
#include <cstdint>

#define N_NODES 50000
#define N_EDGES 600000
#define HID 128
#define N_LAYERS 6
#define N_TILES 4688          // ceil(600000/128)
#define N_NTILES 391          // ceil(50000/128)
#define N_PAD (N_NTILES * 128)

#define SWZ(x) ((x) ^ (((x) >> 3) & 0x70))

// ---- node_pre smem layout ----
#define NPA0_HI 0
#define NPA0_LO 16384
#define NPA1_HI 32768
#define NPA1_LO 49152
#define NPB_HI  65536
#define NPB_LO  81920
#define NP_SMEM 98304

// ---- edge smem layout ----
#define EA_HI 0
#define EA_LO 16384
#define EB_HI 32768
#define EB_LO 49152
#define EOFF_DST 65536
#define EOFF_SRC 66048
#define EOFF_B1  66560
#define E_SMEM   67072

// ---- node_post smem layout (A0/A1 chunk images; fp32 R aliases A0+A1) ----
#define PBA0 0
#define PBA1 32768
#define PBB  65536
#define PBR  0
#define PB_SMEM 98304

// ---- scratch (no allocations allowed) ----
__device__ float g_h   [(size_t)N_NODES * HID];
__device__ float g_h2  [(size_t)N_NODES * HID];
__device__ float g_aggr[(size_t)N_NODES * HID];   // S = sum of relu(z)
__device__ float g_Pa  [(size_t)N_PAD * HID];
__device__ float g_Pb  [(size_t)N_PAD * HID];
__device__ float g_deg [N_NODES];
__device__ float g_inv [N_NODES];
// bf16 hi/lo images of current h: [n][128 cols] bf16 = 256B per node
__device__ unsigned char g_hbf_hi[(size_t)N_NODES * 256];
__device__ unsigned char g_hbf_lo[(size_t)N_NODES * 256];
// weight images: [layer][chunk 0..11][hi/lo][16KB]; [n][k] bf16x2 at SWZ(n*128+k*2)
// 0,1=W1a 2,3=W1b 4,5=W1c 6,7=W2 8,9=updW(h part) 10,11=updW(u part)
__device__ unsigned char g_wimg[(size_t)N_LAYERS * 12 * 2 * 16384];
// edge-embedding images: [tile][half][hi/lo][16KB]; [r][k] bf16x2 at SWZ(r*128+k*2)
__device__ unsigned char g_eimg[(size_t)N_TILES * 2 * 2 * 16384];

// ================= helpers =================
__device__ __forceinline__ uint32_t smem_u32(const void* p) {
    uint32_t a;
    asm("{ .reg .u64 t; cvta.to.shared.u64 t, %1; cvt.u32.u64 %0, t; }" : "=r"(a) : "l"(p));
    return a;
}
__device__ __forceinline__ uint32_t bf16x2_of(float lo, float hi) {
    uint32_t r;
    asm("cvt.rn.bf16x2.f32 %0, %1, %2;" : "=r"(r) : "f"(hi), "f"(lo));
    return r;
}
__device__ __forceinline__ float lo_f(uint32_t p) { return __uint_as_float(p << 16); }
__device__ __forceinline__ float hi_f(uint32_t p) { return __uint_as_float(p & 0xffff0000u); }

__device__ __forceinline__ void ldsm_x4(uint32_t* r, uint32_t addr) {
    asm volatile("ldmatrix.sync.aligned.m8n8.x4.shared.b16 {%0,%1,%2,%3}, [%4];"
        : "=r"(r[0]), "=r"(r[1]), "=r"(r[2]), "=r"(r[3]) : "r"(addr));
}
__device__ __forceinline__ void mma_bf16(float* d, const uint32_t* a, const uint32_t* b) {
    asm volatile(
        "mma.sync.aligned.m16n8k16.row.col.f32.bf16.bf16.f32 "
        "{%0,%1,%2,%3}, {%4,%5,%6,%7}, {%8,%9}, {%0,%1,%2,%3};"
        : "+f"(d[0]), "+f"(d[1]), "+f"(d[2]), "+f"(d[3])
        : "r"(a[0]), "r"(a[1]), "r"(a[2]), "r"(a[3]), "r"(b[0]), "r"(b[1]));
}
__device__ __forceinline__ void red_v2(float* p, float v0, float v1) {
    asm volatile("red.global.add.v2.f32 [%0], {%1, %2};"
                 :: "l"(p), "f"(v0), "f"(v1) : "memory");
}

// ================= small kernels =================
__global__ void zero_aggr_kernel() {
    size_t i = (size_t)blockIdx.x * blockDim.x + threadIdx.x;
    if (i < (size_t)N_NODES * HID) g_aggr[i] = 0.0f;
}
__global__ void zero_deg_kernel() {
    int i = blockIdx.x * blockDim.x + threadIdx.x;
    if (i < N_NODES) g_deg[i] = 0.0f;
}
__global__ void deg_kernel(const int* __restrict__ dst) {
    int e = blockIdx.x * blockDim.x + threadIdx.x;
    if (e < N_EDGES) atomicAdd(&g_deg[dst[e]], 1.0f);
}
__global__ void inv_kernel() {
    int i = blockIdx.x * blockDim.x + threadIdx.x;
    if (i < N_NODES) {
        float d = g_deg[i];
        g_inv[i] = (d > 0.0f) ? (1.0f / d) : 0.0f;
    }
}

// ---- convert h (fp32, buf 0/1) -> bf16 hi/lo node images ----
__global__ __launch_bounds__(256) void conv_h_kernel(int buf) {
    size_t i = (size_t)blockIdx.x * blockDim.x + threadIdx.x;   // pair index
    if (i >= (size_t)N_NODES * 64) return;
    const float2 v = *((const float2*)(buf ? g_h2 : g_h) + i);
    uint32_t hi = bf16x2_of(v.x, v.y);
    uint32_t lo = bf16x2_of(v.x - lo_f(hi), v.y - hi_f(hi));
    ((uint32_t*)g_hbf_hi)[i] = hi;
    ((uint32_t*)g_hbf_lo)[i] = lo;
}

// ---- precompute: weight chunk images ([n][k] bf16 hi/lo, swizzled) ----
__global__ __launch_bounds__(128) void conv_w_kernel(
    const float* __restrict__ msgW1, const float* __restrict__ msgW2,
    const float* __restrict__ updW)
{
    int l = blockIdx.x / 12, ch = blockIdx.x % 12, tid = threadIdx.x;
    const float* W;
    if (ch < 6)      W = msgW1 + (size_t)l * 384 * 128 + (size_t)(64 * ch) * 128;
    else if (ch < 8) W = msgW2 + (size_t)l * 128 * 128 + (size_t)(64 * (ch - 6)) * 128;
    else             W = updW  + (size_t)l * 256 * 128 + (size_t)(64 * (ch - 8)) * 128;
    unsigned char* hiImg = g_wimg + ((size_t)(l * 12 + ch) * 2) * 16384;
    unsigned char* loImg = hiImg + 16384;
    for (int i = tid; i < 4096; i += 128) {
        int n = i & 127, kp = i >> 7;
        int k = kp * 2;
        float v0 = W[(size_t)k * 128 + n];
        float v1 = W[(size_t)(k + 1) * 128 + n];
        uint32_t hi = bf16x2_of(v0, v1);
        uint32_t lo = bf16x2_of(v0 - lo_f(hi), v1 - hi_f(hi));
        uint32_t byte = SWZ((uint32_t)(n * 128 + k * 2));
        *(uint32_t*)(hiImg + byte) = hi;
        *(uint32_t*)(loImg + byte) = lo;
    }
}

// ---- precompute: edge embedding images erow = relu(ea@eeW+eeb) ----
__global__ __launch_bounds__(128) void conv_e_kernel(
    const float* __restrict__ eattr, const float* __restrict__ eeW, const float* __restrict__ eeb)
{
    __shared__ float s_w[4 * HID];
    __shared__ float s_b[HID];
    int tid = threadIdx.x, t = blockIdx.x;
    for (int i = tid; i < 4 * HID; i += 128) s_w[i] = eeW[i];
    s_b[tid] = eeb[tid];
    __syncthreads();
    int e = t * 128 + tid;
    float a0 = 0, a1 = 0, a2 = 0, a3 = 0;
    if (e < N_EDGES) {
        const float4 ea = *(const float4*)(eattr + (size_t)e * 4);
        a0 = ea.x; a1 = ea.y; a2 = ea.z; a3 = ea.w;
    }
    unsigned char* base = g_eimg + (size_t)t * 4 * 16384;
    for (int kp = 0; kp < 64; kp++) {
        int k = kp * 2;
        float v0 = fmaxf(s_b[k]     + a0 * s_w[k]       + a1 * s_w[128 + k]
                                    + a2 * s_w[256 + k] + a3 * s_w[384 + k], 0.0f);
        float v1 = fmaxf(s_b[k + 1] + a0 * s_w[k + 1]       + a1 * s_w[128 + k + 1]
                                    + a2 * s_w[256 + k + 1] + a3 * s_w[384 + k + 1], 0.0f);
        uint32_t hi = bf16x2_of(v0, v1);
        uint32_t lo = bf16x2_of(v0 - lo_f(hi), v1 - hi_f(hi));
        int hh = k >> 6;
        uint32_t byte = SWZ((uint32_t)(tid * 128 + (k & 63) * 2));
        *(uint32_t*)(base + (size_t)(hh * 2) * 16384 + byte)     = hi;
        *(uint32_t*)(base + (size_t)(hh * 2 + 1) * 16384 + byte) = lo;
    }
}

// ---- encoder ----
__global__ __launch_bounds__(128) void encoder_kernel(
    const float* __restrict__ x,
    const float* __restrict__ W1, const float* __restrict__ b1,
    const float* __restrict__ W2, const float* __restrict__ b2)
{
    __shared__ float Hs[32][HID];
    __shared__ float xs[32][3];
    int tid = threadIdx.x;
    int n0 = blockIdx.x * 32;

    for (int idx = tid; idx < 32 * 3; idx += 128) {
        int i = idx / 3, j = idx % 3;
        int n = n0 + i;
        xs[i][j] = (n < N_NODES) ? x[(size_t)n * 3 + j] : 0.0f;
    }
    __syncthreads();

    int c = tid;
    float w0 = W1[c], w1 = W1[HID + c], w2 = W1[2 * HID + c], bc = b1[c];
    #pragma unroll 4
    for (int i = 0; i < 32; i++) {
        float v = bc + xs[i][0] * w0 + xs[i][1] * w1 + xs[i][2] * w2;
        Hs[i][c] = fmaxf(v, 0.0f);
    }
    __syncthreads();

    float acc[32];
    #pragma unroll
    for (int i = 0; i < 32; i++) acc[i] = 0.0f;
    for (int k = 0; k < HID; k++) {
        float w = W2[(size_t)k * HID + c];
        #pragma unroll
        for (int i = 0; i < 32; i++) acc[i] = fmaf(Hs[i][k], w, acc[i]);
    }
    float b2c = b2[c];
    for (int i = 0; i < 32; i++) {
        int n = n0 + i;
        if (n < N_NODES) g_h[(size_t)n * HID + c] = acc[i] + b2c;
    }
}

// ================ shared MMA chunk routine ================
__device__ __forceinline__ void run_chunk_mma(
    uint32_t aHi, uint32_t aLo, uint32_t bHi, uint32_t bLo,
    const int rbyte[4], const int xa[4], const int nbyte[2], const int xb[2],
    float acc[4][4][4])
{
    #pragma unroll
    for (int ks = 0; ks < 4; ks++) {
        int kb = ks * 32;
        uint32_t aH[4][4], aL[4][4], bH[2][4], bL[2][4];
        #pragma unroll
        for (int rt = 0; rt < 4; rt++) {
            uint32_t off = (uint32_t)((rbyte[rt] + kb) ^ xa[rt]);
            ldsm_x4(aH[rt], aHi + off);
            ldsm_x4(aL[rt], aLo + off);
        }
        #pragma unroll
        for (int cp = 0; cp < 2; cp++) {
            uint32_t off = (uint32_t)((nbyte[cp] + kb) ^ xb[cp]);
            ldsm_x4(bH[cp], bHi + off);
            ldsm_x4(bL[cp], bLo + off);
        }
        #pragma unroll
        for (int rt = 0; rt < 4; rt++)
            #pragma unroll
            for (int ct = 0; ct < 4; ct++) {
                const uint32_t* bh = &bH[ct >> 1][(ct & 1) * 2];
                const uint32_t* bl = &bL[ct >> 1][(ct & 1) * 2];
                mma_bf16(acc[rt][ct], aH[rt], bh);
                mma_bf16(acc[rt][ct], aH[rt], bl);
                mma_bf16(acc[rt][ct], aL[rt], bh);
            }
    }
}

__device__ __forceinline__ void ldsm_addrs(int lane, int wrow, int wcol,
                                           int rbyte[4], int xa[4], int nbyte[2], int xb[2])
{
    int q = lane >> 3, i8 = lane & 7;
    #pragma unroll
    for (int rt = 0; rt < 4; rt++) {
        int r = wrow + 16 * rt + i8 + 8 * (q & 1);
        rbyte[rt] = r * 128 + 16 * (q >> 1);
        xa[rt] = (r & 7) << 4;
    }
    #pragma unroll
    for (int cp = 0; cp < 2; cp++) {
        int n = wcol + 16 * cp + i8 + 8 * (q >> 1);
        nbyte[cp] = n * 128 + 16 * (q & 1);
        xb[cp] = (n & 7) << 4;
    }
}

// copy one 16KB weight-image chunk pair (hi/lo) into smem B buffer
__device__ __forceinline__ void copy_w_chunk(char* dsm, int tid,
                                             const unsigned char* wimg, int chunk, int dstoff)
{
    const float4* whi = (const float4*)(wimg + (size_t)(chunk * 2) * 16384);
    const float4* wlo = whi + 1024;
    float4* dhi = (float4*)(dsm + dstoff);
    float4* dlo = (float4*)(dsm + dstoff + 16384);
    #pragma unroll
    for (int i = 0; i < 4; i++) {
        dhi[tid + 256 * i] = whi[tid + 256 * i];
        dlo[tid + 256 * i] = wlo[tid + 256 * i];
    }
}

// stage one 64-col h chunk (hh=0/1) from g_hbf images into smem A buffer
__device__ __forceinline__ void stage_h_chunk(char* dsm, int tid, int n0, int hh, int abase)
{
    int r = tid >> 1, half = tid & 1;
    int node = n0 + r; if (node >= N_NODES) node = N_NODES - 1;
    int rx = r & 7;
    int sgbase = 8 * hh + half * 4;
    const uint4* pHi = (const uint4*)(g_hbf_hi + (size_t)node * 256) + sgbase;
    const uint4* pLo = (const uint4*)(g_hbf_lo + (size_t)node * 256) + sgbase;
    #pragma unroll
    for (int j = 0; j < 4; j++) {
        int dg = (half * 4 + j) ^ rx;
        *(uint4*)(dsm + abase + r * 128 + dg * 16) = pHi[j];
        *(uint4*)(dsm + abase + 16384 + r * 128 + dg * 16) = pLo[j];
    }
}

// ================ node_pre: P_a = h@W1a, P_b = h@W1b ================
__global__ void __launch_bounds__(256) node_pre_kernel(int layer)
{
    extern __shared__ char dsm[];
    uint32_t sb = smem_u32(dsm);
    int tid = threadIdx.x, wid = tid >> 5, lane = tid & 31;
    int wrow = 64 * (wid >> 2), wcol = 32 * (wid & 3);
    int n0 = blockIdx.x * 128;
    const unsigned char* wimg = g_wimg + (size_t)layer * 12 * 2 * 16384;

    stage_h_chunk(dsm, tid, n0, 0, NPA0_HI);
    stage_h_chunk(dsm, tid, n0, 1, NPA1_HI);

    int rbyte[4], xa[4], nbyte[2], xb[2];
    ldsm_addrs(lane, wrow, wcol, rbyte, xa, nbyte, xb);

    float acc[4][4][4];
    #pragma unroll
    for (int a = 0; a < 4; a++)
        #pragma unroll
        for (int b = 0; b < 4; b++)
            #pragma unroll
            for (int c = 0; c < 4; c++) acc[a][b][c] = 0.0f;

    for (int chunk = 0; chunk < 4; chunk++) {
        __syncthreads();
        copy_w_chunk(dsm, tid, wimg, chunk, NPB_HI);
        __syncthreads();
        uint32_t aBase = sb + ((chunk & 1) ? NPA1_HI : NPA0_HI);
        run_chunk_mma(aBase, aBase + 16384, sb + NPB_HI, sb + NPB_LO,
                      rbyte, xa, nbyte, xb, acc);
        if (chunk & 1) {
            float* P = (chunk < 2) ? g_Pa : g_Pb;
            #pragma unroll
            for (int rt = 0; rt < 4; rt++) {
                int m1 = wrow + 16 * rt + (lane >> 2);
                int m2 = m1 + 8;
                #pragma unroll
                for (int ct = 0; ct < 4; ct++) {
                    int col = wcol + 8 * ct + 2 * (lane & 3);
                    if (n0 + m1 < N_NODES) {
                        float2 v = {acc[rt][ct][0], acc[rt][ct][1]};
                        *(float2*)(P + (size_t)(n0 + m1) * HID + col) = v;
                    }
                    if (n0 + m2 < N_NODES) {
                        float2 v = {acc[rt][ct][2], acc[rt][ct][3]};
                        *(float2*)(P + (size_t)(n0 + m2) * HID + col) = v;
                    }
                }
            }
            #pragma unroll
            for (int a = 0; a < 4; a++)
                #pragma unroll
                for (int b = 0; b < 4; b++)
                    #pragma unroll
                    for (int c = 0; c < 4; c++) acc[a][b][c] = 0.0f;
        }
    }
}

// ================ edge kernel: Pe MMA + gather-add + relu + scatter S ================
__global__ void __launch_bounds__(256) edge_kernel(
    int layer,
    const int* __restrict__ src, const int* __restrict__ dst,
    const float* __restrict__ b1)
{
    extern __shared__ char dsm[];
    uint32_t sb = smem_u32(dsm);
    int tid = threadIdx.x, wid = tid >> 5, lane = tid & 31;
    int wrow = 64 * (wid >> 2), wcol = 32 * (wid & 3);
    int t = blockIdx.x, e0 = t * 128;

    if (tid < 128) {
        int e = e0 + tid;
        ((int*)(dsm + EOFF_DST))[tid] = (e < N_EDGES) ? dst[e] : 0;
        ((int*)(dsm + EOFF_SRC))[tid] = (e < N_EDGES) ? src[e] : 0;
        ((float*)(dsm + EOFF_B1))[tid] = b1[tid];
    }
    const int* sd = (const int*)(dsm + EOFF_DST);
    const int* ssrc = (const int*)(dsm + EOFF_SRC);
    const float* sb1 = (const float*)(dsm + EOFF_B1);
    const unsigned char* wimg = g_wimg + (size_t)layer * 12 * 2 * 16384;

    int rbyte[4], xa[4], nbyte[2], xb[2];
    ldsm_addrs(lane, wrow, wcol, rbyte, xa, nbyte, xb);

    float acc[4][4][4];
    #pragma unroll
    for (int a = 0; a < 4; a++)
        #pragma unroll
        for (int b = 0; b < 4; b++)
            #pragma unroll
            for (int c = 0; c < 4; c++) acc[a][b][c] = 0.0f;

    // Pe = e-image @ W1c  (chunks 4,5)
    for (int c = 0; c < 2; c++) {
        if (c) __syncthreads();
        {
            const float4* ehi = (const float4*)(g_eimg + ((size_t)(t * 2 + c) * 2) * 16384);
            const float4* elo = ehi + 1024;
            float4* dahi = (float4*)(dsm + EA_HI);
            float4* dalo = (float4*)(dsm + EA_LO);
            #pragma unroll
            for (int i = 0; i < 4; i++) {
                dahi[tid + 256 * i] = ehi[tid + 256 * i];
                dalo[tid + 256 * i] = elo[tid + 256 * i];
            }
            copy_w_chunk(dsm, tid, wimg, 4 + c, EB_HI);
        }
        __syncthreads();
        run_chunk_mma(sb + EA_HI, sb + EA_LO, sb + EB_HI, sb + EB_LO,
                      rbyte, xa, nbyte, xb, acc);
    }

    // epilogue: z = Pe + b1 + Pa[dst] + Pb[src]; relu; scatter-add into S
    #pragma unroll
    for (int rt = 0; rt < 4; rt++) {
        int m1 = wrow + 16 * rt + (lane >> 2);
        int m2 = m1 + 8;
        bool v1ok = (e0 + m1) < N_EDGES;
        bool v2ok = (e0 + m2) < N_EDGES;
        int d1 = sd[m1], s1 = ssrc[m1];
        int d2 = sd[m2], s2 = ssrc[m2];
        const float* pa1 = g_Pa + (size_t)d1 * HID;
        const float* pb1 = g_Pb + (size_t)s1 * HID;
        const float* pa2 = g_Pa + (size_t)d2 * HID;
        const float* pb2 = g_Pb + (size_t)s2 * HID;
        float* ag1 = g_aggr + (size_t)d1 * HID;
        float* ag2 = g_aggr + (size_t)d2 * HID;
        #pragma unroll
        for (int ct = 0; ct < 4; ct++) {
            int col = wcol + 8 * ct + 2 * (lane & 3);
            float bv0 = sb1[col], bv1 = sb1[col + 1];
            if (v1ok) {
                float2 a = *(const float2*)(pa1 + col);
                float2 b = *(const float2*)(pb1 + col);
                float z0 = fmaxf(acc[rt][ct][0] + bv0 + a.x + b.x, 0.0f);
                float z1 = fmaxf(acc[rt][ct][1] + bv1 + a.y + b.y, 0.0f);
                red_v2(ag1 + col, z0, z1);
            }
            if (v2ok) {
                float2 a = *(const float2*)(pa2 + col);
                float2 b = *(const float2*)(pb2 + col);
                float z0 = fmaxf(acc[rt][ct][2] + bv0 + a.x + b.x, 0.0f);
                float z1 = fmaxf(acc[rt][ct][3] + bv1 + a.y + b.y, 0.0f);
                red_v2(ag2 + col, z0, z1);
            }
        }
    }
}

// ================ node_post (HMMA): u=(S*inv)@W2+b2[deg>0]; upd=[h|u]@updW;
//                 r=h+relu(upd+b); LN -> hout + next-layer bf16 images ================
__global__ void __launch_bounds__(256) node_post_kernel(
    int parity, int layer,
    const float* __restrict__ b2, const float* __restrict__ ub,
    const float* __restrict__ lg, const float* __restrict__ lb)
{
    extern __shared__ char dsm[];
    __shared__ float s_b2[128], s_ub[128], s_g[128], s_lb[128], s_mask[128];
    uint32_t sb = smem_u32(dsm);
    int tid = threadIdx.x, wid = tid >> 5, lane = tid & 31;
    int wrow = 64 * (wid >> 2), wcol = 32 * (wid & 3);
    int n0 = blockIdx.x * 128;
    const float* __restrict__ h    = parity ? g_h2 : g_h;
    float*       __restrict__ hout = parity ? g_h  : g_h2;
    const unsigned char* wimg = g_wimg + (size_t)layer * 12 * 2 * 16384;

    if (tid < 128) {
        s_b2[tid] = b2[tid]; s_ub[tid] = ub[tid];
        s_g[tid] = lg[tid];  s_lb[tid] = lb[tid];
        int n = n0 + tid;
        s_mask[tid] = (n < N_NODES && g_deg[n] > 0.0f) ? 1.0f : 0.0f;
    }

    // stage A = S*inv as bf16 hi/lo images: chunk0 (cols 0-63)->A0, chunk1->A1
    {
        int r = tid >> 1, half = tid & 1;
        int node = n0 + r; float iv = 0.0f;
        if (node < N_NODES) iv = g_inv[node]; else node = N_NODES - 1;
        const float2* Srow = (const float2*)(g_aggr + (size_t)node * HID) + half * 32;
        int ab = half ? PBA1 : PBA0;
        int rx = r & 7;
        #pragma unroll
        for (int gi = 0; gi < 8; gi++) {
            uint32_t hv[4], lv[4];
            #pragma unroll
            for (int j = 0; j < 4; j++) {
                float2 v = Srow[gi * 4 + j];
                v.x *= iv; v.y *= iv;
                uint32_t hi = bf16x2_of(v.x, v.y);
                uint32_t lo = bf16x2_of(v.x - lo_f(hi), v.y - hi_f(hi));
                hv[j] = hi; lv[j] = lo;
            }
            int dg = gi ^ rx;
            *(uint4*)(dsm + ab + r * 128 + dg * 16) = make_uint4(hv[0], hv[1], hv[2], hv[3]);
            *(uint4*)(dsm + ab + 16384 + r * 128 + dg * 16) = make_uint4(lv[0], lv[1], lv[2], lv[3]);
        }
    }

    int rbyte[4], xa[4], nbyte[2], xb[2];
    ldsm_addrs(lane, wrow, wcol, rbyte, xa, nbyte, xb);

    float acc[4][4][4];
    #pragma unroll
    for (int a = 0; a < 4; a++)
        #pragma unroll
        for (int b = 0; b < 4; b++)
            #pragma unroll
            for (int c = 0; c < 4; c++) acc[a][b][c] = 0.0f;

    // ---- stage 1: u = S' @ W2 (W chunks 6,7) ----
    for (int c = 0; c < 2; c++) {
        __syncthreads();
        copy_w_chunk(dsm, tid, wimg, 6 + c, PBB);
        __syncthreads();
        uint32_t aBase = sb + (c ? PBA1 : PBA0);
        run_chunk_mma(aBase, aBase + 16384, sb + PBB, sb + PBB + 16384,
                      rbyte, xa, nbyte, xb, acc);
    }
    __syncthreads();   // mma reads of A0/A1 done

    // u fragments (+ masked b2) -> bf16 images: cols 0-63 -> A0, 64-127 -> A1
    #pragma unroll
    for (int rt = 0; rt < 4; rt++) {
        int m1 = wrow + 16 * rt + (lane >> 2);
        int m2 = m1 + 8;
        float mk1 = s_mask[m1], mk2 = s_mask[m2];
        #pragma unroll
        for (int ct = 0; ct < 4; ct++) {
            int col = wcol + 8 * ct + 2 * (lane & 3);
            int ab = (col >= 64) ? PBA1 : PBA0;
            int k2 = (col & 63) * 2;
            float bb0 = s_b2[col], bb1 = s_b2[col + 1];
            {
                float v0 = acc[rt][ct][0] + mk1 * bb0;
                float v1 = acc[rt][ct][1] + mk1 * bb1;
                uint32_t hi = bf16x2_of(v0, v1);
                uint32_t lo = bf16x2_of(v0 - lo_f(hi), v1 - hi_f(hi));
                uint32_t byte = SWZ((uint32_t)(m1 * 128 + k2));
                *(uint32_t*)(dsm + ab + byte) = hi;
                *(uint32_t*)(dsm + ab + 16384 + byte) = lo;
            }
            {
                float v0 = acc[rt][ct][2] + mk2 * bb0;
                float v1 = acc[rt][ct][3] + mk2 * bb1;
                uint32_t hi = bf16x2_of(v0, v1);
                uint32_t lo = bf16x2_of(v0 - lo_f(hi), v1 - hi_f(hi));
                uint32_t byte = SWZ((uint32_t)(m2 * 128 + k2));
                *(uint32_t*)(dsm + ab + byte) = hi;
                *(uint32_t*)(dsm + ab + 16384 + byte) = lo;
            }
        }
    }
    #pragma unroll
    for (int a = 0; a < 4; a++)
        #pragma unroll
        for (int b = 0; b < 4; b++)
            #pragma unroll
            for (int c = 0; c < 4; c++) acc[a][b][c] = 0.0f;

    // ---- stage 2: upd = [h|u] @ updW. order: u0(A0,ch10) u1(A1,ch11) h0(A0,ch8) h1(A1,ch9)
    for (int s = 0; s < 4; s++) {
        __syncthreads();
        if (s >= 2) stage_h_chunk(dsm, tid, n0, s - 2, (s & 1) ? PBA1 : PBA0);
        copy_w_chunk(dsm, tid, wimg, (s < 2) ? (10 + s) : (8 + (s - 2)), PBB);
        __syncthreads();
        uint32_t aBase = sb + ((s & 1) ? PBA1 : PBA0);
        run_chunk_mma(aBase, aBase + 16384, sb + PBB, sb + PBB + 16384,
                      rbyte, xa, nbyte, xb, acc);
    }
    __syncthreads();   // all mma reads done; A region reusable as fp32 R

    // r = h + relu(upd + ub) -> RBUF fp32 [128][128]
    #pragma unroll
    for (int rt = 0; rt < 4; rt++) {
        int m1 = wrow + 16 * rt + (lane >> 2);
        int m2 = m1 + 8;
        int nd1 = n0 + m1; if (nd1 >= N_NODES) nd1 = N_NODES - 1;
        int nd2 = n0 + m2; if (nd2 >= N_NODES) nd2 = N_NODES - 1;
        #pragma unroll
        for (int ct = 0; ct < 4; ct++) {
            int col = wcol + 8 * ct + 2 * (lane & 3);
            float u0 = s_ub[col], u1 = s_ub[col + 1];
            {
                float2 hv = *(const float2*)(h + (size_t)nd1 * HID + col);
                float r0 = hv.x + fmaxf(acc[rt][ct][0] + u0, 0.0f);
                float r1 = hv.y + fmaxf(acc[rt][ct][1] + u1, 0.0f);
                float2 v = {r0, r1};
                *(float2*)(dsm + PBR + m1 * 512 + col * 4) = v;
            }
            {
                float2 hv = *(const float2*)(h + (size_t)nd2 * HID + col);
                float r0 = hv.x + fmaxf(acc[rt][ct][2] + u0, 0.0f);
                float r1 = hv.y + fmaxf(acc[rt][ct][3] + u1, 0.0f);
                float2 v = {r0, r1};
                *(float2*)(dsm + PBR + m2 * 512 + col * 4) = v;
            }
        }
    }
    __syncthreads();

    // LN: 2 threads per row, each owns 64 cols
    {
        int row = tid >> 1, half = tid & 1;
        const float4* r4 = (const float4*)(dsm + PBR + row * 512 + half * 256);
        float s = 0.0f, q = 0.0f;
        #pragma unroll
        for (int j = 0; j < 16; j++) {
            float4 v = r4[j];
            s += v.x + v.y + v.z + v.w;
            q += v.x * v.x + v.y * v.y + v.z * v.z + v.w * v.w;
        }
        s += __shfl_xor_sync(0xffffffffu, s, 1);
        q += __shfl_xor_sync(0xffffffffu, q, 1);
        float mu = s * (1.0f / HID);
        float var = q * (1.0f / HID) - mu * mu;
        float rs = rsqrtf(var + 1e-5f);

        int node = n0 + row;
        if (node < N_NODES) {
            float4* ho = (float4*)(hout + (size_t)node * HID + half * 64);
            uint4* bh = (uint4*)(g_hbf_hi + (size_t)node * 256) + half * 8;
            uint4* bl = (uint4*)(g_hbf_lo + (size_t)node * 256) + half * 8;
            #pragma unroll
            for (int g2 = 0; g2 < 8; g2++) {
                float ov[8];
                #pragma unroll
                for (int e = 0; e < 2; e++) {
                    float4 v = r4[g2 * 2 + e];
                    int cb = half * 64 + g2 * 8 + e * 4;
                    ov[e * 4 + 0] = (v.x - mu) * rs * s_g[cb + 0] + s_lb[cb + 0];
                    ov[e * 4 + 1] = (v.y - mu) * rs * s_g[cb + 1] + s_lb[cb + 1];
                    ov[e * 4 + 2] = (v.z - mu) * rs * s_g[cb + 2] + s_lb[cb + 2];
                    ov[e * 4 + 3] = (v.w - mu) * rs * s_g[cb + 3] + s_lb[cb + 3];
                }
                float4 o0 = {ov[0], ov[1], ov[2], ov[3]};
                float4 o1 = {ov[4], ov[5], ov[6], ov[7]};
                ho[g2 * 2] = o0; ho[g2 * 2 + 1] = o1;
                uint32_t hv[4], lv[4];
                #pragma unroll
                for (int p = 0; p < 4; p++) {
                    float v0 = ov[2 * p], v1 = ov[2 * p + 1];
                    uint32_t hi = bf16x2_of(v0, v1);
                    uint32_t lo = bf16x2_of(v0 - lo_f(hi), v1 - hi_f(hi));
                    hv[p] = hi; lv[p] = lo;
                }
                bh[g2] = make_uint4(hv[0], hv[1], hv[2], hv[3]);
                bl[g2] = make_uint4(lv[0], lv[1], lv[2], lv[3]);
            }
        }
    }
}

// ---- decoder ----
__global__ __launch_bounds__(128) void decoder_kernel(
    int parity,
    const float* __restrict__ W1, const float* __restrict__ b1,
    const float* __restrict__ W2, const float* __restrict__ b2,
    float* __restrict__ out)
{
    __shared__ float Hs[32][HID];
    __shared__ float s_red[32];

    const float* __restrict__ h = parity ? g_h2 : g_h;

    int tid = threadIdx.x;
    int n0 = blockIdx.x * 32;

    for (int idx = tid; idx < 32 * HID; idx += 128) {
        int i = idx >> 7, k = idx & 127;
        int n = n0 + i;
        Hs[i][k] = (n < N_NODES) ? h[(size_t)n * HID + k] : 0.0f;
    }
    __syncthreads();

    int c = tid;
    float acc[32];
    #pragma unroll
    for (int i = 0; i < 32; i++) acc[i] = 0.0f;
    for (int k = 0; k < HID; k++) {
        float w = W1[(size_t)k * HID + c];
        #pragma unroll
        for (int i = 0; i < 32; i++) acc[i] = fmaf(Hs[i][k], w, acc[i]);
    }
    __syncthreads();

    float b1c = b1[c], w2c = W2[c];
    #pragma unroll
    for (int i = 0; i < 32; i++)
        Hs[i][c] = fmaxf(acc[i] + b1c, 0.0f) * w2c;
    __syncthreads();

    int warp = tid >> 5, lane = tid & 31;
    for (int i = warp; i < 32; i += 4) {
        float s = Hs[i][lane] + Hs[i][32 + lane] + Hs[i][64 + lane] + Hs[i][96 + lane];
        #pragma unroll
        for (int o = 16; o > 0; o >>= 1) s += __shfl_xor_sync(0xffffffffu, s, o);
        if (lane == 0) s_red[i] = s;
    }
    __syncthreads();
    if (tid < 32) {
        int n = n0 + tid;
        if (n < N_NODES) out[n] = s_red[tid] + b2[0];
    }
}

extern "C" void kernel_launch(void* const* d_in, const int* in_sizes, int n_in,
                              void* d_out, int out_size)
{
    const float* x      = (const float*)d_in[0];
    const int*   ei     = (const int*)  d_in[1];
    const float* eattr  = (const float*)d_in[2];
    const float* encW1  = (const float*)d_in[3];
    const float* encb1  = (const float*)d_in[4];
    const float* encW2  = (const float*)d_in[5];
    const float* encb2  = (const float*)d_in[6];
    const float* eeW    = (const float*)d_in[7];
    const float* eeb    = (const float*)d_in[8];
    const float* msgW1  = (const float*)d_in[9];
    const float* msgb1  = (const float*)d_in[10];
    const float* msgW2  = (const float*)d_in[11];
    const float* msgb2  = (const float*)d_in[12];
    const float* updW   = (const float*)d_in[13];
    const float* updb   = (const float*)d_in[14];
    const float* lng    = (const float*)d_in[15];
    const float* lnb    = (const float*)d_in[16];
    const float* decW1  = (const float*)d_in[17];
    const float* decb1  = (const float*)d_in[18];
    const float* decW2  = (const float*)d_in[19];
    const float* decb2  = (const float*)d_in[20];
    float* out = (float*)d_out;

    const int* src = ei;
    const int* dst = ei + N_EDGES;

    cudaFuncSetAttribute(edge_kernel, cudaFuncAttributeMaxDynamicSharedMemorySize, E_SMEM);
    cudaFuncSetAttribute(node_pre_kernel, cudaFuncAttributeMaxDynamicSharedMemorySize, NP_SMEM);
    cudaFuncSetAttribute(node_post_kernel, cudaFuncAttributeMaxDynamicSharedMemorySize, PB_SMEM);

    conv_w_kernel<<<N_LAYERS * 12, 128>>>(msgW1, msgW2, updW);
    conv_e_kernel<<<N_TILES, 128>>>(eattr, eeW, eeb);

    zero_deg_kernel<<<(N_NODES + 255) / 256, 256>>>();
    deg_kernel<<<(N_EDGES + 255) / 256, 256>>>(dst);
    inv_kernel<<<(N_NODES + 255) / 256, 256>>>();
    encoder_kernel<<<(N_NODES + 31) / 32, 128>>>(x, encW1, encb1, encW2, encb2);
    conv_h_kernel<<<(N_NODES * 64 + 255) / 256, 256>>>(0);   // h in g_h

    for (int l = 0; l < N_LAYERS; l++) {
        int parity = l & 1;
        node_pre_kernel<<<N_NTILES, 256, NP_SMEM>>>(l);
        zero_aggr_kernel<<<((N_NODES * HID) + 511) / 512, 512>>>();
        edge_kernel<<<N_TILES, 256, E_SMEM>>>(l, src, dst, msgb1 + (size_t)l * HID);
        node_post_kernel<<<N_NTILES, 256, PB_SMEM>>>(
            parity, l,
            msgb2 + (size_t)l * HID, updb + (size_t)l * HID,
            lng + (size_t)l * HID, lnb + (size_t)l * HID);
    }
    decoder_kernel<<<(N_NODES + 31) / 32, 128>>>(0, decW1, decb1, decW2, decb2, out);
}

// round 14
// speedup vs baseline: 3.2953x; 1.0014x over previous
#include <cuda_runtime.h>
#include <cuda_bf16.h>
#include <cstdint>

#define N_NODES 50000
#define N_EDGES 600000
#define HID 128
#define N_LAYERS 6
#define N_TILES 4688          // ceil(600000/128)
#define N_NTILES 391          // ceil(50000/128)
#define N_PAD (N_NTILES * 128)

#define SWZ(x) ((x) ^ (((x) >> 3) & 0x70))

// ---- node_pre smem layout ----
#define NPA0_HI 0
#define NPA0_LO 16384
#define NPA1_HI 32768
#define NPA1_LO 49152
#define NPB_HI  65536
#define NPB_LO  81920
#define NP_SMEM 98304

// ---- edge smem layout ----
#define EA_HI 0
#define EA_LO 16384
#define EB_HI 32768
#define EB_LO 49152
#define EOFF_DST 65536
#define EOFF_SRC 66048
#define EOFF_B1  66560
#define E_SMEM   67072

// ---- node_post smem layout (A0/A1 chunk images; fp32 R aliases A0+A1) ----
#define PBA0 0
#define PBA1 32768
#define PBB  65536
#define PBR  0
#define PB_SMEM 98304

// ---- scratch (no allocations allowed) ----
__device__ float g_h   [(size_t)N_NODES * HID];
__device__ float g_h2  [(size_t)N_NODES * HID];
__device__ float g_aggr[(size_t)N_NODES * HID];   // S = sum of relu(z)
__device__ float g_Pa  [(size_t)N_PAD * HID];
__device__ float g_Pb  [(size_t)N_PAD * HID];
__device__ float g_deg [N_NODES];
__device__ float g_inv [N_NODES];
// bf16 hi/lo images of current h: [n][128 cols] bf16 = 256B per node
__device__ unsigned char g_hbf_hi[(size_t)N_NODES * 256];
__device__ unsigned char g_hbf_lo[(size_t)N_NODES * 256];
// weight images: [layer][chunk 0..11][hi/lo][16KB]; [n][k] bf16x2 at SWZ(n*128+k*2)
// 0,1=W1a 2,3=W1b 4,5=W1c 6,7=W2 8,9=updW(h part) 10,11=updW(u part)
__device__ unsigned char g_wimg[(size_t)N_LAYERS * 12 * 2 * 16384];
// edge-embedding images: [tile][half][hi/lo][16KB]; [r][k] bf16x2 at SWZ(r*128+k*2)
__device__ unsigned char g_eimg[(size_t)N_TILES * 2 * 2 * 16384];

// ================= helpers =================
__device__ __forceinline__ uint32_t smem_u32(const void* p) {
    uint32_t a;
    asm("{ .reg .u64 t; cvta.to.shared.u64 t, %1; cvt.u32.u64 %0, t; }" : "=r"(a) : "l"(p));
    return a;
}
__device__ __forceinline__ uint32_t bf16x2_of(float lo, float hi) {
    uint32_t r;
    asm("cvt.rn.bf16x2.f32 %0, %1, %2;" : "=r"(r) : "f"(hi), "f"(lo));
    return r;
}
__device__ __forceinline__ float lo_f(uint32_t p) { return __uint_as_float(p << 16); }
__device__ __forceinline__ float hi_f(uint32_t p) { return __uint_as_float(p & 0xffff0000u); }

__device__ __forceinline__ void ldsm_x4(uint32_t* r, uint32_t addr) {
    asm volatile("ldmatrix.sync.aligned.m8n8.x4.shared.b16 {%0,%1,%2,%3}, [%4];"
        : "=r"(r[0]), "=r"(r[1]), "=r"(r[2]), "=r"(r[3]) : "r"(addr));
}
__device__ __forceinline__ void mma_bf16(float* d, const uint32_t* a, const uint32_t* b) {
    asm volatile(
        "mma.sync.aligned.m16n8k16.row.col.f32.bf16.bf16.f32 "
        "{%0,%1,%2,%3}, {%4,%5,%6,%7}, {%8,%9}, {%0,%1,%2,%3};"
        : "+f"(d[0]), "+f"(d[1]), "+f"(d[2]), "+f"(d[3])
        : "r"(a[0]), "r"(a[1]), "r"(a[2]), "r"(a[3]), "r"(b[0]), "r"(b[1]));
}
__device__ __forceinline__ void red_v2(float* p, float v0, float v1) {
    asm volatile("red.global.add.v2.f32 [%0], {%1, %2};"
                 :: "l"(p), "f"(v0), "f"(v1) : "memory");
}

// ================= small kernels =================
__global__ void zero_aggr_kernel() {
    size_t i = (size_t)blockIdx.x * blockDim.x + threadIdx.x;
    if (i < (size_t)N_NODES * HID) g_aggr[i] = 0.0f;
}
__global__ void zero_deg_kernel() {
    int i = blockIdx.x * blockDim.x + threadIdx.x;
    if (i < N_NODES) g_deg[i] = 0.0f;
}
__global__ void deg_kernel(const int* __restrict__ dst) {
    int e = blockIdx.x * blockDim.x + threadIdx.x;
    if (e < N_EDGES) atomicAdd(&g_deg[dst[e]], 1.0f);
}
__global__ void inv_kernel() {
    int i = blockIdx.x * blockDim.x + threadIdx.x;
    if (i < N_NODES) {
        float d = g_deg[i];
        g_inv[i] = (d > 0.0f) ? (1.0f / d) : 0.0f;
    }
}

// ---- convert h (fp32, buf 0/1) -> bf16 hi/lo node images ----
__global__ __launch_bounds__(256) void conv_h_kernel(int buf) {
    size_t i = (size_t)blockIdx.x * blockDim.x + threadIdx.x;   // pair index
    if (i >= (size_t)N_NODES * 64) return;
    const float2 v = *((const float2*)(buf ? g_h2 : g_h) + i);
    uint32_t hi = bf16x2_of(v.x, v.y);
    uint32_t lo = bf16x2_of(v.x - lo_f(hi), v.y - hi_f(hi));
    ((uint32_t*)g_hbf_hi)[i] = hi;
    ((uint32_t*)g_hbf_lo)[i] = lo;
}

// ---- precompute: weight chunk images ([n][k] bf16 hi/lo, swizzled) ----
__global__ __launch_bounds__(128) void conv_w_kernel(
    const float* __restrict__ msgW1, const float* __restrict__ msgW2,
    const float* __restrict__ updW)
{
    int l = blockIdx.x / 12, ch = blockIdx.x % 12, tid = threadIdx.x;
    const float* W;
    if (ch < 6)      W = msgW1 + (size_t)l * 384 * 128 + (size_t)(64 * ch) * 128;
    else if (ch < 8) W = msgW2 + (size_t)l * 128 * 128 + (size_t)(64 * (ch - 6)) * 128;
    else             W = updW  + (size_t)l * 256 * 128 + (size_t)(64 * (ch - 8)) * 128;
    unsigned char* hiImg = g_wimg + ((size_t)(l * 12 + ch) * 2) * 16384;
    unsigned char* loImg = hiImg + 16384;
    for (int i = tid; i < 4096; i += 128) {
        int n = i & 127, kp = i >> 7;
        int k = kp * 2;
        float v0 = W[(size_t)k * 128 + n];
        float v1 = W[(size_t)(k + 1) * 128 + n];
        uint32_t hi = bf16x2_of(v0, v1);
        uint32_t lo = bf16x2_of(v0 - lo_f(hi), v1 - hi_f(hi));
        uint32_t byte = SWZ((uint32_t)(n * 128 + k * 2));
        *(uint32_t*)(hiImg + byte) = hi;
        *(uint32_t*)(loImg + byte) = lo;
    }
}

// ---- precompute: edge embedding images erow = relu(ea@eeW+eeb) ----
__global__ __launch_bounds__(128) void conv_e_kernel(
    const float* __restrict__ eattr, const float* __restrict__ eeW, const float* __restrict__ eeb)
{
    __shared__ float s_w[4 * HID];
    __shared__ float s_b[HID];
    int tid = threadIdx.x, t = blockIdx.x;
    for (int i = tid; i < 4 * HID; i += 128) s_w[i] = eeW[i];
    s_b[tid] = eeb[tid];
    __syncthreads();
    int e = t * 128 + tid;
    float a0 = 0, a1 = 0, a2 = 0, a3 = 0;
    if (e < N_EDGES) {
        const float4 ea = *(const float4*)(eattr + (size_t)e * 4);
        a0 = ea.x; a1 = ea.y; a2 = ea.z; a3 = ea.w;
    }
    unsigned char* base = g_eimg + (size_t)t * 4 * 16384;
    for (int kp = 0; kp < 64; kp++) {
        int k = kp * 2;
        float v0 = fmaxf(s_b[k]     + a0 * s_w[k]       + a1 * s_w[128 + k]
                                    + a2 * s_w[256 + k] + a3 * s_w[384 + k], 0.0f);
        float v1 = fmaxf(s_b[k + 1] + a0 * s_w[k + 1]       + a1 * s_w[128 + k + 1]
                                    + a2 * s_w[256 + k + 1] + a3 * s_w[384 + k + 1], 0.0f);
        uint32_t hi = bf16x2_of(v0, v1);
        uint32_t lo = bf16x2_of(v0 - lo_f(hi), v1 - hi_f(hi));
        int hh = k >> 6;
        uint32_t byte = SWZ((uint32_t)(tid * 128 + (k & 63) * 2));
        *(uint32_t*)(base + (size_t)(hh * 2) * 16384 + byte)     = hi;
        *(uint32_t*)(base + (size_t)(hh * 2 + 1) * 16384 + byte) = lo;
    }
}

// ---- encoder ----
__global__ __launch_bounds__(128) void encoder_kernel(
    const float* __restrict__ x,
    const float* __restrict__ W1, const float* __restrict__ b1,
    const float* __restrict__ W2, const float* __restrict__ b2)
{
    __shared__ float Hs[32][HID];
    __shared__ float xs[32][3];
    int tid = threadIdx.x;
    int n0 = blockIdx.x * 32;

    for (int idx = tid; idx < 32 * 3; idx += 128) {
        int i = idx / 3, j = idx % 3;
        int n = n0 + i;
        xs[i][j] = (n < N_NODES) ? x[(size_t)n * 3 + j] : 0.0f;
    }
    __syncthreads();

    int c = tid;
    float w0 = W1[c], w1 = W1[HID + c], w2 = W1[2 * HID + c], bc = b1[c];
    #pragma unroll 4
    for (int i = 0; i < 32; i++) {
        float v = bc + xs[i][0] * w0 + xs[i][1] * w1 + xs[i][2] * w2;
        Hs[i][c] = fmaxf(v, 0.0f);
    }
    __syncthreads();

    float acc[32];
    #pragma unroll
    for (int i = 0; i < 32; i++) acc[i] = 0.0f;
    for (int k = 0; k < HID; k++) {
        float w = W2[(size_t)k * HID + c];
        #pragma unroll
        for (int i = 0; i < 32; i++) acc[i] = fmaf(Hs[i][k], w, acc[i]);
    }
    float b2c = b2[c];
    for (int i = 0; i < 32; i++) {
        int n = n0 + i;
        if (n < N_NODES) g_h[(size_t)n * HID + c] = acc[i] + b2c;
    }
}

// ================ shared MMA chunk routine ================
__device__ __forceinline__ void run_chunk_mma(
    uint32_t aHi, uint32_t aLo, uint32_t bHi, uint32_t bLo,
    const int rbyte[4], const int xa[4], const int nbyte[2], const int xb[2],
    float acc[4][4][4])
{
    #pragma unroll
    for (int ks = 0; ks < 4; ks++) {
        int kb = ks * 32;
        uint32_t aH[4][4], aL[4][4], bH[2][4], bL[2][4];
        #pragma unroll
        for (int rt = 0; rt < 4; rt++) {
            uint32_t off = (uint32_t)((rbyte[rt] + kb) ^ xa[rt]);
            ldsm_x4(aH[rt], aHi + off);
            ldsm_x4(aL[rt], aLo + off);
        }
        #pragma unroll
        for (int cp = 0; cp < 2; cp++) {
            uint32_t off = (uint32_t)((nbyte[cp] + kb) ^ xb[cp]);
            ldsm_x4(bH[cp], bHi + off);
            ldsm_x4(bL[cp], bLo + off);
        }
        #pragma unroll
        for (int rt = 0; rt < 4; rt++)
            #pragma unroll
            for (int ct = 0; ct < 4; ct++) {
                const uint32_t* bh = &bH[ct >> 1][(ct & 1) * 2];
                const uint32_t* bl = &bL[ct >> 1][(ct & 1) * 2];
                mma_bf16(acc[rt][ct], aH[rt], bh);
                mma_bf16(acc[rt][ct], aH[rt], bl);
                mma_bf16(acc[rt][ct], aL[rt], bh);
            }
    }
}

__device__ __forceinline__ void ldsm_addrs(int lane, int wrow, int wcol,
                                           int rbyte[4], int xa[4], int nbyte[2], int xb[2])
{
    int q = lane >> 3, i8 = lane & 7;
    #pragma unroll
    for (int rt = 0; rt < 4; rt++) {
        int r = wrow + 16 * rt + i8 + 8 * (q & 1);
        rbyte[rt] = r * 128 + 16 * (q >> 1);
        xa[rt] = (r & 7) << 4;
    }
    #pragma unroll
    for (int cp = 0; cp < 2; cp++) {
        int n = wcol + 16 * cp + i8 + 8 * (q >> 1);
        nbyte[cp] = n * 128 + 16 * (q & 1);
        xb[cp] = (n & 7) << 4;
    }
}

// copy one 16KB weight-image chunk pair (hi/lo) into smem B buffer
__device__ __forceinline__ void copy_w_chunk(char* dsm, int tid,
                                             const unsigned char* wimg, int chunk, int dstoff)
{
    const float4* whi = (const float4*)(wimg + (size_t)(chunk * 2) * 16384);
    const float4* wlo = whi + 1024;
    float4* dhi = (float4*)(dsm + dstoff);
    float4* dlo = (float4*)(dsm + dstoff + 16384);
    #pragma unroll
    for (int i = 0; i < 4; i++) {
        dhi[tid + 256 * i] = whi[tid + 256 * i];
        dlo[tid + 256 * i] = wlo[tid + 256 * i];
    }
}

// stage one 64-col h chunk (hh=0/1) from g_hbf images into smem A buffer
__device__ __forceinline__ void stage_h_chunk(char* dsm, int tid, int n0, int hh, int abase)
{
    int r = tid >> 1, half = tid & 1;
    int node = n0 + r; if (node >= N_NODES) node = N_NODES - 1;
    int rx = r & 7;
    int sgbase = 8 * hh + half * 4;
    const uint4* pHi = (const uint4*)(g_hbf_hi + (size_t)node * 256) + sgbase;
    const uint4* pLo = (const uint4*)(g_hbf_lo + (size_t)node * 256) + sgbase;
    #pragma unroll
    for (int j = 0; j < 4; j++) {
        int dg = (half * 4 + j) ^ rx;
        *(uint4*)(dsm + abase + r * 128 + dg * 16) = pHi[j];
        *(uint4*)(dsm + abase + 16384 + r * 128 + dg * 16) = pLo[j];
    }
}

// ================ node_pre: P_a = h@W1a, P_b = h@W1b ================
__global__ void __launch_bounds__(256) node_pre_kernel(int layer)
{
    extern __shared__ char dsm[];
    uint32_t sb = smem_u32(dsm);
    int tid = threadIdx.x, wid = tid >> 5, lane = tid & 31;
    int wrow = 64 * (wid >> 2), wcol = 32 * (wid & 3);
    int n0 = blockIdx.x * 128;
    const unsigned char* wimg = g_wimg + (size_t)layer * 12 * 2 * 16384;

    stage_h_chunk(dsm, tid, n0, 0, NPA0_HI);
    stage_h_chunk(dsm, tid, n0, 1, NPA1_HI);

    int rbyte[4], xa[4], nbyte[2], xb[2];
    ldsm_addrs(lane, wrow, wcol, rbyte, xa, nbyte, xb);

    float acc[4][4][4];
    #pragma unroll
    for (int a = 0; a < 4; a++)
        #pragma unroll
        for (int b = 0; b < 4; b++)
            #pragma unroll
            for (int c = 0; c < 4; c++) acc[a][b][c] = 0.0f;

    for (int chunk = 0; chunk < 4; chunk++) {
        __syncthreads();
        copy_w_chunk(dsm, tid, wimg, chunk, NPB_HI);
        __syncthreads();
        uint32_t aBase = sb + ((chunk & 1) ? NPA1_HI : NPA0_HI);
        run_chunk_mma(aBase, aBase + 16384, sb + NPB_HI, sb + NPB_LO,
                      rbyte, xa, nbyte, xb, acc);
        if (chunk & 1) {
            float* P = (chunk < 2) ? g_Pa : g_Pb;
            #pragma unroll
            for (int rt = 0; rt < 4; rt++) {
                int m1 = wrow + 16 * rt + (lane >> 2);
                int m2 = m1 + 8;
                #pragma unroll
                for (int ct = 0; ct < 4; ct++) {
                    int col = wcol + 8 * ct + 2 * (lane & 3);
                    if (n0 + m1 < N_NODES) {
                        float2 v = {acc[rt][ct][0], acc[rt][ct][1]};
                        *(float2*)(P + (size_t)(n0 + m1) * HID + col) = v;
                    }
                    if (n0 + m2 < N_NODES) {
                        float2 v = {acc[rt][ct][2], acc[rt][ct][3]};
                        *(float2*)(P + (size_t)(n0 + m2) * HID + col) = v;
                    }
                }
            }
            #pragma unroll
            for (int a = 0; a < 4; a++)
                #pragma unroll
                for (int b = 0; b < 4; b++)
                    #pragma unroll
                    for (int c = 0; c < 4; c++) acc[a][b][c] = 0.0f;
        }
    }
}

// ================ edge kernel: Pe MMA + gather-add + relu + scatter S ================
__global__ void __launch_bounds__(256) edge_kernel(
    int layer,
    const int* __restrict__ src, const int* __restrict__ dst,
    const float* __restrict__ b1)
{
    extern __shared__ char dsm[];
    uint32_t sb = smem_u32(dsm);
    int tid = threadIdx.x, wid = tid >> 5, lane = tid & 31;
    int wrow = 64 * (wid >> 2), wcol = 32 * (wid & 3);
    int t = blockIdx.x, e0 = t * 128;

    if (tid < 128) {
        int e = e0 + tid;
        ((int*)(dsm + EOFF_DST))[tid] = (e < N_EDGES) ? dst[e] : 0;
        ((int*)(dsm + EOFF_SRC))[tid] = (e < N_EDGES) ? src[e] : 0;
        ((float*)(dsm + EOFF_B1))[tid] = b1[tid];
    }
    const int* sd = (const int*)(dsm + EOFF_DST);
    const int* ssrc = (const int*)(dsm + EOFF_SRC);
    const float* sb1 = (const float*)(dsm + EOFF_B1);
    const unsigned char* wimg = g_wimg + (size_t)layer * 12 * 2 * 16384;

    int rbyte[4], xa[4], nbyte[2], xb[2];
    ldsm_addrs(lane, wrow, wcol, rbyte, xa, nbyte, xb);

    float acc[4][4][4];
    #pragma unroll
    for (int a = 0; a < 4; a++)
        #pragma unroll
        for (int b = 0; b < 4; b++)
            #pragma unroll
            for (int c = 0; c < 4; c++) acc[a][b][c] = 0.0f;

    // Pe = e-image @ W1c  (chunks 4,5)
    for (int c = 0; c < 2; c++) {
        if (c) __syncthreads();
        {
            const float4* ehi = (const float4*)(g_eimg + ((size_t)(t * 2 + c) * 2) * 16384);
            const float4* elo = ehi + 1024;
            float4* dahi = (float4*)(dsm + EA_HI);
            float4* dalo = (float4*)(dsm + EA_LO);
            #pragma unroll
            for (int i = 0; i < 4; i++) {
                dahi[tid + 256 * i] = ehi[tid + 256 * i];
                dalo[tid + 256 * i] = elo[tid + 256 * i];
            }
            copy_w_chunk(dsm, tid, wimg, 4 + c, EB_HI);
        }
        __syncthreads();
        run_chunk_mma(sb + EA_HI, sb + EA_LO, sb + EB_HI, sb + EB_LO,
                      rbyte, xa, nbyte, xb, acc);
    }

    // epilogue: z = Pe + b1 + Pa[dst] + Pb[src]; relu; scatter-add into S
    #pragma unroll
    for (int rt = 0; rt < 4; rt++) {
        int m1 = wrow + 16 * rt + (lane >> 2);
        int m2 = m1 + 8;
        bool v1ok = (e0 + m1) < N_EDGES;
        bool v2ok = (e0 + m2) < N_EDGES;
        int d1 = sd[m1], s1 = ssrc[m1];
        int d2 = sd[m2], s2 = ssrc[m2];
        const float* pa1 = g_Pa + (size_t)d1 * HID;
        const float* pb1 = g_Pb + (size_t)s1 * HID;
        const float* pa2 = g_Pa + (size_t)d2 * HID;
        const float* pb2 = g_Pb + (size_t)s2 * HID;
        float* ag1 = g_aggr + (size_t)d1 * HID;
        float* ag2 = g_aggr + (size_t)d2 * HID;
        #pragma unroll
        for (int ct = 0; ct < 4; ct++) {
            int col = wcol + 8 * ct + 2 * (lane & 3);
            float bv0 = sb1[col], bv1 = sb1[col + 1];
            if (v1ok) {
                float2 a = *(const float2*)(pa1 + col);
                float2 b = *(const float2*)(pb1 + col);
                float z0 = fmaxf(acc[rt][ct][0] + bv0 + a.x + b.x, 0.0f);
                float z1 = fmaxf(acc[rt][ct][1] + bv1 + a.y + b.y, 0.0f);
                red_v2(ag1 + col, z0, z1);
            }
            if (v2ok) {
                float2 a = *(const float2*)(pa2 + col);
                float2 b = *(const float2*)(pb2 + col);
                float z0 = fmaxf(acc[rt][ct][2] + bv0 + a.x + b.x, 0.0f);
                float z1 = fmaxf(acc[rt][ct][3] + bv1 + a.y + b.y, 0.0f);
                red_v2(ag2 + col, z0, z1);
            }
        }
    }
}

// ================ node_post (HMMA): u=(S*inv)@W2+b2[deg>0]; upd=[h|u]@updW;
//                 r=h+relu(upd+b); LN -> hout + next-layer bf16 images ================
__global__ void __launch_bounds__(256) node_post_kernel(
    int parity, int layer,
    const float* __restrict__ b2, const float* __restrict__ ub,
    const float* __restrict__ lg, const float* __restrict__ lb)
{
    extern __shared__ char dsm[];
    __shared__ float s_b2[128], s_ub[128], s_g[128], s_lb[128], s_mask[128];
    uint32_t sb = smem_u32(dsm);
    int tid = threadIdx.x, wid = tid >> 5, lane = tid & 31;
    int wrow = 64 * (wid >> 2), wcol = 32 * (wid & 3);
    int n0 = blockIdx.x * 128;
    const float* __restrict__ h    = parity ? g_h2 : g_h;
    float*       __restrict__ hout = parity ? g_h  : g_h2;
    const unsigned char* wimg = g_wimg + (size_t)layer * 12 * 2 * 16384;

    if (tid < 128) {
        s_b2[tid] = b2[tid]; s_ub[tid] = ub[tid];
        s_g[tid] = lg[tid];  s_lb[tid] = lb[tid];
        int n = n0 + tid;
        s_mask[tid] = (n < N_NODES && g_deg[n] > 0.0f) ? 1.0f : 0.0f;
    }

    // stage A = S*inv as bf16 hi/lo images: chunk0 (cols 0-63)->A0, chunk1->A1
    {
        int r = tid >> 1, half = tid & 1;
        int node = n0 + r; float iv = 0.0f;
        if (node < N_NODES) iv = g_inv[node]; else node = N_NODES - 1;
        const float2* Srow = (const float2*)(g_aggr + (size_t)node * HID) + half * 32;
        int ab = half ? PBA1 : PBA0;
        int rx = r & 7;
        #pragma unroll
        for (int gi = 0; gi < 8; gi++) {
            uint32_t hv[4], lv[4];
            #pragma unroll
            for (int j = 0; j < 4; j++) {
                float2 v = Srow[gi * 4 + j];
                v.x *= iv; v.y *= iv;
                uint32_t hi = bf16x2_of(v.x, v.y);
                uint32_t lo = bf16x2_of(v.x - lo_f(hi), v.y - hi_f(hi));
                hv[j] = hi; lv[j] = lo;
            }
            int dg = gi ^ rx;
            *(uint4*)(dsm + ab + r * 128 + dg * 16) = make_uint4(hv[0], hv[1], hv[2], hv[3]);
            *(uint4*)(dsm + ab + 16384 + r * 128 + dg * 16) = make_uint4(lv[0], lv[1], lv[2], lv[3]);
        }
    }

    int rbyte[4], xa[4], nbyte[2], xb[2];
    ldsm_addrs(lane, wrow, wcol, rbyte, xa, nbyte, xb);

    float acc[4][4][4];
    #pragma unroll
    for (int a = 0; a < 4; a++)
        #pragma unroll
        for (int b = 0; b < 4; b++)
            #pragma unroll
            for (int c = 0; c < 4; c++) acc[a][b][c] = 0.0f;

    // ---- stage 1: u = S' @ W2 (W chunks 6,7) ----
    for (int c = 0; c < 2; c++) {
        __syncthreads();
        copy_w_chunk(dsm, tid, wimg, 6 + c, PBB);
        __syncthreads();
        uint32_t aBase = sb + (c ? PBA1 : PBA0);
        run_chunk_mma(aBase, aBase + 16384, sb + PBB, sb + PBB + 16384,
                      rbyte, xa, nbyte, xb, acc);
    }
    __syncthreads();   // mma reads of A0/A1 done

    // u fragments (+ masked b2) -> bf16 images: cols 0-63 -> A0, 64-127 -> A1
    #pragma unroll
    for (int rt = 0; rt < 4; rt++) {
        int m1 = wrow + 16 * rt + (lane >> 2);
        int m2 = m1 + 8;
        float mk1 = s_mask[m1], mk2 = s_mask[m2];
        #pragma unroll
        for (int ct = 0; ct < 4; ct++) {
            int col = wcol + 8 * ct + 2 * (lane & 3);
            int ab = (col >= 64) ? PBA1 : PBA0;
            int k2 = (col & 63) * 2;
            float bb0 = s_b2[col], bb1 = s_b2[col + 1];
            {
                float v0 = acc[rt][ct][0] + mk1 * bb0;
                float v1 = acc[rt][ct][1] + mk1 * bb1;
                uint32_t hi = bf16x2_of(v0, v1);
                uint32_t lo = bf16x2_of(v0 - lo_f(hi), v1 - hi_f(hi));
                uint32_t byte = SWZ((uint32_t)(m1 * 128 + k2));
                *(uint32_t*)(dsm + ab + byte) = hi;
                *(uint32_t*)(dsm + ab + 16384 + byte) = lo;
            }
            {
                float v0 = acc[rt][ct][2] + mk2 * bb0;
                float v1 = acc[rt][ct][3] + mk2 * bb1;
                uint32_t hi = bf16x2_of(v0, v1);
                uint32_t lo = bf16x2_of(v0 - lo_f(hi), v1 - hi_f(hi));
                uint32_t byte = SWZ((uint32_t)(m2 * 128 + k2));
                *(uint32_t*)(dsm + ab + byte) = hi;
                *(uint32_t*)(dsm + ab + 16384 + byte) = lo;
            }
        }
    }
    #pragma unroll
    for (int a = 0; a < 4; a++)
        #pragma unroll
        for (int b = 0; b < 4; b++)
            #pragma unroll
            for (int c = 0; c < 4; c++) acc[a][b][c] = 0.0f;

    // ---- stage 2: upd = [h|u] @ updW. order: u0(A0,ch10) u1(A1,ch11) h0(A0,ch8) h1(A1,ch9)
    for (int s = 0; s < 4; s++) {
        __syncthreads();
        if (s >= 2) stage_h_chunk(dsm, tid, n0, s - 2, (s & 1) ? PBA1 : PBA0);
        copy_w_chunk(dsm, tid, wimg, (s < 2) ? (10 + s) : (8 + (s - 2)), PBB);
        __syncthreads();
        uint32_t aBase = sb + ((s & 1) ? PBA1 : PBA0);
        run_chunk_mma(aBase, aBase + 16384, sb + PBB, sb + PBB + 16384,
                      rbyte, xa, nbyte, xb, acc);
    }
    __syncthreads();   // all mma reads done; A region reusable as fp32 R

    // r = h + relu(upd + ub) -> RBUF fp32 [128][128]
    #pragma unroll
    for (int rt = 0; rt < 4; rt++) {
        int m1 = wrow + 16 * rt + (lane >> 2);
        int m2 = m1 + 8;
        int nd1 = n0 + m1; if (nd1 >= N_NODES) nd1 = N_NODES - 1;
        int nd2 = n0 + m2; if (nd2 >= N_NODES) nd2 = N_NODES - 1;
        #pragma unroll
        for (int ct = 0; ct < 4; ct++) {
            int col = wcol + 8 * ct + 2 * (lane & 3);
            float u0 = s_ub[col], u1 = s_ub[col + 1];
            {
                float2 hv = *(const float2*)(h + (size_t)nd1 * HID + col);
                float r0 = hv.x + fmaxf(acc[rt][ct][0] + u0, 0.0f);
                float r1 = hv.y + fmaxf(acc[rt][ct][1] + u1, 0.0f);
                float2 v = {r0, r1};
                *(float2*)(dsm + PBR + m1 * 512 + col * 4) = v;
            }
            {
                float2 hv = *(const float2*)(h + (size_t)nd2 * HID + col);
                float r0 = hv.x + fmaxf(acc[rt][ct][2] + u0, 0.0f);
                float r1 = hv.y + fmaxf(acc[rt][ct][3] + u1, 0.0f);
                float2 v = {r0, r1};
                *(float2*)(dsm + PBR + m2 * 512 + col * 4) = v;
            }
        }
    }
    __syncthreads();

    // LN: 2 threads per row, each owns 64 cols
    {
        int row = tid >> 1, half = tid & 1;
        const float4* r4 = (const float4*)(dsm + PBR + row * 512 + half * 256);
        float s = 0.0f, q = 0.0f;
        #pragma unroll
        for (int j = 0; j < 16; j++) {
            float4 v = r4[j];
            s += v.x + v.y + v.z + v.w;
            q += v.x * v.x + v.y * v.y + v.z * v.z + v.w * v.w;
        }
        s += __shfl_xor_sync(0xffffffffu, s, 1);
        q += __shfl_xor_sync(0xffffffffu, q, 1);
        float mu = s * (1.0f / HID);
        float var = q * (1.0f / HID) - mu * mu;
        float rs = rsqrtf(var + 1e-5f);

        int node = n0 + row;
        if (node < N_NODES) {
            float4* ho = (float4*)(hout + (size_t)node * HID + half * 64);
            uint4* bh = (uint4*)(g_hbf_hi + (size_t)node * 256) + half * 8;
            uint4* bl = (uint4*)(g_hbf_lo + (size_t)node * 256) + half * 8;
            #pragma unroll
            for (int g2 = 0; g2 < 8; g2++) {
                float ov[8];
                #pragma unroll
                for (int e = 0; e < 2; e++) {
                    float4 v = r4[g2 * 2 + e];
                    int cb = half * 64 + g2 * 8 + e * 4;
                    ov[e * 4 + 0] = (v.x - mu) * rs * s_g[cb + 0] + s_lb[cb + 0];
                    ov[e * 4 + 1] = (v.y - mu) * rs * s_g[cb + 1] + s_lb[cb + 1];
                    ov[e * 4 + 2] = (v.z - mu) * rs * s_g[cb + 2] + s_lb[cb + 2];
                    ov[e * 4 + 3] = (v.w - mu) * rs * s_g[cb + 3] + s_lb[cb + 3];
                }
                float4 o0 = {ov[0], ov[1], ov[2], ov[3]};
                float4 o1 = {ov[4], ov[5], ov[6], ov[7]};
                ho[g2 * 2] = o0; ho[g2 * 2 + 1] = o1;
                uint32_t hv[4], lv[4];
                #pragma unroll
                for (int p = 0; p < 4; p++) {
                    float v0 = ov[2 * p], v1 = ov[2 * p + 1];
                    uint32_t hi = bf16x2_of(v0, v1);
                    uint32_t lo = bf16x2_of(v0 - lo_f(hi), v1 - hi_f(hi));
                    hv[p] = hi; lv[p] = lo;
                }
                bh[g2] = make_uint4(hv[0], hv[1], hv[2], hv[3]);
                bl[g2] = make_uint4(lv[0], lv[1], lv[2], lv[3]);
            }
        }
    }
}

// ---- decoder ----
__global__ __launch_bounds__(128) void decoder_kernel(
    int parity,
    const float* __restrict__ W1, const float* __restrict__ b1,
    const float* __restrict__ W2, const float* __restrict__ b2,
    float* __restrict__ out)
{
    __shared__ float Hs[32][HID];
    __shared__ float s_red[32];

    const float* __restrict__ h = parity ? g_h2 : g_h;

    int tid = threadIdx.x;
    int n0 = blockIdx.x * 32;

    for (int idx = tid; idx < 32 * HID; idx += 128) {
        int i = idx >> 7, k = idx & 127;
        int n = n0 + i;
        Hs[i][k] = (n < N_NODES) ? h[(size_t)n * HID + k] : 0.0f;
    }
    __syncthreads();

    int c = tid;
    float acc[32];
    #pragma unroll
    for (int i = 0; i < 32; i++) acc[i] = 0.0f;
    for (int k = 0; k < HID; k++) {
        float w = W1[(size_t)k * HID + c];
        #pragma unroll
        for (int i = 0; i < 32; i++) acc[i] = fmaf(Hs[i][k], w, acc[i]);
    }
    __syncthreads();

    float b1c = b1[c], w2c = W2[c];
    #pragma unroll
    for (int i = 0; i < 32; i++)
        Hs[i][c] = fmaxf(acc[i] + b1c, 0.0f) * w2c;
    __syncthreads();

    int warp = tid >> 5, lane = tid & 31;
    for (int i = warp; i < 32; i += 4) {
        float s = Hs[i][lane] + Hs[i][32 + lane] + Hs[i][64 + lane] + Hs[i][96 + lane];
        #pragma unroll
        for (int o = 16; o > 0; o >>= 1) s += __shfl_xor_sync(0xffffffffu, s, o);
        if (lane == 0) s_red[i] = s;
    }
    __syncthreads();
    if (tid < 32) {
        int n = n0 + tid;
        if (n < N_NODES) out[n] = s_red[tid] + b2[0];
    }
}

extern "C" void kernel_launch(void* const* d_in, const int* in_sizes, int n_in,
                              void* d_out, int out_size)
{
    const float* x      = (const float*)d_in[0];
    const int*   ei     = (const int*)  d_in[1];
    const float* eattr  = (const float*)d_in[2];
    const float* encW1  = (const float*)d_in[3];
    const float* encb1  = (const float*)d_in[4];
    const float* encW2  = (const float*)d_in[5];
    const float* encb2  = (const float*)d_in[6];
    const float* eeW    = (const float*)d_in[7];
    const float* eeb    = (const float*)d_in[8];
    const float* msgW1  = (const float*)d_in[9];
    const float* msgb1  = (const float*)d_in[10];
    const float* msgW2  = (const float*)d_in[11];
    const float* msgb2  = (const float*)d_in[12];
    const float* updW   = (const float*)d_in[13];
    const float* updb   = (const float*)d_in[14];
    const float* lng    = (const float*)d_in[15];
    const float* lnb    = (const float*)d_in[16];
    const float* decW1  = (const float*)d_in[17];
    const float* decb1  = (const float*)d_in[18];
    const float* decW2  = (const float*)d_in[19];
    const float* decb2  = (const float*)d_in[20];
    float* out = (float*)d_out;

    const int* src = ei;
    const int* dst = ei + N_EDGES;

    cudaFuncSetAttribute(edge_kernel, cudaFuncAttributeMaxDynamicSharedMemorySize, E_SMEM);
    cudaFuncSetAttribute(node_pre_kernel, cudaFuncAttributeMaxDynamicSharedMemorySize, NP_SMEM);
    cudaFuncSetAttribute(node_post_kernel, cudaFuncAttributeMaxDynamicSharedMemorySize, PB_SMEM);

    conv_w_kernel<<<N_LAYERS * 12, 128>>>(msgW1, msgW2, updW);
    conv_e_kernel<<<N_TILES, 128>>>(eattr, eeW, eeb);

    zero_deg_kernel<<<(N_NODES + 255) / 256, 256>>>();
    deg_kernel<<<(N_EDGES + 255) / 256, 256>>>(dst);
    inv_kernel<<<(N_NODES + 255) / 256, 256>>>();
    encoder_kernel<<<(N_NODES + 31) / 32, 128>>>(x, encW1, encb1, encW2, encb2);
    conv_h_kernel<<<(N_NODES * 64 + 255) / 256, 256>>>(0);   // h in g_h

    for (int l = 0; l < N_LAYERS; l++) {
        int parity = l & 1;
        node_pre_kernel<<<N_NTILES, 256, NP_SMEM>>>(l);
        zero_aggr_kernel<<<((N_NODES * HID) + 511) / 512, 512>>>();
        edge_kernel<<<N_TILES, 256, E_SMEM>>>(l, src, dst, msgb1 + (size_t)l * HID);
        node_post_kernel<<<N_NTILES, 256, PB_SMEM>>>(
            parity, l,
            msgb2 + (size_t)l * HID, updb + (size_t)l * HID,
            lng + (size_t)l * HID, lnb + (size_t)l * HID);
    }
    decoder_kernel<<<(N_NODES + 31) / 32, 128>>>(0, decW1, decb1, decW2, decb2, out);
}

// round 15
// speedup vs baseline: 4.5313x; 1.3751x over previous
#include <cuda_runtime.h>
#include <cuda_bf16.h>
#include <cstdint>

#define N_NODES 50000
#define N_EDGES 600000
#define HID 128
#define N_LAYERS 6
#define N_TILES 4688          // ceil(600000/128)
#define N_NTILES 391          // ceil(50000/128)
#define N_PAD (N_NTILES * 128)
#define EDGE_GRID 296

#define SWZ(x) ((x) ^ (((x) >> 3) & 0x70))

// ---- node kernels dynamic smem layout (A0/A1 = 64-col K-chunk images, B = weight chunk) ----
#define A0_HI 0
#define A0_LO 16384
#define A1_HI 32768
#define A1_LO 49152
#define BB_HI 65536
#define BB_LO 81920
#define ND_SMEM 98304

// ---- edge smem layout (persistent: both W chunks resident) ----
#define EA_HI 0
#define EA_LO 16384
#define EBC0_HI 32768
#define EBC0_LO 49152
#define EBC1_HI 65536
#define EBC1_LO 81920
#define EOFF_DST 98304
#define EOFF_SRC 98816
#define E_SMEM   99328

// ---- scratch (no allocations allowed) ----
__device__ float g_h   [(size_t)N_NODES * HID];
__device__ float g_h2  [(size_t)N_NODES * HID];
__device__ float g_aggr[(size_t)N_NODES * HID];   // S = sum of relu(z)
__device__ float g_Pa  [(size_t)N_PAD * HID];
__device__ float g_Pb  [(size_t)N_PAD * HID];
__device__ float g_deg [N_NODES];
__device__ float g_inv [N_NODES];
__device__ unsigned char g_hbf_hi[(size_t)N_NODES * 256];
__device__ unsigned char g_hbf_lo[(size_t)N_NODES * 256];
// weight images: [layer][chunk 0..11][hi/lo][16KB]; [n][k] bf16x2 at SWZ(n*128+k*2)
// 0,1=W1a 2,3=W1b 4,5=W1c 6,7=W2 8,9=updW(h part) 10,11=updW(u part)
__device__ unsigned char g_wimg[(size_t)N_LAYERS * 12 * 2 * 16384];
// edge-embedding images: [tile][half][hi/lo][16KB]
__device__ unsigned char g_eimg[(size_t)N_TILES * 2 * 2 * 16384];

// ================= helpers =================
__device__ __forceinline__ uint32_t smem_u32(const void* p) {
    uint32_t a;
    asm("{ .reg .u64 t; cvta.to.shared.u64 t, %1; cvt.u32.u64 %0, t; }" : "=r"(a) : "l"(p));
    return a;
}
__device__ __forceinline__ uint32_t bf16x2_of(float lo, float hi) {
    uint32_t r;
    asm("cvt.rn.bf16x2.f32 %0, %1, %2;" : "=r"(r) : "f"(hi), "f"(lo));
    return r;
}
__device__ __forceinline__ float lo_f(uint32_t p) { return __uint_as_float(p << 16); }
__device__ __forceinline__ float hi_f(uint32_t p) { return __uint_as_float(p & 0xffff0000u); }

__device__ __forceinline__ void ldsm_x4(uint32_t* r, uint32_t addr) {
    asm volatile("ldmatrix.sync.aligned.m8n8.x4.shared.b16 {%0,%1,%2,%3}, [%4];"
        : "=r"(r[0]), "=r"(r[1]), "=r"(r[2]), "=r"(r[3]) : "r"(addr));
}
__device__ __forceinline__ void mma_bf16(float* d, const uint32_t* a, const uint32_t* b) {
    asm volatile(
        "mma.sync.aligned.m16n8k16.row.col.f32.bf16.bf16.f32 "
        "{%0,%1,%2,%3}, {%4,%5,%6,%7}, {%8,%9}, {%0,%1,%2,%3};"
        : "+f"(d[0]), "+f"(d[1]), "+f"(d[2]), "+f"(d[3])
        : "r"(a[0]), "r"(a[1]), "r"(a[2]), "r"(a[3]), "r"(b[0]), "r"(b[1]));
}
__device__ __forceinline__ void red_v2(float* p, float v0, float v1) {
    asm volatile("red.global.add.v2.f32 [%0], {%1, %2};"
                 :: "l"(p), "f"(v0), "f"(v1) : "memory");
}

// ================= small kernels =================
__global__ void zero_deg_kernel() {
    int i = blockIdx.x * blockDim.x + threadIdx.x;
    if (i < N_NODES) g_deg[i] = 0.0f;
}
__global__ void deg_kernel(const int* __restrict__ dst) {
    int e = blockIdx.x * blockDim.x + threadIdx.x;
    if (e < N_EDGES) atomicAdd(&g_deg[dst[e]], 1.0f);
}
__global__ void inv_kernel() {
    int i = blockIdx.x * blockDim.x + threadIdx.x;
    if (i < N_NODES) {
        float d = g_deg[i];
        g_inv[i] = (d > 0.0f) ? (1.0f / d) : 0.0f;
    }
}

// ---- convert h (fp32 in g_h) -> bf16 hi/lo node images (layer 0 only) ----
__global__ __launch_bounds__(256) void conv_h_kernel() {
    size_t i = (size_t)blockIdx.x * blockDim.x + threadIdx.x;
    if (i >= (size_t)N_NODES * 64) return;
    const float2 v = *((const float2*)g_h + i);
    uint32_t hi = bf16x2_of(v.x, v.y);
    uint32_t lo = bf16x2_of(v.x - lo_f(hi), v.y - hi_f(hi));
    ((uint32_t*)g_hbf_hi)[i] = hi;
    ((uint32_t*)g_hbf_lo)[i] = lo;
}

// ---- precompute: weight chunk images ----
__global__ __launch_bounds__(128) void conv_w_kernel(
    const float* __restrict__ msgW1, const float* __restrict__ msgW2,
    const float* __restrict__ updW)
{
    int l = blockIdx.x / 12, ch = blockIdx.x % 12, tid = threadIdx.x;
    const float* W;
    if (ch < 6)      W = msgW1 + (size_t)l * 384 * 128 + (size_t)(64 * ch) * 128;
    else if (ch < 8) W = msgW2 + (size_t)l * 128 * 128 + (size_t)(64 * (ch - 6)) * 128;
    else             W = updW  + (size_t)l * 256 * 128 + (size_t)(64 * (ch - 8)) * 128;
    unsigned char* hiImg = g_wimg + ((size_t)(l * 12 + ch) * 2) * 16384;
    unsigned char* loImg = hiImg + 16384;
    for (int i = tid; i < 4096; i += 128) {
        int n = i & 127, kp = i >> 7;
        int k = kp * 2;
        float v0 = W[(size_t)k * 128 + n];
        float v1 = W[(size_t)(k + 1) * 128 + n];
        uint32_t hi = bf16x2_of(v0, v1);
        uint32_t lo = bf16x2_of(v0 - lo_f(hi), v1 - hi_f(hi));
        uint32_t byte = SWZ((uint32_t)(n * 128 + k * 2));
        *(uint32_t*)(hiImg + byte) = hi;
        *(uint32_t*)(loImg + byte) = lo;
    }
}

// ---- precompute: edge embedding images erow = relu(ea@eeW+eeb) ----
__global__ __launch_bounds__(128) void conv_e_kernel(
    const float* __restrict__ eattr, const float* __restrict__ eeW, const float* __restrict__ eeb)
{
    __shared__ float s_w[4 * HID];
    __shared__ float s_b[HID];
    int tid = threadIdx.x, t = blockIdx.x;
    for (int i = tid; i < 4 * HID; i += 128) s_w[i] = eeW[i];
    s_b[tid] = eeb[tid];
    __syncthreads();
    int e = t * 128 + tid;
    float a0 = 0, a1 = 0, a2 = 0, a3 = 0;
    if (e < N_EDGES) {
        const float4 ea = *(const float4*)(eattr + (size_t)e * 4);
        a0 = ea.x; a1 = ea.y; a2 = ea.z; a3 = ea.w;
    }
    unsigned char* base = g_eimg + (size_t)t * 4 * 16384;
    for (int kp = 0; kp < 64; kp++) {
        int k = kp * 2;
        float v0 = fmaxf(s_b[k]     + a0 * s_w[k]       + a1 * s_w[128 + k]
                                    + a2 * s_w[256 + k] + a3 * s_w[384 + k], 0.0f);
        float v1 = fmaxf(s_b[k + 1] + a0 * s_w[k + 1]       + a1 * s_w[128 + k + 1]
                                    + a2 * s_w[256 + k + 1] + a3 * s_w[384 + k + 1], 0.0f);
        uint32_t hi = bf16x2_of(v0, v1);
        uint32_t lo = bf16x2_of(v0 - lo_f(hi), v1 - hi_f(hi));
        int hh = k >> 6;
        uint32_t byte = SWZ((uint32_t)(tid * 128 + (k & 63) * 2));
        *(uint32_t*)(base + (size_t)(hh * 2) * 16384 + byte)     = hi;
        *(uint32_t*)(base + (size_t)(hh * 2 + 1) * 16384 + byte) = lo;
    }
}

// ---- encoder ----
__global__ __launch_bounds__(128) void encoder_kernel(
    const float* __restrict__ x,
    const float* __restrict__ W1, const float* __restrict__ b1,
    const float* __restrict__ W2, const float* __restrict__ b2)
{
    __shared__ float Hs[32][HID];
    __shared__ float xs[32][3];
    int tid = threadIdx.x;
    int n0 = blockIdx.x * 32;

    for (int idx = tid; idx < 32 * 3; idx += 128) {
        int i = idx / 3, j = idx % 3;
        int n = n0 + i;
        xs[i][j] = (n < N_NODES) ? x[(size_t)n * 3 + j] : 0.0f;
    }
    __syncthreads();

    int c = tid;
    float w0 = W1[c], w1 = W1[HID + c], w2 = W1[2 * HID + c], bc = b1[c];
    #pragma unroll 4
    for (int i = 0; i < 32; i++) {
        float v = bc + xs[i][0] * w0 + xs[i][1] * w1 + xs[i][2] * w2;
        Hs[i][c] = fmaxf(v, 0.0f);
    }
    __syncthreads();

    float acc[32];
    #pragma unroll
    for (int i = 0; i < 32; i++) acc[i] = 0.0f;
    for (int k = 0; k < HID; k++) {
        float w = W2[(size_t)k * HID + c];
        #pragma unroll
        for (int i = 0; i < 32; i++) acc[i] = fmaf(Hs[i][k], w, acc[i]);
    }
    float b2c = b2[c];
    for (int i = 0; i < 32; i++) {
        int n = n0 + i;
        if (n < N_NODES) g_h[(size_t)n * HID + c] = acc[i] + b2c;
    }
}

// ================ shared MMA routines ================
__device__ __forceinline__ void run_chunk_mma(
    uint32_t aHi, uint32_t aLo, uint32_t bHi, uint32_t bLo,
    const int rbyte[4], const int xa[4], const int nbyte[2], const int xb[2],
    float acc[4][4][4])
{
    #pragma unroll
    for (int ks = 0; ks < 4; ks++) {
        int kb = ks * 32;
        uint32_t aH[4][4], aL[4][4], bH[2][4], bL[2][4];
        #pragma unroll
        for (int rt = 0; rt < 4; rt++) {
            uint32_t off = (uint32_t)((rbyte[rt] + kb) ^ xa[rt]);
            ldsm_x4(aH[rt], aHi + off);
            ldsm_x4(aL[rt], aLo + off);
        }
        #pragma unroll
        for (int cp = 0; cp < 2; cp++) {
            uint32_t off = (uint32_t)((nbyte[cp] + kb) ^ xb[cp]);
            ldsm_x4(bH[cp], bHi + off);
            ldsm_x4(bL[cp], bLo + off);
        }
        #pragma unroll
        for (int rt = 0; rt < 4; rt++)
            #pragma unroll
            for (int ct = 0; ct < 4; ct++) {
                const uint32_t* bh = &bH[ct >> 1][(ct & 1) * 2];
                const uint32_t* bl = &bL[ct >> 1][(ct & 1) * 2];
                mma_bf16(acc[rt][ct], aH[rt], bh);
                mma_bf16(acc[rt][ct], aH[rt], bl);
                mma_bf16(acc[rt][ct], aL[rt], bh);
            }
    }
}

__device__ __forceinline__ void ldsm_addrs(int lane, int wrow, int wcol,
                                           int rbyte[4], int xa[4], int nbyte[2], int xb[2])
{
    int q = lane >> 3, i8 = lane & 7;
    #pragma unroll
    for (int rt = 0; rt < 4; rt++) {
        int r = wrow + 16 * rt + i8 + 8 * (q & 1);
        rbyte[rt] = r * 128 + 16 * (q >> 1);
        xa[rt] = (r & 7) << 4;
    }
    #pragma unroll
    for (int cp = 0; cp < 2; cp++) {
        int n = wcol + 16 * cp + i8 + 8 * (q >> 1);
        nbyte[cp] = n * 128 + 16 * (q & 1);
        xb[cp] = (n & 7) << 4;
    }
}

__device__ __forceinline__ void copy_w_chunk(char* dsm, int tid,
                                             const unsigned char* wimg, int chunk, int dstoff)
{
    const float4* whi = (const float4*)(wimg + (size_t)(chunk * 2) * 16384);
    const float4* wlo = whi + 1024;
    float4* dhi = (float4*)(dsm + dstoff);
    float4* dlo = (float4*)(dsm + dstoff + 16384);
    #pragma unroll
    for (int i = 0; i < 4; i++) {
        dhi[tid + 256 * i] = whi[tid + 256 * i];
        dlo[tid + 256 * i] = wlo[tid + 256 * i];
    }
}

__device__ __forceinline__ void stage_h_chunk(char* dsm, int tid, int n0, int hh, int abase)
{
    int r = tid >> 1, half = tid & 1;
    int node = n0 + r; if (node >= N_NODES) node = N_NODES - 1;
    int rx = r & 7;
    int sgbase = 8 * hh + half * 4;
    const uint4* pHi = (const uint4*)(g_hbf_hi + (size_t)node * 256) + sgbase;
    const uint4* pLo = (const uint4*)(g_hbf_lo + (size_t)node * 256) + sgbase;
    #pragma unroll
    for (int j = 0; j < 4; j++) {
        int dg = (half * 4 + j) ^ rx;
        *(uint4*)(dsm + abase + r * 128 + dg * 16) = pHi[j];
        *(uint4*)(dsm + abase + 16384 + r * 128 + dg * 16) = pLo[j];
    }
}

// P_a/P_b = A-images @ W1a/W1b (chunks 0..3 of wimg). A0/A1 must hold h-chunk images.
__device__ __forceinline__ void compute_P(char* dsm, uint32_t sb, int tid, int lane,
    int wrow, int wcol, int n0, const unsigned char* wimg,
    const int rbyte[4], const int xa[4], const int nbyte[2], const int xb[2])
{
    float acc[4][4][4];
    #pragma unroll
    for (int a = 0; a < 4; a++)
        #pragma unroll
        for (int b = 0; b < 4; b++)
            #pragma unroll
            for (int c = 0; c < 4; c++) acc[a][b][c] = 0.0f;

    for (int chunk = 0; chunk < 4; chunk++) {
        __syncthreads();
        copy_w_chunk(dsm, tid, wimg, chunk, BB_HI);
        __syncthreads();
        uint32_t aBase = sb + ((chunk & 1) ? A1_HI : A0_HI);
        run_chunk_mma(aBase, aBase + 16384, sb + BB_HI, sb + BB_LO,
                      rbyte, xa, nbyte, xb, acc);
        if (chunk & 1) {
            float* P = (chunk < 2) ? g_Pa : g_Pb;
            #pragma unroll
            for (int rt = 0; rt < 4; rt++) {
                int m1 = wrow + 16 * rt + (lane >> 2);
                int m2 = m1 + 8;
                #pragma unroll
                for (int ct = 0; ct < 4; ct++) {
                    int col = wcol + 8 * ct + 2 * (lane & 3);
                    if (n0 + m1 < N_NODES) {
                        float2 v = {acc[rt][ct][0], acc[rt][ct][1]};
                        *(float2*)(P + (size_t)(n0 + m1) * HID + col) = v;
                    }
                    if (n0 + m2 < N_NODES) {
                        float2 v = {acc[rt][ct][2], acc[rt][ct][3]};
                        *(float2*)(P + (size_t)(n0 + m2) * HID + col) = v;
                    }
                }
            }
            #pragma unroll
            for (int a = 0; a < 4; a++)
                #pragma unroll
                for (int b = 0; b < 4; b++)
                    #pragma unroll
                    for (int c = 0; c < 4; c++) acc[a][b][c] = 0.0f;
        }
    }
}

// ================ node_pre (layer 0 only): P from h images + zero aggr ================
__global__ void __launch_bounds__(256) node_pre_kernel(int layer)
{
    extern __shared__ char dsm[];
    uint32_t sb = smem_u32(dsm);
    int tid = threadIdx.x, wid = tid >> 5, lane = tid & 31;
    int wrow = 64 * (wid >> 2), wcol = 32 * (wid & 3);
    int n0 = blockIdx.x * 128;
    const unsigned char* wimg = g_wimg + (size_t)layer * 12 * 2 * 16384;

    stage_h_chunk(dsm, tid, n0, 0, A0_HI);
    stage_h_chunk(dsm, tid, n0, 1, A1_HI);

    // zero aggr rows for this block's nodes
    {
        int r = tid >> 1, half = tid & 1;
        int node = n0 + r;
        if (node < N_NODES) {
            float4 z = {0.0f, 0.0f, 0.0f, 0.0f};
            float4* Sz = (float4*)(g_aggr + (size_t)node * HID) + half * 16;
            #pragma unroll
            for (int j = 0; j < 16; j++) Sz[j] = z;
        }
    }

    int rbyte[4], xa[4], nbyte[2], xb[2];
    ldsm_addrs(lane, wrow, wcol, rbyte, xa, nbyte, xb);
    compute_P(dsm, sb, tid, lane, wrow, wcol, n0, wimg, rbyte, xa, nbyte, xb);
}

// ================ persistent edge kernel ================
__global__ void __launch_bounds__(256, 2) edge_kernel(
    int layer,
    const int* __restrict__ src, const int* __restrict__ dst,
    const float* __restrict__ b1)
{
    extern __shared__ char dsm[];
    __shared__ float s_b1[128];
    uint32_t sb = smem_u32(dsm);
    int tid = threadIdx.x, wid = tid >> 5, lane = tid & 31;
    int wrow = 64 * (wid >> 2), wcol = 32 * (wid & 3);
    const unsigned char* wimg = g_wimg + (size_t)layer * 12 * 2 * 16384;

    if (tid < 128) s_b1[tid] = b1[tid];
    copy_w_chunk(dsm, tid, wimg, 4, EBC0_HI);
    copy_w_chunk(dsm, tid, wimg, 5, EBC1_HI);

    int* sd   = (int*)(dsm + EOFF_DST);
    int* ssrc = (int*)(dsm + EOFF_SRC);

    int rbyte[4], xa[4], nbyte[2], xb[2];
    ldsm_addrs(lane, wrow, wcol, rbyte, xa, nbyte, xb);

    for (int t = blockIdx.x; t < N_TILES; t += EDGE_GRID) {
        int e0 = t * 128;
        __syncthreads();    // prior epilogue readers done; W staging visible on first iter
        if (tid < 128) {
            int e = e0 + tid;
            sd[tid]   = (e < N_EDGES) ? dst[e] : 0;
            ssrc[tid] = (e < N_EDGES) ? src[e] : 0;
        }

        float acc[4][4][4];
        #pragma unroll
        for (int a = 0; a < 4; a++)
            #pragma unroll
            for (int b = 0; b < 4; b++)
                #pragma unroll
                for (int c = 0; c < 4; c++) acc[a][b][c] = 0.0f;

        #pragma unroll
        for (int c = 0; c < 2; c++) {
            if (c) __syncthreads();     // prior chunk's A reads done
            {
                const float4* ehi = (const float4*)(g_eimg + ((size_t)(t * 2 + c) * 2) * 16384);
                const float4* elo = ehi + 1024;
                float4* dahi = (float4*)(dsm + EA_HI);
                float4* dalo = (float4*)(dsm + EA_LO);
                #pragma unroll
                for (int i = 0; i < 4; i++) {
                    dahi[tid + 256 * i] = ehi[tid + 256 * i];
                    dalo[tid + 256 * i] = elo[tid + 256 * i];
                }
            }
            __syncthreads();
            uint32_t bBase = sb + (c ? EBC1_HI : EBC0_HI);
            run_chunk_mma(sb + EA_HI, sb + EA_LO, bBase, bBase + 16384,
                          rbyte, xa, nbyte, xb, acc);
        }

        // epilogue: z = Pe + b1 + Pa[dst] + Pb[src]; relu; scatter-add into S
        #pragma unroll
        for (int rt = 0; rt < 4; rt++) {
            int m1 = wrow + 16 * rt + (lane >> 2);
            int m2 = m1 + 8;
            bool v1ok = (e0 + m1) < N_EDGES;
            bool v2ok = (e0 + m2) < N_EDGES;
            int d1 = sd[m1], s1 = ssrc[m1];
            int d2 = sd[m2], s2 = ssrc[m2];
            const float* pa1 = g_Pa + (size_t)d1 * HID;
            const float* pb1 = g_Pb + (size_t)s1 * HID;
            const float* pa2 = g_Pa + (size_t)d2 * HID;
            const float* pb2 = g_Pb + (size_t)s2 * HID;
            float* ag1 = g_aggr + (size_t)d1 * HID;
            float* ag2 = g_aggr + (size_t)d2 * HID;
            #pragma unroll
            for (int ct = 0; ct < 4; ct++) {
                int col = wcol + 8 * ct + 2 * (lane & 3);
                float bv0 = s_b1[col], bv1 = s_b1[col + 1];
                if (v1ok) {
                    float2 a = *(const float2*)(pa1 + col);
                    float2 b = *(const float2*)(pb1 + col);
                    float z0 = fmaxf(acc[rt][ct][0] + bv0 + a.x + b.x, 0.0f);
                    float z1 = fmaxf(acc[rt][ct][1] + bv1 + a.y + b.y, 0.0f);
                    red_v2(ag1 + col, z0, z1);
                }
                if (v2ok) {
                    float2 a = *(const float2*)(pa2 + col);
                    float2 b = *(const float2*)(pb2 + col);
                    float z0 = fmaxf(acc[rt][ct][2] + bv0 + a.x + b.x, 0.0f);
                    float z1 = fmaxf(acc[rt][ct][3] + bv1 + a.y + b.y, 0.0f);
                    red_v2(ag2 + col, z0, z1);
                }
            }
        }
    }
}

// ================ node_post (HMMA, fused): u=(S*inv)@W2+b2[deg>0]; zero S;
//   upd=[h|u]@updW; r=h+relu(upd+ub); LN -> hout + bf16 images; tail: P for next layer ====
__global__ void __launch_bounds__(256) node_post_kernel(
    int parity, int layer, int last,
    const float* __restrict__ b2, const float* __restrict__ ub,
    const float* __restrict__ lg, const float* __restrict__ lb)
{
    extern __shared__ char dsm[];
    __shared__ float s_b2[128], s_ub[128], s_g[128], s_lb[128], s_mask[128];
    __shared__ float s_sum[128], s_qsum[128];
    uint32_t sb = smem_u32(dsm);
    int tid = threadIdx.x, wid = tid >> 5, lane = tid & 31;
    int wrow = 64 * (wid >> 2), wcol = 32 * (wid & 3);
    int n0 = blockIdx.x * 128;
    const float* __restrict__ h    = parity ? g_h2 : g_h;
    float*       __restrict__ hout = parity ? g_h  : g_h2;
    const unsigned char* wimg = g_wimg + (size_t)layer * 12 * 2 * 16384;

    if (tid < 128) {
        s_b2[tid] = b2[tid]; s_ub[tid] = ub[tid];
        s_g[tid] = lg[tid];  s_lb[tid] = lb[tid];
        int n = n0 + tid;
        s_mask[tid] = (n < N_NODES && g_deg[n] > 0.0f) ? 1.0f : 0.0f;
        s_sum[tid] = 0.0f; s_qsum[tid] = 0.0f;
    }

    // stage A = S*inv as bf16 hi/lo images, then zero the S row (consumed)
    {
        int r = tid >> 1, half = tid & 1;
        int node = n0 + r; float iv = 0.0f;
        bool own = (node < N_NODES);
        if (own) iv = g_inv[node]; else node = N_NODES - 1;
        const float2* Srow = (const float2*)(g_aggr + (size_t)node * HID) + half * 32;
        int ab = half ? A1_HI : A0_HI;
        int rx = r & 7;
        #pragma unroll
        for (int gi = 0; gi < 8; gi++) {
            uint32_t hv[4], lv[4];
            #pragma unroll
            for (int j = 0; j < 4; j++) {
                float2 v = Srow[gi * 4 + j];
                v.x *= iv; v.y *= iv;
                uint32_t hi = bf16x2_of(v.x, v.y);
                uint32_t lo = bf16x2_of(v.x - lo_f(hi), v.y - hi_f(hi));
                hv[j] = hi; lv[j] = lo;
            }
            int dg = gi ^ rx;
            *(uint4*)(dsm + ab + r * 128 + dg * 16) = make_uint4(hv[0], hv[1], hv[2], hv[3]);
            *(uint4*)(dsm + ab + 16384 + r * 128 + dg * 16) = make_uint4(lv[0], lv[1], lv[2], lv[3]);
        }
        if (own) {
            float4 z = {0.0f, 0.0f, 0.0f, 0.0f};
            float4* Sz = (float4*)(g_aggr + (size_t)node * HID) + half * 16;
            #pragma unroll
            for (int j = 0; j < 16; j++) Sz[j] = z;
        }
    }

    int rbyte[4], xa[4], nbyte[2], xb[2];
    ldsm_addrs(lane, wrow, wcol, rbyte, xa, nbyte, xb);

    float acc[4][4][4];
    #pragma unroll
    for (int a = 0; a < 4; a++)
        #pragma unroll
        for (int b = 0; b < 4; b++)
            #pragma unroll
            for (int c = 0; c < 4; c++) acc[a][b][c] = 0.0f;

    // ---- stage 1: u = S' @ W2 (chunks 6,7) ----
    for (int c = 0; c < 2; c++) {
        __syncthreads();
        copy_w_chunk(dsm, tid, wimg, 6 + c, BB_HI);
        __syncthreads();
        uint32_t aBase = sb + (c ? A1_HI : A0_HI);
        run_chunk_mma(aBase, aBase + 16384, sb + BB_HI, sb + BB_LO,
                      rbyte, xa, nbyte, xb, acc);
    }
    __syncthreads();

    // u fragments (+ masked b2) -> bf16 images into A0/A1
    #pragma unroll
    for (int rt = 0; rt < 4; rt++) {
        int m1 = wrow + 16 * rt + (lane >> 2);
        int m2 = m1 + 8;
        float mk1 = s_mask[m1], mk2 = s_mask[m2];
        #pragma unroll
        for (int ct = 0; ct < 4; ct++) {
            int col = wcol + 8 * ct + 2 * (lane & 3);
            int ab = (col >= 64) ? A1_HI : A0_HI;
            int k2 = (col & 63) * 2;
            float bb0 = s_b2[col], bb1 = s_b2[col + 1];
            {
                float v0 = acc[rt][ct][0] + mk1 * bb0;
                float v1 = acc[rt][ct][1] + mk1 * bb1;
                uint32_t hi = bf16x2_of(v0, v1);
                uint32_t lo = bf16x2_of(v0 - lo_f(hi), v1 - hi_f(hi));
                uint32_t byte = SWZ((uint32_t)(m1 * 128 + k2));
                *(uint32_t*)(dsm + ab + byte) = hi;
                *(uint32_t*)(dsm + ab + 16384 + byte) = lo;
            }
            {
                float v0 = acc[rt][ct][2] + mk2 * bb0;
                float v1 = acc[rt][ct][3] + mk2 * bb1;
                uint32_t hi = bf16x2_of(v0, v1);
                uint32_t lo = bf16x2_of(v0 - lo_f(hi), v1 - hi_f(hi));
                uint32_t byte = SWZ((uint32_t)(m2 * 128 + k2));
                *(uint32_t*)(dsm + ab + byte) = hi;
                *(uint32_t*)(dsm + ab + 16384 + byte) = lo;
            }
        }
    }
    #pragma unroll
    for (int a = 0; a < 4; a++)
        #pragma unroll
        for (int b = 0; b < 4; b++)
            #pragma unroll
            for (int c = 0; c < 4; c++) acc[a][b][c] = 0.0f;

    // ---- stage 2: upd = [h|u] @ updW. order: u0(A0,ch10) u1(A1,ch11) h0(A0,ch8) h1(A1,ch9)
    for (int s = 0; s < 4; s++) {
        __syncthreads();
        if (s >= 2) stage_h_chunk(dsm, tid, n0, s - 2, (s & 1) ? A1_HI : A0_HI);
        copy_w_chunk(dsm, tid, wimg, (s < 2) ? (10 + s) : (8 + (s - 2)), BB_HI);
        __syncthreads();
        uint32_t aBase = sb + ((s & 1) ? A1_HI : A0_HI);
        run_chunk_mma(aBase, aBase + 16384, sb + BB_HI, sb + BB_LO,
                      rbyte, xa, nbyte, xb, acc);
    }

    // ---- r = h + relu(upd + ub), stored in-place in acc; LN stats via shared atomics ----
    #pragma unroll
    for (int rt = 0; rt < 4; rt++) {
        int m1 = wrow + 16 * rt + (lane >> 2);
        int m2 = m1 + 8;
        int nd1 = n0 + m1; if (nd1 >= N_NODES) nd1 = N_NODES - 1;
        int nd2 = n0 + m2; if (nd2 >= N_NODES) nd2 = N_NODES - 1;
        float s1 = 0.0f, q1 = 0.0f, s2 = 0.0f, q2 = 0.0f;
        #pragma unroll
        for (int ct = 0; ct < 4; ct++) {
            int col = wcol + 8 * ct + 2 * (lane & 3);
            float u0 = s_ub[col], u1 = s_ub[col + 1];
            float2 hv1 = *(const float2*)(h + (size_t)nd1 * HID + col);
            float r0 = hv1.x + fmaxf(acc[rt][ct][0] + u0, 0.0f);
            float r1 = hv1.y + fmaxf(acc[rt][ct][1] + u1, 0.0f);
            acc[rt][ct][0] = r0; acc[rt][ct][1] = r1;
            s1 += r0 + r1; q1 += r0 * r0 + r1 * r1;
            float2 hv2 = *(const float2*)(h + (size_t)nd2 * HID + col);
            float r2 = hv2.x + fmaxf(acc[rt][ct][2] + u0, 0.0f);
            float r3 = hv2.y + fmaxf(acc[rt][ct][3] + u1, 0.0f);
            acc[rt][ct][2] = r2; acc[rt][ct][3] = r3;
            s2 += r2 + r3; q2 += r2 * r2 + r3 * r3;
        }
        atomicAdd(&s_sum[m1], s1); atomicAdd(&s_qsum[m1], q1);
        atomicAdd(&s_sum[m2], s2); atomicAdd(&s_qsum[m2], q2);
    }
    __syncthreads();   // stats complete; also MMA A-reads done

    // ---- LN outputs -> hout + g_hbf images + smem A images (for tail P) ----
    #pragma unroll
    for (int rt = 0; rt < 4; rt++) {
        #pragma unroll
        for (int half = 0; half < 2; half++) {
            int m = wrow + 16 * rt + (lane >> 2) + 8 * half;
            int node = n0 + m;
            bool own = (node < N_NODES);
            float mu = s_sum[m] * (1.0f / HID);
            float var = s_qsum[m] * (1.0f / HID) - mu * mu;
            float rs = rsqrtf(var + 1e-5f);
            #pragma unroll
            for (int ct = 0; ct < 4; ct++) {
                int col = wcol + 8 * ct + 2 * (lane & 3);
                float r0 = acc[rt][ct][half * 2];
                float r1 = acc[rt][ct][half * 2 + 1];
                float o0 = (r0 - mu) * rs * s_g[col] + s_lb[col];
                float o1 = (r1 - mu) * rs * s_g[col + 1] + s_lb[col + 1];
                uint32_t hi = bf16x2_of(o0, o1);
                uint32_t lo = bf16x2_of(o0 - lo_f(hi), o1 - hi_f(hi));
                if (own) {
                    float2 v = {o0, o1};
                    *(float2*)(hout + (size_t)node * HID + col) = v;
                    ((uint32_t*)g_hbf_hi)[(size_t)node * 64 + (col >> 1)] = hi;
                    ((uint32_t*)g_hbf_lo)[(size_t)node * 64 + (col >> 1)] = lo;
                }
                int ab = (col >= 64) ? A1_HI : A0_HI;
                uint32_t byte = SWZ((uint32_t)(m * 128 + (col & 63) * 2));
                *(uint32_t*)(dsm + ab + byte) = hi;
                *(uint32_t*)(dsm + ab + 16384 + byte) = lo;
            }
        }
    }

    // ---- tail: P_a/P_b for next layer from the fresh h images ----
    if (!last) {
        const unsigned char* wimgN = g_wimg + (size_t)(layer + 1) * 12 * 2 * 16384;
        compute_P(dsm, sb, tid, lane, wrow, wcol, n0, wimgN, rbyte, xa, nbyte, xb);
    }
}

// ---- decoder ----
__global__ __launch_bounds__(128) void decoder_kernel(
    int parity,
    const float* __restrict__ W1, const float* __restrict__ b1,
    const float* __restrict__ W2, const float* __restrict__ b2,
    float* __restrict__ out)
{
    __shared__ float Hs[32][HID];
    __shared__ float s_red[32];

    const float* __restrict__ h = parity ? g_h2 : g_h;

    int tid = threadIdx.x;
    int n0 = blockIdx.x * 32;

    for (int idx = tid; idx < 32 * HID; idx += 128) {
        int i = idx >> 7, k = idx & 127;
        int n = n0 + i;
        Hs[i][k] = (n < N_NODES) ? h[(size_t)n * HID + k] : 0.0f;
    }
    __syncthreads();

    int c = tid;
    float acc[32];
    #pragma unroll
    for (int i = 0; i < 32; i++) acc[i] = 0.0f;
    for (int k = 0; k < HID; k++) {
        float w = W1[(size_t)k * HID + c];
        #pragma unroll
        for (int i = 0; i < 32; i++) acc[i] = fmaf(Hs[i][k], w, acc[i]);
    }
    __syncthreads();

    float b1c = b1[c], w2c = W2[c];
    #pragma unroll
    for (int i = 0; i < 32; i++)
        Hs[i][c] = fmaxf(acc[i] + b1c, 0.0f) * w2c;
    __syncthreads();

    int warp = tid >> 5, lane = tid & 31;
    for (int i = warp; i < 32; i += 4) {
        float s = Hs[i][lane] + Hs[i][32 + lane] + Hs[i][64 + lane] + Hs[i][96 + lane];
        #pragma unroll
        for (int o = 16; o > 0; o >>= 1) s += __shfl_xor_sync(0xffffffffu, s, o);
        if (lane == 0) s_red[i] = s;
    }
    __syncthreads();
    if (tid < 32) {
        int n = n0 + tid;
        if (n < N_NODES) out[n] = s_red[tid] + b2[0];
    }
}

extern "C" void kernel_launch(void* const* d_in, const int* in_sizes, int n_in,
                              void* d_out, int out_size)
{
    const float* x      = (const float*)d_in[0];
    const int*   ei     = (const int*)  d_in[1];
    const float* eattr  = (const float*)d_in[2];
    const float* encW1  = (const float*)d_in[3];
    const float* encb1  = (const float*)d_in[4];
    const float* encW2  = (const float*)d_in[5];
    const float* encb2  = (const float*)d_in[6];
    const float* eeW    = (const float*)d_in[7];
    const float* eeb    = (const float*)d_in[8];
    const float* msgW1  = (const float*)d_in[9];
    const float* msgb1  = (const float*)d_in[10];
    const float* msgW2  = (const float*)d_in[11];
    const float* msgb2  = (const float*)d_in[12];
    const float* updW   = (const float*)d_in[13];
    const float* updb   = (const float*)d_in[14];
    const float* lng    = (const float*)d_in[15];
    const float* lnb    = (const float*)d_in[16];
    const float* decW1  = (const float*)d_in[17];
    const float* decb1  = (const float*)d_in[18];
    const float* decW2  = (const float*)d_in[19];
    const float* decb2  = (const float*)d_in[20];
    float* out = (float*)d_out;

    const int* src = ei;
    const int* dst = ei + N_EDGES;

    cudaFuncSetAttribute(edge_kernel, cudaFuncAttributeMaxDynamicSharedMemorySize, E_SMEM);
    cudaFuncSetAttribute(node_pre_kernel, cudaFuncAttributeMaxDynamicSharedMemorySize, ND_SMEM);
    cudaFuncSetAttribute(node_post_kernel, cudaFuncAttributeMaxDynamicSharedMemorySize, ND_SMEM);

    conv_w_kernel<<<N_LAYERS * 12, 128>>>(msgW1, msgW2, updW);
    conv_e_kernel<<<N_TILES, 128>>>(eattr, eeW, eeb);

    zero_deg_kernel<<<(N_NODES + 255) / 256, 256>>>();
    deg_kernel<<<(N_EDGES + 255) / 256, 256>>>(dst);
    inv_kernel<<<(N_NODES + 255) / 256, 256>>>();
    encoder_kernel<<<(N_NODES + 31) / 32, 128>>>(x, encW1, encb1, encW2, encb2);
    conv_h_kernel<<<(N_NODES * 64 + 255) / 256, 256>>>();
    node_pre_kernel<<<N_NTILES, 256, ND_SMEM>>>(0);   // P for layer 0 + zero aggr

    for (int l = 0; l < N_LAYERS; l++) {
        int parity = l & 1;
        edge_kernel<<<EDGE_GRID, 256, E_SMEM>>>(l, src, dst, msgb1 + (size_t)l * HID);
        node_post_kernel<<<N_NTILES, 256, ND_SMEM>>>(
            parity, l, (l == N_LAYERS - 1) ? 1 : 0,
            msgb2 + (size_t)l * HID, updb + (size_t)l * HID,
            lng + (size_t)l * HID, lnb + (size_t)l * HID);
    }
    decoder_kernel<<<(N_NODES + 31) / 32, 128>>>(0, decW1, decb1, decW2, decb2, out);
}

// round 16
// speedup vs baseline: 5.7968x; 1.2793x over previous
#include <cuda_runtime.h>
#include <cuda_bf16.h>
#include <cstdint>

#define N_NODES 50000
#define N_EDGES 600000
#define HID 128
#define N_LAYERS 6
#define N_TILES 4688          // ceil(600000/128)
#define N_NTILES 391          // ceil(50000/128)
#define N_PAD (N_NTILES * 128)
#define EDGE_GRID 296

#define SWZ(x) ((x) ^ (((x) >> 3) & 0x70))

// ---- node kernels dynamic smem layout ----
#define A0_HI 0
#define A0_LO 16384
#define A1_HI 32768
#define A1_LO 49152
#define BB_HI 65536
#define BB_LO 81920
#define ND_SMEM 98304

// ---- edge smem layout (persistent: both W chunks resident) ----
#define EA_HI 0
#define EA_LO 16384
#define EBC0_HI 32768
#define EBC0_LO 49152
#define EBC1_HI 65536
#define EBC1_LO 81920
#define EOFF_DST 98304
#define EOFF_SRC 98816
#define E_SMEM   99328

// ---- scratch (no allocations allowed) ----
__device__ float g_h   [(size_t)N_NODES * HID];
__device__ float g_h2  [(size_t)N_NODES * HID];
__device__ float g_aggr[(size_t)N_NODES * HID];   // S = sum of relu(z)
__device__ float g_Pa  [(size_t)N_PAD * HID];
__device__ float g_Pb  [(size_t)N_PAD * HID];
__device__ float g_deg [N_NODES];
__device__ float g_inv [N_NODES];
__device__ float g_W2comb[(size_t)N_LAYERS * HID * HID];  // W2 @ updW_u
__device__ float g_cvec  [(size_t)N_LAYERS * HID];        // b2 @ updW_u
__device__ unsigned char g_hbf_hi[(size_t)N_NODES * 256];
__device__ unsigned char g_hbf_lo[(size_t)N_NODES * 256];
// weight images: [layer][chunk 0..9][hi/lo][16KB]; [n][k] bf16x2 at SWZ(n*128+k*2)
// 0,1=W1a 2,3=W1b 4,5=W1c 6,7=updW_h 8,9=W2comb
__device__ unsigned char g_wimg[(size_t)N_LAYERS * 10 * 2 * 16384];

// ================= helpers =================
__device__ __forceinline__ uint32_t smem_u32(const void* p) {
    uint32_t a;
    asm("{ .reg .u64 t; cvta.to.shared.u64 t, %1; cvt.u32.u64 %0, t; }" : "=r"(a) : "l"(p));
    return a;
}
__device__ __forceinline__ uint32_t bf16x2_of(float lo, float hi) {
    uint32_t r;
    asm("cvt.rn.bf16x2.f32 %0, %1, %2;" : "=r"(r) : "f"(hi), "f"(lo));
    return r;
}
__device__ __forceinline__ float lo_f(uint32_t p) { return __uint_as_float(p << 16); }
__device__ __forceinline__ float hi_f(uint32_t p) { return __uint_as_float(p & 0xffff0000u); }

__device__ __forceinline__ void ldsm_x4(uint32_t* r, uint32_t addr) {
    asm volatile("ldmatrix.sync.aligned.m8n8.x4.shared.b16 {%0,%1,%2,%3}, [%4];"
        : "=r"(r[0]), "=r"(r[1]), "=r"(r[2]), "=r"(r[3]) : "r"(addr));
}
__device__ __forceinline__ void mma_bf16(float* d, const uint32_t* a, const uint32_t* b) {
    asm volatile(
        "mma.sync.aligned.m16n8k16.row.col.f32.bf16.bf16.f32 "
        "{%0,%1,%2,%3}, {%4,%5,%6,%7}, {%8,%9}, {%0,%1,%2,%3};"
        : "+f"(d[0]), "+f"(d[1]), "+f"(d[2]), "+f"(d[3])
        : "r"(a[0]), "r"(a[1]), "r"(a[2]), "r"(a[3]), "r"(b[0]), "r"(b[1]));
}
__device__ __forceinline__ void red_v2(float* p, float v0, float v1) {
    asm volatile("red.global.add.v2.f32 [%0], {%1, %2};"
                 :: "l"(p), "f"(v0), "f"(v1) : "memory");
}

// ================= small kernels =================
__global__ void zero_deg_kernel() {
    int i = blockIdx.x * blockDim.x + threadIdx.x;
    if (i < N_NODES) g_deg[i] = 0.0f;
}
__global__ void deg_kernel(const int* __restrict__ dst) {
    int e = blockIdx.x * blockDim.x + threadIdx.x;
    if (e < N_EDGES) atomicAdd(&g_deg[dst[e]], 1.0f);
}
__global__ void inv_kernel() {
    int i = blockIdx.x * blockDim.x + threadIdx.x;
    if (i < N_NODES) {
        float d = g_deg[i];
        g_inv[i] = (d > 0.0f) ? (1.0f / d) : 0.0f;
    }
}

// ---- combined weights: W2comb[l][k][n] = sum_j W2[l][k][j] * updW[l][128+j][n] ----
__global__ __launch_bounds__(128) void comb_w_kernel(
    const float* __restrict__ msgW2, const float* __restrict__ updW)
{
    int l = blockIdx.x >> 7, k = blockIdx.x & 127;
    int n = threadIdx.x;
    const float* W2 = msgW2 + (size_t)l * 128 * 128 + (size_t)k * 128;
    const float* Wu = updW + (size_t)l * 256 * 128 + (size_t)128 * 128;
    float acc = 0.0f;
    for (int j = 0; j < 128; j++)
        acc = fmaf(W2[j], Wu[(size_t)j * 128 + n], acc);
    g_W2comb[(size_t)l * 128 * 128 + (size_t)k * 128 + n] = acc;
}
__global__ __launch_bounds__(128) void cvec_kernel(
    const float* __restrict__ msgb2, const float* __restrict__ updW)
{
    int l = blockIdx.x, n = threadIdx.x;
    const float* b2 = msgb2 + (size_t)l * 128;
    const float* Wu = updW + (size_t)l * 256 * 128 + (size_t)128 * 128;
    float acc = 0.0f;
    for (int j = 0; j < 128; j++)
        acc = fmaf(b2[j], Wu[(size_t)j * 128 + n], acc);
    g_cvec[(size_t)l * 128 + n] = acc;
}

// ---- convert h (fp32 in g_h) -> bf16 hi/lo node images (layer 0 only) ----
__global__ __launch_bounds__(256) void conv_h_kernel() {
    size_t i = (size_t)blockIdx.x * blockDim.x + threadIdx.x;
    if (i >= (size_t)N_NODES * 64) return;
    const float2 v = *((const float2*)g_h + i);
    uint32_t hi = bf16x2_of(v.x, v.y);
    uint32_t lo = bf16x2_of(v.x - lo_f(hi), v.y - hi_f(hi));
    ((uint32_t*)g_hbf_hi)[i] = hi;
    ((uint32_t*)g_hbf_lo)[i] = lo;
}

// ---- precompute: weight chunk images ----
__global__ __launch_bounds__(128) void conv_w_kernel(
    const float* __restrict__ msgW1, const float* __restrict__ updW)
{
    int l = blockIdx.x / 10, ch = blockIdx.x % 10, tid = threadIdx.x;
    const float* W;
    if (ch < 6)      W = msgW1 + (size_t)l * 384 * 128 + (size_t)(64 * ch) * 128;
    else if (ch < 8) W = updW  + (size_t)l * 256 * 128 + (size_t)(64 * (ch - 6)) * 128;
    else             W = g_W2comb + (size_t)l * 128 * 128 + (size_t)(64 * (ch - 8)) * 128;
    unsigned char* hiImg = g_wimg + ((size_t)(l * 10 + ch) * 2) * 16384;
    unsigned char* loImg = hiImg + 16384;
    for (int i = tid; i < 4096; i += 128) {
        int n = i & 127, kp = i >> 7;
        int k = kp * 2;
        float v0 = W[(size_t)k * 128 + n];
        float v1 = W[(size_t)(k + 1) * 128 + n];
        uint32_t hi = bf16x2_of(v0, v1);
        uint32_t lo = bf16x2_of(v0 - lo_f(hi), v1 - hi_f(hi));
        uint32_t byte = SWZ((uint32_t)(n * 128 + k * 2));
        *(uint32_t*)(hiImg + byte) = hi;
        *(uint32_t*)(loImg + byte) = lo;
    }
}

// ---- encoder ----
__global__ __launch_bounds__(128) void encoder_kernel(
    const float* __restrict__ x,
    const float* __restrict__ W1, const float* __restrict__ b1,
    const float* __restrict__ W2, const float* __restrict__ b2)
{
    __shared__ float Hs[32][HID];
    __shared__ float xs[32][3];
    int tid = threadIdx.x;
    int n0 = blockIdx.x * 32;

    for (int idx = tid; idx < 32 * 3; idx += 128) {
        int i = idx / 3, j = idx % 3;
        int n = n0 + i;
        xs[i][j] = (n < N_NODES) ? x[(size_t)n * 3 + j] : 0.0f;
    }
    __syncthreads();

    int c = tid;
    float w0 = W1[c], w1 = W1[HID + c], w2 = W1[2 * HID + c], bc = b1[c];
    #pragma unroll 4
    for (int i = 0; i < 32; i++) {
        float v = bc + xs[i][0] * w0 + xs[i][1] * w1 + xs[i][2] * w2;
        Hs[i][c] = fmaxf(v, 0.0f);
    }
    __syncthreads();

    float acc[32];
    #pragma unroll
    for (int i = 0; i < 32; i++) acc[i] = 0.0f;
    for (int k = 0; k < HID; k++) {
        float w = W2[(size_t)k * HID + c];
        #pragma unroll
        for (int i = 0; i < 32; i++) acc[i] = fmaf(Hs[i][k], w, acc[i]);
    }
    float b2c = b2[c];
    for (int i = 0; i < 32; i++) {
        int n = n0 + i;
        if (n < N_NODES) g_h[(size_t)n * HID + c] = acc[i] + b2c;
    }
}

// ================ shared MMA routines ================
__device__ __forceinline__ void run_chunk_mma(
    uint32_t aHi, uint32_t aLo, uint32_t bHi, uint32_t bLo,
    const int rbyte[4], const int xa[4], const int nbyte[2], const int xb[2],
    float acc[4][4][4])
{
    #pragma unroll
    for (int ks = 0; ks < 4; ks++) {
        int kb = ks * 32;
        uint32_t aH[4][4], aL[4][4], bH[2][4], bL[2][4];
        #pragma unroll
        for (int rt = 0; rt < 4; rt++) {
            uint32_t off = (uint32_t)((rbyte[rt] + kb) ^ xa[rt]);
            ldsm_x4(aH[rt], aHi + off);
            ldsm_x4(aL[rt], aLo + off);
        }
        #pragma unroll
        for (int cp = 0; cp < 2; cp++) {
            uint32_t off = (uint32_t)((nbyte[cp] + kb) ^ xb[cp]);
            ldsm_x4(bH[cp], bHi + off);
            ldsm_x4(bL[cp], bLo + off);
        }
        #pragma unroll
        for (int rt = 0; rt < 4; rt++)
            #pragma unroll
            for (int ct = 0; ct < 4; ct++) {
                const uint32_t* bh = &bH[ct >> 1][(ct & 1) * 2];
                const uint32_t* bl = &bL[ct >> 1][(ct & 1) * 2];
                mma_bf16(acc[rt][ct], aH[rt], bh);
                mma_bf16(acc[rt][ct], aH[rt], bl);
                mma_bf16(acc[rt][ct], aL[rt], bh);
            }
    }
}

__device__ __forceinline__ void ldsm_addrs(int lane, int wrow, int wcol,
                                           int rbyte[4], int xa[4], int nbyte[2], int xb[2])
{
    int q = lane >> 3, i8 = lane & 7;
    #pragma unroll
    for (int rt = 0; rt < 4; rt++) {
        int r = wrow + 16 * rt + i8 + 8 * (q & 1);
        rbyte[rt] = r * 128 + 16 * (q >> 1);
        xa[rt] = (r & 7) << 4;
    }
    #pragma unroll
    for (int cp = 0; cp < 2; cp++) {
        int n = wcol + 16 * cp + i8 + 8 * (q >> 1);
        nbyte[cp] = n * 128 + 16 * (q & 1);
        xb[cp] = (n & 7) << 4;
    }
}

__device__ __forceinline__ void copy_w_chunk(char* dsm, int tid,
                                             const unsigned char* wimg, int chunk, int dstoff)
{
    const float4* whi = (const float4*)(wimg + (size_t)(chunk * 2) * 16384);
    const float4* wlo = whi + 1024;
    float4* dhi = (float4*)(dsm + dstoff);
    float4* dlo = (float4*)(dsm + dstoff + 16384);
    #pragma unroll
    for (int i = 0; i < 4; i++) {
        dhi[tid + 256 * i] = whi[tid + 256 * i];
        dlo[tid + 256 * i] = wlo[tid + 256 * i];
    }
}

__device__ __forceinline__ void stage_h_chunk(char* dsm, int tid, int n0, int hh, int abase)
{
    int r = tid >> 1, half = tid & 1;
    int node = n0 + r; if (node >= N_NODES) node = N_NODES - 1;
    int rx = r & 7;
    int sgbase = 8 * hh + half * 4;
    const uint4* pHi = (const uint4*)(g_hbf_hi + (size_t)node * 256) + sgbase;
    const uint4* pLo = (const uint4*)(g_hbf_lo + (size_t)node * 256) + sgbase;
    #pragma unroll
    for (int j = 0; j < 4; j++) {
        int dg = (half * 4 + j) ^ rx;
        *(uint4*)(dsm + abase + r * 128 + dg * 16) = pHi[j];
        *(uint4*)(dsm + abase + 16384 + r * 128 + dg * 16) = pLo[j];
    }
}

// P_a/P_b = A-images @ W1a/W1b (chunks 0..3). A0/A1 must hold h-chunk images.
__device__ __forceinline__ void compute_P(char* dsm, uint32_t sb, int tid, int lane,
    int wrow, int wcol, int n0, const unsigned char* wimg,
    const int rbyte[4], const int xa[4], const int nbyte[2], const int xb[2])
{
    float acc[4][4][4];
    #pragma unroll
    for (int a = 0; a < 4; a++)
        #pragma unroll
        for (int b = 0; b < 4; b++)
            #pragma unroll
            for (int c = 0; c < 4; c++) acc[a][b][c] = 0.0f;

    for (int chunk = 0; chunk < 4; chunk++) {
        __syncthreads();
        copy_w_chunk(dsm, tid, wimg, chunk, BB_HI);
        __syncthreads();
        uint32_t aBase = sb + ((chunk & 1) ? A1_HI : A0_HI);
        run_chunk_mma(aBase, aBase + 16384, sb + BB_HI, sb + BB_LO,
                      rbyte, xa, nbyte, xb, acc);
        if (chunk & 1) {
            float* P = (chunk < 2) ? g_Pa : g_Pb;
            #pragma unroll
            for (int rt = 0; rt < 4; rt++) {
                int m1 = wrow + 16 * rt + (lane >> 2);
                int m2 = m1 + 8;
                #pragma unroll
                for (int ct = 0; ct < 4; ct++) {
                    int col = wcol + 8 * ct + 2 * (lane & 3);
                    if (n0 + m1 < N_NODES) {
                        float2 v = {acc[rt][ct][0], acc[rt][ct][1]};
                        *(float2*)(P + (size_t)(n0 + m1) * HID + col) = v;
                    }
                    if (n0 + m2 < N_NODES) {
                        float2 v = {acc[rt][ct][2], acc[rt][ct][3]};
                        *(float2*)(P + (size_t)(n0 + m2) * HID + col) = v;
                    }
                }
            }
            #pragma unroll
            for (int a = 0; a < 4; a++)
                #pragma unroll
                for (int b = 0; b < 4; b++)
                    #pragma unroll
                    for (int c = 0; c < 4; c++) acc[a][b][c] = 0.0f;
        }
    }
}

// ================ node_pre (layer 0 only): P from h images + zero aggr ================
__global__ void __launch_bounds__(256) node_pre_kernel(int layer)
{
    extern __shared__ char dsm[];
    uint32_t sb = smem_u32(dsm);
    int tid = threadIdx.x, wid = tid >> 5, lane = tid & 31;
    int wrow = 64 * (wid >> 2), wcol = 32 * (wid & 3);
    int n0 = blockIdx.x * 128;
    const unsigned char* wimg = g_wimg + (size_t)layer * 10 * 2 * 16384;

    stage_h_chunk(dsm, tid, n0, 0, A0_HI);
    stage_h_chunk(dsm, tid, n0, 1, A1_HI);

    {
        int r = tid >> 1, half = tid & 1;
        int node = n0 + r;
        if (node < N_NODES) {
            float4 z = {0.0f, 0.0f, 0.0f, 0.0f};
            float4* Sz = (float4*)(g_aggr + (size_t)node * HID) + half * 16;
            #pragma unroll
            for (int j = 0; j < 16; j++) Sz[j] = z;
        }
    }

    int rbyte[4], xa[4], nbyte[2], xb[2];
    ldsm_addrs(lane, wrow, wcol, rbyte, xa, nbyte, xb);
    compute_P(dsm, sb, tid, lane, wrow, wcol, n0, wimg, rbyte, xa, nbyte, xb);
}

// ================ persistent edge kernel (erow recomputed in-kernel) ================
__global__ void __launch_bounds__(256, 2) edge_kernel(
    int layer,
    const int* __restrict__ src, const int* __restrict__ dst,
    const float* __restrict__ eattr,
    const float* __restrict__ eeW, const float* __restrict__ eeb,
    const float* __restrict__ b1)
{
    extern __shared__ char dsm[];
    __shared__ float s_b1[128];
    __shared__ float s_w[4 * HID];
    __shared__ float s_b[HID];
    uint32_t sb = smem_u32(dsm);
    int tid = threadIdx.x, wid = tid >> 5, lane = tid & 31;
    int wrow = 64 * (wid >> 2), wcol = 32 * (wid & 3);
    const unsigned char* wimg = g_wimg + (size_t)layer * 10 * 2 * 16384;

    if (tid < 128) { s_b1[tid] = b1[tid]; s_b[tid] = eeb[tid]; }
    for (int i = tid; i < 4 * HID; i += 256) s_w[i] = eeW[i];
    copy_w_chunk(dsm, tid, wimg, 4, EBC0_HI);
    copy_w_chunk(dsm, tid, wimg, 5, EBC1_HI);

    int* sd   = (int*)(dsm + EOFF_DST);
    int* ssrc = (int*)(dsm + EOFF_SRC);

    int rbyte[4], xa[4], nbyte[2], xb[2];
    ldsm_addrs(lane, wrow, wcol, rbyte, xa, nbyte, xb);

    for (int t = blockIdx.x; t < N_TILES; t += EDGE_GRID) {
        int e0 = t * 128;
        __syncthreads();    // prior epilogue readers done; initial staging visible
        if (tid < 128) {
            int e = e0 + tid;
            sd[tid]   = (e < N_EDGES) ? dst[e] : 0;
            ssrc[tid] = (e < N_EDGES) ? src[e] : 0;
        }
        // edge attrs for this thread's row
        int r = tid >> 1, half = tid & 1, rx = r & 7;
        float4 ea = {0.0f, 0.0f, 0.0f, 0.0f};
        if (e0 + r < N_EDGES) ea = *(const float4*)(eattr + (size_t)(e0 + r) * 4);

        float acc[4][4][4];
        #pragma unroll
        for (int a = 0; a < 4; a++)
            #pragma unroll
            for (int b = 0; b < 4; b++)
                #pragma unroll
                for (int c = 0; c < 4; c++) acc[a][b][c] = 0.0f;

        #pragma unroll
        for (int c = 0; c < 2; c++) {
            if (c) __syncthreads();     // prior chunk's A reads done
            // stage A: compute erow cols [64c, 64c+64) directly into images
            #pragma unroll
            for (int g = 0; g < 4; g++) {
                uint32_t hv[4], lv[4];
                #pragma unroll
                for (int p = 0; p < 4; p++) {
                    int kl = half * 32 + g * 8 + p * 2;
                    int k = c * 64 + kl;
                    float v0 = fmaxf(s_b[k] + ea.x * s_w[k] + ea.y * s_w[128 + k]
                                            + ea.z * s_w[256 + k] + ea.w * s_w[384 + k], 0.0f);
                    float v1 = fmaxf(s_b[k + 1] + ea.x * s_w[k + 1] + ea.y * s_w[128 + k + 1]
                                                + ea.z * s_w[256 + k + 1] + ea.w * s_w[384 + k + 1], 0.0f);
                    uint32_t hi = bf16x2_of(v0, v1);
                    uint32_t lo = bf16x2_of(v0 - lo_f(hi), v1 - hi_f(hi));
                    hv[p] = hi; lv[p] = lo;
                }
                int dg = (half * 4 + g) ^ rx;
                *(uint4*)(dsm + EA_HI + r * 128 + dg * 16) = make_uint4(hv[0], hv[1], hv[2], hv[3]);
                *(uint4*)(dsm + EA_LO + r * 128 + dg * 16) = make_uint4(lv[0], lv[1], lv[2], lv[3]);
            }
            __syncthreads();
            uint32_t bBase = sb + (c ? EBC1_HI : EBC0_HI);
            run_chunk_mma(sb + EA_HI, sb + EA_LO, bBase, bBase + 16384,
                          rbyte, xa, nbyte, xb, acc);
        }

        // epilogue: z = Pe + b1 + Pa[dst] + Pb[src]; relu; scatter-add into S
        #pragma unroll
        for (int rt = 0; rt < 4; rt++) {
            int m1 = wrow + 16 * rt + (lane >> 2);
            int m2 = m1 + 8;
            bool v1ok = (e0 + m1) < N_EDGES;
            bool v2ok = (e0 + m2) < N_EDGES;
            int d1 = sd[m1], s1 = ssrc[m1];
            int d2 = sd[m2], s2 = ssrc[m2];
            const float* pa1 = g_Pa + (size_t)d1 * HID;
            const float* pb1 = g_Pb + (size_t)s1 * HID;
            const float* pa2 = g_Pa + (size_t)d2 * HID;
            const float* pb2 = g_Pb + (size_t)s2 * HID;
            float* ag1 = g_aggr + (size_t)d1 * HID;
            float* ag2 = g_aggr + (size_t)d2 * HID;
            #pragma unroll
            for (int ct = 0; ct < 4; ct++) {
                int col = wcol + 8 * ct + 2 * (lane & 3);
                float bv0 = s_b1[col], bv1 = s_b1[col + 1];
                if (v1ok) {
                    float2 a = *(const float2*)(pa1 + col);
                    float2 b = *(const float2*)(pb1 + col);
                    float z0 = fmaxf(acc[rt][ct][0] + bv0 + a.x + b.x, 0.0f);
                    float z1 = fmaxf(acc[rt][ct][1] + bv1 + a.y + b.y, 0.0f);
                    red_v2(ag1 + col, z0, z1);
                }
                if (v2ok) {
                    float2 a = *(const float2*)(pa2 + col);
                    float2 b = *(const float2*)(pb2 + col);
                    float z0 = fmaxf(acc[rt][ct][2] + bv0 + a.x + b.x, 0.0f);
                    float z1 = fmaxf(acc[rt][ct][3] + bv1 + a.y + b.y, 0.0f);
                    red_v2(ag2 + col, z0, z1);
                }
            }
        }
    }
}

// ================ node_post (HMMA, fused, W2comb form):
//   upd = S'@W2comb + h@updW_h (+ mask*cvec + ub); r=h+relu(upd); LN -> hout + images;
//   zero S; tail: P for next layer ================
__global__ void __launch_bounds__(256) node_post_kernel(
    int parity, int layer, int last,
    const float* __restrict__ ub,
    const float* __restrict__ lg, const float* __restrict__ lb)
{
    extern __shared__ char dsm[];
    __shared__ float s_cv[128], s_ub[128], s_g[128], s_lb[128], s_mask[128];
    __shared__ float s_sum[128], s_qsum[128];
    uint32_t sb = smem_u32(dsm);
    int tid = threadIdx.x, wid = tid >> 5, lane = tid & 31;
    int wrow = 64 * (wid >> 2), wcol = 32 * (wid & 3);
    int n0 = blockIdx.x * 128;
    const float* __restrict__ h    = parity ? g_h2 : g_h;
    float*       __restrict__ hout = parity ? g_h  : g_h2;
    const unsigned char* wimg = g_wimg + (size_t)layer * 10 * 2 * 16384;

    if (tid < 128) {
        s_cv[tid] = g_cvec[(size_t)layer * 128 + tid];
        s_ub[tid] = ub[tid];
        s_g[tid] = lg[tid];  s_lb[tid] = lb[tid];
        int n = n0 + tid;
        s_mask[tid] = (n < N_NODES && g_deg[n] > 0.0f) ? 1.0f : 0.0f;
        s_sum[tid] = 0.0f; s_qsum[tid] = 0.0f;
    }

    // stage A = S*inv as bf16 hi/lo images, then zero the S row (consumed)
    {
        int r = tid >> 1, half = tid & 1;
        int node = n0 + r; float iv = 0.0f;
        bool own = (node < N_NODES);
        if (own) iv = g_inv[node]; else node = N_NODES - 1;
        const float2* Srow = (const float2*)(g_aggr + (size_t)node * HID) + half * 32;
        int ab = half ? A1_HI : A0_HI;
        int rx = r & 7;
        #pragma unroll
        for (int gi = 0; gi < 8; gi++) {
            uint32_t hv[4], lv[4];
            #pragma unroll
            for (int j = 0; j < 4; j++) {
                float2 v = Srow[gi * 4 + j];
                v.x *= iv; v.y *= iv;
                uint32_t hi = bf16x2_of(v.x, v.y);
                uint32_t lo = bf16x2_of(v.x - lo_f(hi), v.y - hi_f(hi));
                hv[j] = hi; lv[j] = lo;
            }
            int dg = gi ^ rx;
            *(uint4*)(dsm + ab + r * 128 + dg * 16) = make_uint4(hv[0], hv[1], hv[2], hv[3]);
            *(uint4*)(dsm + ab + 16384 + r * 128 + dg * 16) = make_uint4(lv[0], lv[1], lv[2], lv[3]);
        }
        if (own) {
            float4 z = {0.0f, 0.0f, 0.0f, 0.0f};
            float4* Sz = (float4*)(g_aggr + (size_t)node * HID) + half * 16;
            #pragma unroll
            for (int j = 0; j < 16; j++) Sz[j] = z;
        }
    }

    int rbyte[4], xa[4], nbyte[2], xb[2];
    ldsm_addrs(lane, wrow, wcol, rbyte, xa, nbyte, xb);

    float acc[4][4][4];
    #pragma unroll
    for (int a = 0; a < 4; a++)
        #pragma unroll
        for (int b = 0; b < 4; b++)
            #pragma unroll
            for (int c = 0; c < 4; c++) acc[a][b][c] = 0.0f;

    // ---- upd = S'@W2comb (ch 8,9) + h@updW_h (ch 6,7) ----
    for (int s = 0; s < 4; s++) {
        __syncthreads();
        if (s >= 2) stage_h_chunk(dsm, tid, n0, s - 2, (s & 1) ? A1_HI : A0_HI);
        copy_w_chunk(dsm, tid, wimg, (s < 2) ? (8 + s) : (6 + (s - 2)), BB_HI);
        __syncthreads();
        uint32_t aBase = sb + ((s & 1) ? A1_HI : A0_HI);
        run_chunk_mma(aBase, aBase + 16384, sb + BB_HI, sb + BB_LO,
                      rbyte, xa, nbyte, xb, acc);
    }

    // ---- r = h + relu(upd + mask*cvec + ub); LN stats via shared atomics ----
    #pragma unroll
    for (int rt = 0; rt < 4; rt++) {
        int m1 = wrow + 16 * rt + (lane >> 2);
        int m2 = m1 + 8;
        int nd1 = n0 + m1; if (nd1 >= N_NODES) nd1 = N_NODES - 1;
        int nd2 = n0 + m2; if (nd2 >= N_NODES) nd2 = N_NODES - 1;
        float mk1 = s_mask[m1], mk2 = s_mask[m2];
        float s1 = 0.0f, q1 = 0.0f, s2 = 0.0f, q2 = 0.0f;
        #pragma unroll
        for (int ct = 0; ct < 4; ct++) {
            int col = wcol + 8 * ct + 2 * (lane & 3);
            float u0 = s_ub[col], u1 = s_ub[col + 1];
            float c0 = s_cv[col], c1 = s_cv[col + 1];
            float2 hv1 = *(const float2*)(h + (size_t)nd1 * HID + col);
            float r0 = hv1.x + fmaxf(acc[rt][ct][0] + mk1 * c0 + u0, 0.0f);
            float r1 = hv1.y + fmaxf(acc[rt][ct][1] + mk1 * c1 + u1, 0.0f);
            acc[rt][ct][0] = r0; acc[rt][ct][1] = r1;
            s1 += r0 + r1; q1 += r0 * r0 + r1 * r1;
            float2 hv2 = *(const float2*)(h + (size_t)nd2 * HID + col);
            float r2 = hv2.x + fmaxf(acc[rt][ct][2] + mk2 * c0 + u0, 0.0f);
            float r3 = hv2.y + fmaxf(acc[rt][ct][3] + mk2 * c1 + u1, 0.0f);
            acc[rt][ct][2] = r2; acc[rt][ct][3] = r3;
            s2 += r2 + r3; q2 += r2 * r2 + r3 * r3;
        }
        atomicAdd(&s_sum[m1], s1); atomicAdd(&s_qsum[m1], q1);
        atomicAdd(&s_sum[m2], s2); atomicAdd(&s_qsum[m2], q2);
    }
    __syncthreads();   // stats complete; MMA A-reads done

    // ---- LN outputs -> hout + g_hbf images + smem A images (for tail P) ----
    #pragma unroll
    for (int rt = 0; rt < 4; rt++) {
        #pragma unroll
        for (int half = 0; half < 2; half++) {
            int m = wrow + 16 * rt + (lane >> 2) + 8 * half;
            int node = n0 + m;
            bool own = (node < N_NODES);
            float mu = s_sum[m] * (1.0f / HID);
            float var = s_qsum[m] * (1.0f / HID) - mu * mu;
            float rs = rsqrtf(var + 1e-5f);
            #pragma unroll
            for (int ct = 0; ct < 4; ct++) {
                int col = wcol + 8 * ct + 2 * (lane & 3);
                float r0 = acc[rt][ct][half * 2];
                float r1 = acc[rt][ct][half * 2 + 1];
                float o0 = (r0 - mu) * rs * s_g[col] + s_lb[col];
                float o1 = (r1 - mu) * rs * s_g[col + 1] + s_lb[col + 1];
                uint32_t hi = bf16x2_of(o0, o1);
                uint32_t lo = bf16x2_of(o0 - lo_f(hi), o1 - hi_f(hi));
                if (own) {
                    float2 v = {o0, o1};
                    *(float2*)(hout + (size_t)node * HID + col) = v;
                    ((uint32_t*)g_hbf_hi)[(size_t)node * 64 + (col >> 1)] = hi;
                    ((uint32_t*)g_hbf_lo)[(size_t)node * 64 + (col >> 1)] = lo;
                }
                int ab = (col >= 64) ? A1_HI : A0_HI;
                uint32_t byte = SWZ((uint32_t)(m * 128 + (col & 63) * 2));
                *(uint32_t*)(dsm + ab + byte) = hi;
                *(uint32_t*)(dsm + ab + 16384 + byte) = lo;
            }
        }
    }

    // ---- tail: P_a/P_b for next layer ----
    if (!last) {
        const unsigned char* wimgN = g_wimg + (size_t)(layer + 1) * 10 * 2 * 16384;
        compute_P(dsm, sb, tid, lane, wrow, wcol, n0, wimgN, rbyte, xa, nbyte, xb);
    }
}

// ---- decoder ----
__global__ __launch_bounds__(128) void decoder_kernel(
    int parity,
    const float* __restrict__ W1, const float* __restrict__ b1,
    const float* __restrict__ W2, const float* __restrict__ b2,
    float* __restrict__ out)
{
    __shared__ float Hs[32][HID];
    __shared__ float s_red[32];

    const float* __restrict__ h = parity ? g_h2 : g_h;

    int tid = threadIdx.x;
    int n0 = blockIdx.x * 32;

    for (int idx = tid; idx < 32 * HID; idx += 128) {
        int i = idx >> 7, k = idx & 127;
        int n = n0 + i;
        Hs[i][k] = (n < N_NODES) ? h[(size_t)n * HID + k] : 0.0f;
    }
    __syncthreads();

    int c = tid;
    float acc[32];
    #pragma unroll
    for (int i = 0; i < 32; i++) acc[i] = 0.0f;
    for (int k = 0; k < HID; k++) {
        float w = W1[(size_t)k * HID + c];
        #pragma unroll
        for (int i = 0; i < 32; i++) acc[i] = fmaf(Hs[i][k], w, acc[i]);
    }
    __syncthreads();

    float b1c = b1[c], w2c = W2[c];
    #pragma unroll
    for (int i = 0; i < 32; i++)
        Hs[i][c] = fmaxf(acc[i] + b1c, 0.0f) * w2c;
    __syncthreads();

    int warp = tid >> 5, lane = tid & 31;
    for (int i = warp; i < 32; i += 4) {
        float s = Hs[i][lane] + Hs[i][32 + lane] + Hs[i][64 + lane] + Hs[i][96 + lane];
        #pragma unroll
        for (int o = 16; o > 0; o >>= 1) s += __shfl_xor_sync(0xffffffffu, s, o);
        if (lane == 0) s_red[i] = s;
    }
    __syncthreads();
    if (tid < 32) {
        int n = n0 + tid;
        if (n < N_NODES) out[n] = s_red[tid] + b2[0];
    }
}

extern "C" void kernel_launch(void* const* d_in, const int* in_sizes, int n_in,
                              void* d_out, int out_size)
{
    const float* x      = (const float*)d_in[0];
    const int*   ei     = (const int*)  d_in[1];
    const float* eattr  = (const float*)d_in[2];
    const float* encW1  = (const float*)d_in[3];
    const float* encb1  = (const float*)d_in[4];
    const float* encW2  = (const float*)d_in[5];
    const float* encb2  = (const float*)d_in[6];
    const float* eeW    = (const float*)d_in[7];
    const float* eeb    = (const float*)d_in[8];
    const float* msgW1  = (const float*)d_in[9];
    const float* msgb1  = (const float*)d_in[10];
    const float* msgW2  = (const float*)d_in[11];
    const float* msgb2  = (const float*)d_in[12];
    const float* updW   = (const float*)d_in[13];
    const float* updb   = (const float*)d_in[14];
    const float* lng    = (const float*)d_in[15];
    const float* lnb    = (const float*)d_in[16];
    const float* decW1  = (const float*)d_in[17];
    const float* decb1  = (const float*)d_in[18];
    const float* decW2  = (const float*)d_in[19];
    const float* decb2  = (const float*)d_in[20];
    float* out = (float*)d_out;

    const int* src = ei;
    const int* dst = ei + N_EDGES;

    cudaFuncSetAttribute(edge_kernel, cudaFuncAttributeMaxDynamicSharedMemorySize, E_SMEM);
    cudaFuncSetAttribute(node_pre_kernel, cudaFuncAttributeMaxDynamicSharedMemorySize, ND_SMEM);
    cudaFuncSetAttribute(node_post_kernel, cudaFuncAttributeMaxDynamicSharedMemorySize, ND_SMEM);

    comb_w_kernel<<<N_LAYERS * 128, 128>>>(msgW2, updW);
    cvec_kernel<<<N_LAYERS, 128>>>(msgb2, updW);
    conv_w_kernel<<<N_LAYERS * 10, 128>>>(msgW1, updW);

    zero_deg_kernel<<<(N_NODES + 255) / 256, 256>>>();
    deg_kernel<<<(N_EDGES + 255) / 256, 256>>>(dst);
    inv_kernel<<<(N_NODES + 255) / 256, 256>>>();
    encoder_kernel<<<(N_NODES + 31) / 32, 128>>>(x, encW1, encb1, encW2, encb2);
    conv_h_kernel<<<(N_NODES * 64 + 255) / 256, 256>>>();
    node_pre_kernel<<<N_NTILES, 256, ND_SMEM>>>(0);   // P for layer 0 + zero aggr

    for (int l = 0; l < N_LAYERS; l++) {
        int parity = l & 1;
        edge_kernel<<<EDGE_GRID, 256, E_SMEM>>>(
            l, src, dst, eattr, eeW, eeb, msgb1 + (size_t)l * HID);
        node_post_kernel<<<N_NTILES, 256, ND_SMEM>>>(
            parity, l, (l == N_LAYERS - 1) ? 1 : 0,
            updb + (size_t)l * HID,
            lng + (size_t)l * HID, lnb + (size_t)l * HID);
    }
    decoder_kernel<<<(N_NODES + 31) / 32, 128>>>(0, decW1, decb1, decW2, decb2, out);
}